// round 7
// baseline (speedup 1.0000x reference)
#include <cuda_runtime.h>
#include <math.h>
#include <stdint.h>

#define BN_EPS 1e-5f

// ---------------- f32x2 helpers ----------------
__device__ __forceinline__ uint64_t bcast2(float v) {
    uint64_t r; asm("mov.b64 %0, {%1,%1};" : "=l"(r) : "f"(v)); return r;
}
__device__ __forceinline__ uint64_t fma2(uint64_t a, uint64_t b, uint64_t c) {
    uint64_t d; asm("fma.rn.f32x2 %0, %1, %2, %3;" : "=l"(d) : "l"(a), "l"(b), "l"(c)); return d;
}
__device__ __forceinline__ float2 unpack2(uint64_t v) {
    float2 f; asm("mov.b64 {%0,%1}, %2;" : "=f"(f.x), "=f"(f.y) : "l"(v)); return f;
}

// ---------------- scratch ----------------
__device__ float g_out [16777216];  // ping
__device__ float g_up  [16777216];  // pong
__device__ float g_q   [2097152];
__device__ float g_k   [2097152];
__device__ float g_klo [524288];
__device__ float g_att [294912];
__device__ float g_part[4194304];

// ---------------- conv5: 3x3, 2048->512 @ 16x16, K-split partial ----------------
__global__ void __launch_bounds__(256, 2)
conv5_partial(const float* __restrict__ in, const float* __restrict__ w,
              float* __restrict__ part)
{
    const int ks = blockIdx.x, ocb = blockIdx.y, n = blockIdx.z;
    __shared__ float s_in[8 * 342];        // 8 ic x (18 rows, stride 19)
    __shared__ float s_w [8 * 9 * 64];     // [ic][tap][oc]
    const int tid = threadIdx.x;
    const int og  = tid >> 5;
    const int pg  = tid & 31;
    const int py  = pg >> 1;
    const int px0 = (pg & 1) << 3;

    uint64_t acc2[4][8];
#pragma unroll
    for (int i = 0; i < 4; i++)
#pragma unroll
        for (int j = 0; j < 8; j++) acc2[i][j] = 0ull;

    const int icbase = ks * 128;
    for (int tile = 0; tile < 16; ++tile) {
        const int ict0 = icbase + tile * 8;
        __syncthreads();
        for (int i = tid; i < 8 * 324; i += 256) {
            const int ic = i / 324, rem = i - ic * 324;
            const int ry = rem / 18, rx = rem - ry * 18;
            const int yy = ry - 1, xx = rx - 1;
            float v = 0.f;
            if ((unsigned)yy < 16u && (unsigned)xx < 16u)
                v = in[(((size_t)n * 2048 + ict0 + ic) * 16 + yy) * 16 + xx];
            s_in[ic * 342 + ry * 19 + rx] = v;
        }
        for (int i = tid; i < 8 * 576; i += 256) {
            const int oc = i / 72, r = i - oc * 72;
            const int ic = r / 9, t = r - ic * 9;
            s_w[(ic * 9 + t) * 64 + oc] =
                w[(size_t)(ocb * 64 + oc) * 18432 + (size_t)(ict0 + ic) * 9 + t];
        }
        __syncthreads();
        for (int ic = 0; ic < 8; ++ic) {
            const float* si  = s_in + ic * 342;
            const float* swp = s_w  + ic * 576;
#pragma unroll
            for (int t = 0; t < 9; ++t) {
                const int r = t / 3, s = t - 3 * r;
                const uint64_t* wrow = (const uint64_t*)(swp + t * 64 + og * 8);
                uint64_t wv2[4];
#pragma unroll
                for (int i = 0; i < 4; i++) wv2[i] = wrow[i];
                const float* ib = si + (py + r) * 19 + px0 + s;
#pragma unroll
                for (int j = 0; j < 8; j++) {
                    const uint64_t iv2 = bcast2(ib[j]);
#pragma unroll
                    for (int i = 0; i < 4; i++) acc2[i][j] = fma2(wv2[i], iv2, acc2[i][j]);
                }
            }
        }
    }
    float* dst = part + (size_t)(ks * 2 + n) * 512 * 256;
    const int px = py * 16 + px0;
#pragma unroll
    for (int i = 0; i < 4; i++) {
        const int oc = ocb * 64 + og * 8 + 2 * i;
#pragma unroll
        for (int j = 0; j < 8; j++) {
            const float2 v = unpack2(acc2[i][j]);
            dst[oc * 256 + px + j]       = v.x;
            dst[(oc + 1) * 256 + px + j] = v.y;
        }
    }
}

// ---------------- generic 1x1 conv (GEMM) K-split partial ----------------
__global__ void __launch_bounds__(256)
conv1x1_partial(const float* __restrict__ in, const float* __restrict__ w,
                float* __restrict__ part,
                int Cin, int Cout, int P, int KS, int KCH)
{
    const int pxb = blockIdx.x;
    const int ocb = blockIdx.y / KS;
    const int ks  = blockIdx.y % KS;
    const int n   = blockIdx.z;
    const int k0  = ks * KCH;
    __shared__ float sA[16][68];
    __shared__ float sB[16][136];
    const int tid = threadIdx.x;
    const int ocg = tid >> 4;
    const int pxg = tid & 15;

    uint64_t acc2[4][4];
#pragma unroll
    for (int i = 0; i < 4; i++)
#pragma unroll
        for (int j = 0; j < 4; j++) acc2[i][j] = 0ull;

    const float* wrow = w + (size_t)(ocb * 64) * Cin + k0;
    const float* brow = in + ((size_t)n * Cin + k0) * P + pxb * 128;

    for (int kc = 0; kc < KCH; kc += 16) {
        __syncthreads();
        for (int i = tid; i < 1024; i += 256) {
            int oc = i >> 4, kk = i & 15;
            sA[kk][oc] = wrow[(size_t)oc * Cin + kc + kk];
        }
        for (int i = tid; i < 512; i += 256) {
            int kk = i >> 5, p4 = (i & 31) << 2;
            *(float4*)&sB[kk][p4] = *(const float4*)&brow[((size_t)(kc + kk)) * P + p4];
        }
        __syncthreads();
#pragma unroll
        for (int kk = 0; kk < 16; ++kk) {
            const float4 a4 = *(const float4*)&sA[kk][ocg << 2];
            const float4 b40 = *(const float4*)&sB[kk][pxg << 3];
            const float4 b41 = *(const float4*)&sB[kk][(pxg << 3) + 4];
            const uint64_t* b2 = (const uint64_t*)&b40;
            const uint64_t* b3 = (const uint64_t*)&b41;
            const uint64_t a0 = bcast2(a4.x), a1 = bcast2(a4.y);
            const uint64_t a2 = bcast2(a4.z), a3 = bcast2(a4.w);
            acc2[0][0] = fma2(a0, b2[0], acc2[0][0]);
            acc2[0][1] = fma2(a0, b2[1], acc2[0][1]);
            acc2[0][2] = fma2(a0, b3[0], acc2[0][2]);
            acc2[0][3] = fma2(a0, b3[1], acc2[0][3]);
            acc2[1][0] = fma2(a1, b2[0], acc2[1][0]);
            acc2[1][1] = fma2(a1, b2[1], acc2[1][1]);
            acc2[1][2] = fma2(a1, b3[0], acc2[1][2]);
            acc2[1][3] = fma2(a1, b3[1], acc2[1][3]);
            acc2[2][0] = fma2(a2, b2[0], acc2[2][0]);
            acc2[2][1] = fma2(a2, b2[1], acc2[2][1]);
            acc2[2][2] = fma2(a2, b3[0], acc2[2][2]);
            acc2[2][3] = fma2(a2, b3[1], acc2[2][3]);
            acc2[3][0] = fma2(a3, b2[0], acc2[3][0]);
            acc2[3][1] = fma2(a3, b2[1], acc2[3][1]);
            acc2[3][2] = fma2(a3, b3[0], acc2[3][2]);
            acc2[3][3] = fma2(a3, b3[1], acc2[3][3]);
        }
    }
    float* dst = part + (size_t)(ks * 2 + n) * Cout * P;
    const int ocx = ocb * 64 + (ocg << 2);
    const int px  = pxb * 128 + (pxg << 3);
#pragma unroll
    for (int i = 0; i < 4; i++) {
        const float2 v0 = unpack2(acc2[i][0]), v1 = unpack2(acc2[i][1]);
        const float2 v2 = unpack2(acc2[i][2]), v3 = unpack2(acc2[i][3]);
        *(float4*)&dst[(size_t)(ocx + i) * P + px]     = make_float4(v0.x, v0.y, v1.x, v1.y);
        *(float4*)&dst[(size_t)(ocx + i) * P + px + 4] = make_float4(v2.x, v2.y, v3.x, v3.y);
    }
}

// ---------------- 1x1 conv + fused BN (no K-split) ----------------
__global__ void __launch_bounds__(256)
conv1x1_bn(const float* __restrict__ in, const float* __restrict__ w,
           const float* __restrict__ bn, float* __restrict__ outp,
           int Cin, int Cout, int P)
{
    const int pxb = blockIdx.x;
    const int ocb = blockIdx.y;
    const int n   = blockIdx.z;
    __shared__ float sA[16][68];
    __shared__ float sB[16][136];
    const int tid = threadIdx.x;
    const int ocg = tid >> 4;
    const int pxg = tid & 15;

    uint64_t acc2[4][4];
#pragma unroll
    for (int i = 0; i < 4; i++)
#pragma unroll
        for (int j = 0; j < 4; j++) acc2[i][j] = 0ull;

    const float* wrow = w + (size_t)(ocb * 64) * Cin;
    const float* brow = in + ((size_t)n * Cin) * P + pxb * 128;

    for (int kc = 0; kc < Cin; kc += 16) {
        __syncthreads();
        for (int i = tid; i < 1024; i += 256) {
            int oc = i >> 4, kk = i & 15;
            sA[kk][oc] = wrow[(size_t)oc * Cin + kc + kk];
        }
        for (int i = tid; i < 512; i += 256) {
            int kk = i >> 5, p4 = (i & 31) << 2;
            *(float4*)&sB[kk][p4] = *(const float4*)&brow[((size_t)(kc + kk)) * P + p4];
        }
        __syncthreads();
#pragma unroll
        for (int kk = 0; kk < 16; ++kk) {
            const float4 a4 = *(const float4*)&sA[kk][ocg << 2];
            const uint64_t* bp = (const uint64_t*)&sB[kk][pxg << 3];
            uint64_t b2[4] = { bp[0], bp[1], bp[2], bp[3] };
            const uint64_t a0 = bcast2(a4.x), a1 = bcast2(a4.y);
            const uint64_t a2 = bcast2(a4.z), a3 = bcast2(a4.w);
#pragma unroll
            for (int j = 0; j < 4; j++) {
                acc2[0][j] = fma2(a0, b2[j], acc2[0][j]);
                acc2[1][j] = fma2(a1, b2[j], acc2[1][j]);
                acc2[2][j] = fma2(a2, b2[j], acc2[2][j]);
                acc2[3][j] = fma2(a3, b2[j], acc2[3][j]);
            }
        }
    }
    const int ocx = ocb * 64 + (ocg << 2);
    const int px  = pxb * 128 + (pxg << 3);
#pragma unroll
    for (int i = 0; i < 4; i++) {
        const int oc = ocx + i;
        const float g = bn[oc], b = bn[Cout + oc], m = bn[2 * Cout + oc], v = bn[3 * Cout + oc];
        const float sc = g / sqrtf(v + BN_EPS);
        const float sh = b - m * sc;
        const float2 v0 = unpack2(acc2[i][0]), v1 = unpack2(acc2[i][1]);
        const float2 v2 = unpack2(acc2[i][2]), v3 = unpack2(acc2[i][3]);
        float* op = outp + ((size_t)n * Cout + oc) * P + px;
        *(float4*)op       = make_float4(v0.x * sc + sh, v0.y * sc + sh, v1.x * sc + sh, v1.y * sc + sh);
        *(float4*)(op + 4) = make_float4(v2.x * sc + sh, v2.y * sc + sh, v3.x * sc + sh, v3.y * sc + sh);
    }
}

// ---------------- reduce K-splits + BN (+ReLU), float4 ----------------
__global__ void __launch_bounds__(256)
reduce_bn4(const float4* __restrict__ part, const float* __restrict__ bn,
           float4* __restrict__ out, int C, int P, int KS, int relu)
{
    const int idx = blockIdx.x * 256 + threadIdx.x;
    const int total4 = 2 * C * P / 4;
    if (idx >= total4) return;
    const int c = ((idx * 4) / P) % C;
    const size_t stride4 = (size_t)2 * C * P / 4;
    float4 s = make_float4(0.f, 0.f, 0.f, 0.f);
    for (int k = 0; k < KS; ++k) {
        const float4 q = part[(size_t)k * stride4 + idx];
        s.x += q.x; s.y += q.y; s.z += q.z; s.w += q.w;
    }
    const float g = bn[c], b = bn[C + c], m = bn[2 * C + c], v = bn[3 * C + c];
    const float sc = g / sqrtf(v + BN_EPS);
    const float sh = b - m * sc;
    float4 r = make_float4(s.x * sc + sh, s.y * sc + sh, s.z * sc + sh, s.w * sc + sh);
    if (relu) {
        r.x = fmaxf(r.x, 0.f); r.y = fmaxf(r.y, 0.f);
        r.z = fmaxf(r.z, 0.f); r.w = fmaxf(r.w, 0.f);
    }
    out[idx] = r;
}

// ---------------- bilinear upsample (k path only) ----------------
__global__ void __launch_bounds__(256)
upsample_ac(const float* __restrict__ in, float* __restrict__ out,
            int NC, int h, int w, int H, int W, float sy, float sx)
{
    const int idx = blockIdx.x * 256 + threadIdx.x;
    const int total = NC * H * W;
    if (idx >= total) return;
    const int x  = idx % W;
    const int y  = (idx / W) % H;
    const int nc = idx / (W * H);
    const float fy = y * sy;
    const float fx = x * sx;
    int y0 = (int)fy; if (y0 > h - 1) y0 = h - 1;
    int x0 = (int)fx; if (x0 > w - 1) x0 = w - 1;
    const int y1 = min(y0 + 1, h - 1);
    const int x1 = min(x0 + 1, w - 1);
    const float wy = fy - y0, wx = fx - x0;
    const float* p = in + (size_t)nc * h * w;
    const float v00 = p[y0 * w + x0], v01 = p[y0 * w + x1];
    const float v10 = p[y1 * w + x0], v11 = p[y1 * w + x1];
    const float a = v00 * (1.f - wy) + v10 * wy;
    const float b = v01 * (1.f - wy) + v11 * wy;
    out[idx] = a * (1.f - wx) + b * wx;
}

// ---------------- attention v2: kd-split across block for SM parallelism ------
__global__ void __launch_bounds__(256)
attention_v2(const float* __restrict__ q, const float* __restrict__ kmap,
             float* __restrict__ att, int kd, int H, int W)
{
    __shared__ float s_part[32][8][36];
    __shared__ float s_red[8][36];
    const int tid  = threadIdx.x;
    const int qloc = tid & 7;
    const int si   = tid >> 3;
    const int Wq   = W >> 2;
    const int qg   = blockIdx.x * 8 + qloc;
    const int xq   = qg % Wq;
    const int y    = (qg / Wq) % H;
    const int n    = qg / (Wq * H);
    const int x0   = xq << 2;
    const size_t plane = (size_t)H * W;

    const bool lok = (x0 >= 4);
    const bool rok = (x0 + 4 < W);
    int rowoff[3]; bool rowok[3];
#pragma unroll
    for (int r = 0; r < 3; r++) {
        const int yy = y + (r - 1) * 2;
        rowok[r]  = ((unsigned)yy < (unsigned)H);
        rowoff[r] = yy * W + x0;
    }

    uint64_t lg[9][2];
#pragma unroll
    for (int t = 0; t < 9; t++) { lg[t][0] = 0ull; lg[t][1] = 0ull; }

    const int cpt = kd >> 5;
    const int c0  = si * cpt;
    const float* qp = q + ((size_t)n * kd + c0) * plane + (size_t)y * W + x0;
    const float* kp = kmap + ((size_t)n * kd + c0) * plane;
    const float4 z4 = make_float4(0.f, 0.f, 0.f, 0.f);

    for (int c = 0; c < cpt; ++c) {
        const float4 qv = *(const float4*)(qp + (size_t)c * plane);
        const uint64_t* qh = (const uint64_t*)&qv;
        const uint64_t q01 = qh[0], q23 = qh[1];
        const float* kc = kp + (size_t)c * plane;
#pragma unroll
        for (int r = 0; r < 3; r++) {
            if (!rowok[r]) continue;
            const float* kr = kc + rowoff[r];
            const float4 L = lok ? *(const float4*)(kr - 4) : z4;
            const float4 M = *(const float4*)kr;
            const float4 R = rok ? *(const float4*)(kr + 4) : z4;
            const uint64_t* Lh = (const uint64_t*)&L;
            const uint64_t* Mh = (const uint64_t*)&M;
            const uint64_t* Rh = (const uint64_t*)&R;
            const int t0 = r * 3;
            lg[t0 + 0][0] = fma2(q01, Lh[1], lg[t0 + 0][0]);
            lg[t0 + 0][1] = fma2(q23, Mh[0], lg[t0 + 0][1]);
            lg[t0 + 1][0] = fma2(q01, Mh[0], lg[t0 + 1][0]);
            lg[t0 + 1][1] = fma2(q23, Mh[1], lg[t0 + 1][1]);
            lg[t0 + 2][0] = fma2(q01, Mh[1], lg[t0 + 2][0]);
            lg[t0 + 2][1] = fma2(q23, Rh[0], lg[t0 + 2][1]);
        }
    }
#pragma unroll
    for (int t = 0; t < 9; t++) {
        const float2 a = unpack2(lg[t][0]);
        const float2 b = unpack2(lg[t][1]);
        s_part[si][qloc][t * 4 + 0] = a.x;
        s_part[si][qloc][t * 4 + 1] = a.y;
        s_part[si][qloc][t * 4 + 2] = b.x;
        s_part[si][qloc][t * 4 + 3] = b.y;
    }
    __syncthreads();

    for (int i = tid; i < 8 * 36; i += 256) {
        const int qq = i / 36, j = i - qq * 36;
        float s = 0.f;
#pragma unroll
        for (int s2 = 0; s2 < 32; s2++) s += s_part[s2][qq][j];
        s_red[qq][j] = s;
    }
    __syncthreads();

    if (tid < 32) {
        const int qq = tid >> 2, p = tid & 3;
        float l[9];
#pragma unroll
        for (int t = 0; t < 9; t++) l[t] = s_red[qq][t * 4 + p];
        float mx = l[0];
#pragma unroll
        for (int t = 1; t < 9; t++) mx = fmaxf(mx, l[t]);
        float s = 0.f;
#pragma unroll
        for (int t = 0; t < 9; t++) { l[t] = expf(l[t] - mx); s += l[t]; }
        const float inv = 1.f / s;
        const int qg2 = blockIdx.x * 8 + qq;
        const int xq2 = qg2 % Wq;
        const int y2  = (qg2 / Wq) % H;
        const int n2  = qg2 / (Wq * H);
        float* ap = att + (size_t)n2 * 9 * plane + (size_t)y2 * W + (xq2 << 2) + p;
#pragma unroll
        for (int t = 0; t < 9; t++) ap[(size_t)t * plane] = l[t] * inv;
    }
}

// ---------------- fused upsample + attention apply ----------------
template<int H, int W, int h, int w>
__global__ void __launch_bounds__(256)
apply_fused(const float* __restrict__ att, const float* __restrict__ lo,
            float* __restrict__ outp)
{
    constexpr int WPAD = W + 8;
    __shared__ __align__(16) float s_lo[8][6][w + 2];
    __shared__ __align__(16) float s_up[8][8][WPAD];
    const int y0  = blockIdx.x * 4;
    const int ch0 = blockIdx.y * 8;
    const int n   = blockIdx.z;
    const int tid = threadIdx.x;
    const int nth = blockDim.x;
    constexpr float sy = (float)(h - 1) / (float)(H - 1);
    constexpr float sx = (float)(w - 1) / (float)(W - 1);
    const size_t planeL = (size_t)h * w;
    const size_t planeH = (size_t)H * W;

    const int ylo = (y0 >= 2 ? y0 - 2 : 0);
    const int base = (int)((float)ylo * sy);
    for (int i = tid; i < 8 * 6 * w; i += nth) {
        const int ch = i / (6 * w);
        const int r  = (i / w) % 6;
        const int x  = i % w;
        const int gr = min(base + r, h - 1);
        s_lo[ch][r][x] = lo[((size_t)(n * 512 + ch0 + ch)) * planeL + (size_t)gr * w + x];
    }
    __syncthreads();

    for (int i = tid; i < 8 * 8 * WPAD; i += nth) {
        const int ch  = i / (8 * WPAD);
        const int rem = i - ch * (8 * WPAD);
        const int row = rem / WPAD;
        const int col = rem - row * WPAD;
        const int Y = y0 - 2 + row;
        const int X = col - 4;
        float v = 0.f;
        if ((unsigned)Y < (unsigned)H && (unsigned)X < (unsigned)W) {
            const float fy = Y * sy;
            int iy0 = (int)fy; if (iy0 > h - 1) iy0 = h - 1;
            const int ry0 = iy0 - base;
            const int ry1 = min(iy0 + 1, h - 1) - base;
            const float wy = fy - iy0;
            const float fx = X * sx;
            int ix0 = (int)fx; if (ix0 > w - 1) ix0 = w - 1;
            const int ix1 = min(ix0 + 1, w - 1);
            const float wx = fx - ix0;
            const float a = s_lo[ch][ry0][ix0] * (1.f - wx) + s_lo[ch][ry0][ix1] * wx;
            const float b = s_lo[ch][ry1][ix0] * (1.f - wx) + s_lo[ch][ry1][ix1] * wx;
            v = a * (1.f - wy) + b * wy;
        }
        s_up[ch][row][col] = v;
    }
    __syncthreads();

    const int Wp = W >> 1;
    const int xp = tid % Wp;
    const int yy = tid / Wp;
    const int y  = y0 + yy;
    const int x0 = xp << 1;

    uint64_t att2[9];
    const float* ap = att + (size_t)n * 9 * planeH + (size_t)y * W + x0;
#pragma unroll
    for (int t = 0; t < 9; t++) att2[t] = *(const uint64_t*)(ap + (size_t)t * planeH);

#pragma unroll
    for (int c = 0; c < 8; ++c) {
        uint64_t acc = 0ull;
#pragma unroll
        for (int iy = 0; iy < 3; iy++) {
            const float* rp = &s_up[c][yy + 2 * iy][0];
#pragma unroll
            for (int ix = 0; ix < 3; ix++) {
                const uint64_t u2 = *(const uint64_t*)(rp + x0 + 2 * ix + 2);
                acc = fma2(att2[iy * 3 + ix], u2, acc);
            }
        }
        const float2 v = unpack2(acc);
        *(float2*)&outp[((size_t)(n * 512 + ch0 + c)) * planeH + (size_t)y * W + x0] = v;
    }
}

// ---------------- conv6: 1x1, 512->19, C-split partial, f32x2 ----------------
__global__ void __launch_bounds__(128)
conv6_partial(const float* __restrict__ in, const float* __restrict__ w,
              float* __restrict__ part)
{
    __shared__ float sw[19 * 128];
    const int tid = threadIdx.x;
    const int cs  = blockIdx.y;
    const int n   = blockIdx.z;
    const int c0  = cs * 128;
    for (int i = tid; i < 19 * 128; i += 128) {
        const int o = i >> 7, c = i & 127;
        sw[i] = w[o * 512 + c0 + c];
    }
    __syncthreads();
    const int px = (blockIdx.x * 128 + tid) * 2;
    uint64_t acc2[19];
#pragma unroll
    for (int o = 0; o < 19; o++) acc2[o] = 0ull;
    const float* ip = in + ((size_t)n * 512 + c0) * 16384 + px;
    for (int c = 0; c < 128; ++c) {
        const uint64_t v2 = *(const uint64_t*)(ip + (size_t)c * 16384);
#pragma unroll
        for (int o = 0; o < 19; o++)
            acc2[o] = fma2(bcast2(sw[(o << 7) + c]), v2, acc2[o]);
    }
    float* op = part + ((size_t)(cs * 2 + n) * 19) * 16384 + px;
#pragma unroll
    for (int o = 0; o < 19; o++) {
        const float2 v = unpack2(acc2[o]);
        *(float2*)(op + (size_t)o * 16384) = v;
    }
}

// ---------------- conv6 reduce + bias, float4 ----------------
__global__ void __launch_bounds__(256)
conv6_reduce(const float4* __restrict__ part, const float* __restrict__ bias,
             float4* __restrict__ out)
{
    const int idx = blockIdx.x * 256 + threadIdx.x;
    const int perN = 19 * 16384 / 4;
    const int total = 2 * perN;
    if (idx >= total) return;
    const int n   = idx / perN;
    const int rem = idx - n * perN;
    const int o   = (rem * 4) / 16384;
    float4 s = make_float4(0.f, 0.f, 0.f, 0.f);
#pragma unroll
    for (int cs = 0; cs < 4; ++cs) {
        const float4 q = part[(size_t)(cs * 2 + n) * perN + rem];
        s.x += q.x; s.y += q.y; s.z += q.z; s.w += q.w;
    }
    const float b = bias[o];
    out[idx] = make_float4(s.x + b, s.y + b, s.z + b, s.w + b);
}

// ---------------- launch ----------------
extern "C" void kernel_launch(void* const* d_in, const int* in_sizes, int n_in,
                              void* d_out, int out_size)
{
    (void)in_sizes; (void)n_in; (void)out_size;
    const float* c1      = (const float*)d_in[0];
    const float* c2      = (const float*)d_in[1];
    const float* c3      = (const float*)d_in[2];
    const float* c4      = (const float*)d_in[3];
    const float* c30     = (const float*)d_in[5];
    const float* c40     = (const float*)d_in[6];
    const float* conv5_w = (const float*)d_in[7];
    const float* bn5     = (const float*)d_in[8];
    const float* conv6_w = (const float*)d_in[9];
    const float* conv6_b = (const float*)d_in[10];
    const float* lu4_w1  = (const float*)d_in[11];
    const float* lu4_bn1 = (const float*)d_in[12];
    const float* lu4_w2  = (const float*)d_in[13];
    const float* lu4_bn2 = (const float*)d_in[14];
    const float* lu3_w1  = (const float*)d_in[15];
    const float* lu3_bn1 = (const float*)d_in[16];
    const float* lu3_w2  = (const float*)d_in[17];
    const float* lu3_bn2 = (const float*)d_in[18];
    const float* lu2_w1  = (const float*)d_in[19];
    const float* lu2_bn1 = (const float*)d_in[20];
    const float* lu2_w2  = (const float*)d_in[21];
    const float* lu2_bn2 = (const float*)d_in[22];
    float* out = (float*)d_out;

    float *p_out, *p_up, *p_q, *p_k, *p_klo, *p_att, *p_part;
    cudaGetSymbolAddress((void**)&p_out,  g_out);
    cudaGetSymbolAddress((void**)&p_up,   g_up);
    cudaGetSymbolAddress((void**)&p_q,    g_q);
    cudaGetSymbolAddress((void**)&p_k,    g_k);
    cudaGetSymbolAddress((void**)&p_klo,  g_klo);
    cudaGetSymbolAddress((void**)&p_att,  g_att);
    cudaGetSymbolAddress((void**)&p_part, g_part);

    // ---- conv5 + BN + ReLU -> g_out (2,512,16,16) ----
    conv5_partial<<<dim3(16, 8, 2), 256>>>(c4, conv5_w, p_part);
    reduce_bn4<<<(2 * 512 * 256 / 4 + 255) / 256, 256>>>((const float4*)p_part, bn5, (float4*)p_out, 512, 256, 16, 1);

    // ---- localUp4: H=32, kd=128; lo=g_out -> g_up ----
    conv1x1_partial<<<dim3(8, 2 * 4, 2), 256>>>(c3, lu4_w1, p_part, 1024, 128, 1024, 4, 256);
    reduce_bn4<<<(2 * 128 * 1024 / 4 + 255) / 256, 256>>>((const float4*)p_part, lu4_bn1, (float4*)p_q, 128, 1024, 4, 0);
    conv1x1_partial<<<dim3(2, 2 * 16, 2), 256>>>(c40, lu4_w2, p_part, 2048, 128, 256, 16, 128);
    reduce_bn4<<<(2 * 128 * 256 / 4 + 255) / 256, 256>>>((const float4*)p_part, lu4_bn2, (float4*)p_klo, 128, 256, 16, 0);
    upsample_ac<<<(2 * 128 * 32 * 32 + 255) / 256, 256>>>(p_klo, p_k, 2 * 128, 16, 16, 32, 32, 15.f / 31.f, 15.f / 31.f);
    attention_v2<<<2 * 32 * 8 / 8, 256>>>(p_q, p_k, p_att, 128, 32, 32);
    apply_fused<32, 32, 16, 16><<<dim3(8, 64, 2), 64>>>(p_att, p_out, p_up);

    // ---- localUp3: H=64, kd=64; lo=g_up -> g_out ----
    conv1x1_bn<<<dim3(32, 1, 2), 256>>>(c2, lu3_w1, lu3_bn1, p_q, 512, 64, 4096);
    conv1x1_partial<<<dim3(8, 1 * 8, 2), 256>>>(c30, lu3_w2, p_part, 1024, 64, 1024, 8, 128);
    reduce_bn4<<<(2 * 64 * 1024 / 4 + 255) / 256, 256>>>((const float4*)p_part, lu3_bn2, (float4*)p_klo, 64, 1024, 8, 0);
    upsample_ac<<<(2 * 64 * 64 * 64 + 255) / 256, 256>>>(p_klo, p_k, 2 * 64, 32, 32, 64, 64, 31.f / 63.f, 31.f / 63.f);
    attention_v2<<<2 * 64 * 16 / 8, 256>>>(p_q, p_k, p_att, 64, 64, 64);
    apply_fused<64, 64, 32, 32><<<dim3(16, 64, 2), 128>>>(p_att, p_up, p_out);

    // ---- localUp2: H=128, kd=64; lo=g_out -> g_up ----
    conv1x1_bn<<<dim3(128, 1, 2), 256>>>(c1, lu2_w1, lu2_bn1, p_q, 256, 64, 16384);
    conv1x1_bn<<<dim3(32, 1, 2), 256>>>(c2, lu2_w2, lu2_bn2, p_klo, 512, 64, 4096);
    upsample_ac<<<(2 * 64 * 128 * 128 + 255) / 256, 256>>>(p_klo, p_k, 2 * 64, 64, 64, 128, 128, 63.f / 127.f, 63.f / 127.f);
    attention_v2<<<2 * 128 * 32 / 8, 256>>>(p_q, p_k, p_att, 64, 128, 128);
    apply_fused<128, 128, 64, 64><<<dim3(32, 64, 2), 256>>>(p_att, p_out, p_up);

    // ---- conv6 1x1 -> (2,19,128,128), C-split x4 ----
    conv6_partial<<<dim3(64, 4, 2), 128>>>(p_up, conv6_w, p_part);
    conv6_reduce<<<(2 * 19 * 16384 / 4 + 255) / 256, 256>>>((const float4*)p_part, conv6_b, (float4*)out);
}

// round 8
// speedup vs baseline: 1.2223x; 1.2223x over previous
#include <cuda_runtime.h>
#include <math.h>
#include <stdint.h>

#define BN_EPS 1e-5f

// ---------------- f32x2 helpers ----------------
__device__ __forceinline__ uint64_t bcast2(float v) {
    uint64_t r; asm("mov.b64 %0, {%1,%1};" : "=l"(r) : "f"(v)); return r;
}
__device__ __forceinline__ uint64_t fma2(uint64_t a, uint64_t b, uint64_t c) {
    uint64_t d; asm("fma.rn.f32x2 %0, %1, %2, %3;" : "=l"(d) : "l"(a), "l"(b), "l"(c)); return d;
}
__device__ __forceinline__ float2 unpack2(uint64_t v) {
    float2 f; asm("mov.b64 {%0,%1}, %2;" : "=f"(f.x), "=f"(f.y) : "l"(v)); return f;
}

// ---------------- scratch ----------------
__device__ float g_out [16777216];  // ping
__device__ float g_up  [16777216];  // pong
__device__ float g_q   [2097152];
__device__ float g_k   [2097152];
__device__ float g_klo [524288];
__device__ float g_att [294912];
__device__ float g_part[4194304];

// ---------------- conv5: 3x3, 2048->512 @ 16x16, K-split partial ----------------
__global__ void __launch_bounds__(256, 2)
conv5_partial(const float* __restrict__ in, const float* __restrict__ w,
              float* __restrict__ part)
{
    const int ks = blockIdx.x, ocb = blockIdx.y, n = blockIdx.z;
    __shared__ float s_in[8 * 342];        // 8 ic x (18 rows, stride 19)
    __shared__ float s_w [8 * 9 * 64];     // [ic][tap][oc]
    const int tid = threadIdx.x;
    const int og  = tid >> 5;
    const int pg  = tid & 31;
    const int py  = pg >> 1;
    const int px0 = (pg & 1) << 3;

    uint64_t acc2[4][8];
#pragma unroll
    for (int i = 0; i < 4; i++)
#pragma unroll
        for (int j = 0; j < 8; j++) acc2[i][j] = 0ull;

    const int icbase = ks * 128;
    for (int tile = 0; tile < 16; ++tile) {
        const int ict0 = icbase + tile * 8;
        __syncthreads();
        for (int i = tid; i < 8 * 324; i += 256) {
            const int ic = i / 324, rem = i - ic * 324;
            const int ry = rem / 18, rx = rem - ry * 18;
            const int yy = ry - 1, xx = rx - 1;
            float v = 0.f;
            if ((unsigned)yy < 16u && (unsigned)xx < 16u)
                v = in[(((size_t)n * 2048 + ict0 + ic) * 16 + yy) * 16 + xx];
            s_in[ic * 342 + ry * 19 + rx] = v;
        }
        for (int i = tid; i < 8 * 576; i += 256) {
            const int oc = i / 72, r = i - oc * 72;
            const int ic = r / 9, t = r - ic * 9;
            s_w[(ic * 9 + t) * 64 + oc] =
                w[(size_t)(ocb * 64 + oc) * 18432 + (size_t)(ict0 + ic) * 9 + t];
        }
        __syncthreads();
        for (int ic = 0; ic < 8; ++ic) {
            const float* si  = s_in + ic * 342;
            const float* swp = s_w  + ic * 576;
#pragma unroll
            for (int t = 0; t < 9; ++t) {
                const int r = t / 3, s = t - 3 * r;
                const uint64_t* wrow = (const uint64_t*)(swp + t * 64 + og * 8);
                uint64_t wv2[4];
#pragma unroll
                for (int i = 0; i < 4; i++) wv2[i] = wrow[i];
                const float* ib = si + (py + r) * 19 + px0 + s;
#pragma unroll
                for (int j = 0; j < 8; j++) {
                    const uint64_t iv2 = bcast2(ib[j]);
#pragma unroll
                    for (int i = 0; i < 4; i++) acc2[i][j] = fma2(wv2[i], iv2, acc2[i][j]);
                }
            }
        }
    }
    float* dst = part + (size_t)(ks * 2 + n) * 512 * 256;
    const int px = py * 16 + px0;
#pragma unroll
    for (int i = 0; i < 4; i++) {
        const int oc = ocb * 64 + og * 8 + 2 * i;
#pragma unroll
        for (int j = 0; j < 8; j++) {
            const float2 v = unpack2(acc2[i][j]);
            dst[oc * 256 + px + j]       = v.x;
            dst[(oc + 1) * 256 + px + j] = v.y;
        }
    }
}

// ---------------- generic 1x1 conv (GEMM) K-split partial ----------------
__global__ void __launch_bounds__(256)
conv1x1_partial(const float* __restrict__ in, const float* __restrict__ w,
                float* __restrict__ part,
                int Cin, int Cout, int P, int KS, int KCH)
{
    const int pxb = blockIdx.x;
    const int ocb = blockIdx.y / KS;
    const int ks  = blockIdx.y % KS;
    const int n   = blockIdx.z;
    const int k0  = ks * KCH;
    __shared__ float sA[16][68];
    __shared__ float sB[16][136];
    const int tid = threadIdx.x;
    const int ocg = tid >> 4;
    const int pxg = tid & 15;

    uint64_t acc2[4][4];
#pragma unroll
    for (int i = 0; i < 4; i++)
#pragma unroll
        for (int j = 0; j < 4; j++) acc2[i][j] = 0ull;

    const float* wrow = w + (size_t)(ocb * 64) * Cin + k0;
    const float* brow = in + ((size_t)n * Cin + k0) * P + pxb * 128;

    for (int kc = 0; kc < KCH; kc += 16) {
        __syncthreads();
        for (int i = tid; i < 1024; i += 256) {
            int oc = i >> 4, kk = i & 15;
            sA[kk][oc] = wrow[(size_t)oc * Cin + kc + kk];
        }
        for (int i = tid; i < 512; i += 256) {
            int kk = i >> 5, p4 = (i & 31) << 2;
            *(float4*)&sB[kk][p4] = *(const float4*)&brow[((size_t)(kc + kk)) * P + p4];
        }
        __syncthreads();
#pragma unroll
        for (int kk = 0; kk < 16; ++kk) {
            const float4 a4 = *(const float4*)&sA[kk][ocg << 2];
            const float4 b40 = *(const float4*)&sB[kk][pxg << 3];
            const float4 b41 = *(const float4*)&sB[kk][(pxg << 3) + 4];
            const uint64_t* b2 = (const uint64_t*)&b40;
            const uint64_t* b3 = (const uint64_t*)&b41;
            const uint64_t a0 = bcast2(a4.x), a1 = bcast2(a4.y);
            const uint64_t a2 = bcast2(a4.z), a3 = bcast2(a4.w);
            acc2[0][0] = fma2(a0, b2[0], acc2[0][0]);
            acc2[0][1] = fma2(a0, b2[1], acc2[0][1]);
            acc2[0][2] = fma2(a0, b3[0], acc2[0][2]);
            acc2[0][3] = fma2(a0, b3[1], acc2[0][3]);
            acc2[1][0] = fma2(a1, b2[0], acc2[1][0]);
            acc2[1][1] = fma2(a1, b2[1], acc2[1][1]);
            acc2[1][2] = fma2(a1, b3[0], acc2[1][2]);
            acc2[1][3] = fma2(a1, b3[1], acc2[1][3]);
            acc2[2][0] = fma2(a2, b2[0], acc2[2][0]);
            acc2[2][1] = fma2(a2, b2[1], acc2[2][1]);
            acc2[2][2] = fma2(a2, b3[0], acc2[2][2]);
            acc2[2][3] = fma2(a2, b3[1], acc2[2][3]);
            acc2[3][0] = fma2(a3, b2[0], acc2[3][0]);
            acc2[3][1] = fma2(a3, b2[1], acc2[3][1]);
            acc2[3][2] = fma2(a3, b3[0], acc2[3][2]);
            acc2[3][3] = fma2(a3, b3[1], acc2[3][3]);
        }
    }
    float* dst = part + (size_t)(ks * 2 + n) * Cout * P;
    const int ocx = ocb * 64 + (ocg << 2);
    const int px  = pxb * 128 + (pxg << 3);
#pragma unroll
    for (int i = 0; i < 4; i++) {
        const float2 v0 = unpack2(acc2[i][0]), v1 = unpack2(acc2[i][1]);
        const float2 v2 = unpack2(acc2[i][2]), v3 = unpack2(acc2[i][3]);
        *(float4*)&dst[(size_t)(ocx + i) * P + px]     = make_float4(v0.x, v0.y, v1.x, v1.y);
        *(float4*)&dst[(size_t)(ocx + i) * P + px + 4] = make_float4(v2.x, v2.y, v3.x, v3.y);
    }
}

// ---------------- 1x1 conv + fused BN (no K-split; used only where blocks >= 256) ----
__global__ void __launch_bounds__(256)
conv1x1_bn(const float* __restrict__ in, const float* __restrict__ w,
           const float* __restrict__ bn, float* __restrict__ outp,
           int Cin, int Cout, int P)
{
    const int pxb = blockIdx.x;
    const int ocb = blockIdx.y;
    const int n   = blockIdx.z;
    __shared__ float sA[16][68];
    __shared__ float sB[16][136];
    const int tid = threadIdx.x;
    const int ocg = tid >> 4;
    const int pxg = tid & 15;

    uint64_t acc2[4][4];
#pragma unroll
    for (int i = 0; i < 4; i++)
#pragma unroll
        for (int j = 0; j < 4; j++) acc2[i][j] = 0ull;

    const float* wrow = w + (size_t)(ocb * 64) * Cin;
    const float* brow = in + ((size_t)n * Cin) * P + pxb * 128;

    for (int kc = 0; kc < Cin; kc += 16) {
        __syncthreads();
        for (int i = tid; i < 1024; i += 256) {
            int oc = i >> 4, kk = i & 15;
            sA[kk][oc] = wrow[(size_t)oc * Cin + kc + kk];
        }
        for (int i = tid; i < 512; i += 256) {
            int kk = i >> 5, p4 = (i & 31) << 2;
            *(float4*)&sB[kk][p4] = *(const float4*)&brow[((size_t)(kc + kk)) * P + p4];
        }
        __syncthreads();
#pragma unroll
        for (int kk = 0; kk < 16; ++kk) {
            const float4 a4 = *(const float4*)&sA[kk][ocg << 2];
            const uint64_t* bp = (const uint64_t*)&sB[kk][pxg << 3];
            uint64_t b2[4] = { bp[0], bp[1], bp[2], bp[3] };
            const uint64_t a0 = bcast2(a4.x), a1 = bcast2(a4.y);
            const uint64_t a2 = bcast2(a4.z), a3 = bcast2(a4.w);
#pragma unroll
            for (int j = 0; j < 4; j++) {
                acc2[0][j] = fma2(a0, b2[j], acc2[0][j]);
                acc2[1][j] = fma2(a1, b2[j], acc2[1][j]);
                acc2[2][j] = fma2(a2, b2[j], acc2[2][j]);
                acc2[3][j] = fma2(a3, b2[j], acc2[3][j]);
            }
        }
    }
    const int ocx = ocb * 64 + (ocg << 2);
    const int px  = pxb * 128 + (pxg << 3);
#pragma unroll
    for (int i = 0; i < 4; i++) {
        const int oc = ocx + i;
        const float g = bn[oc], b = bn[Cout + oc], m = bn[2 * Cout + oc], v = bn[3 * Cout + oc];
        const float sc = g / sqrtf(v + BN_EPS);
        const float sh = b - m * sc;
        const float2 v0 = unpack2(acc2[i][0]), v1 = unpack2(acc2[i][1]);
        const float2 v2 = unpack2(acc2[i][2]), v3 = unpack2(acc2[i][3]);
        float* op = outp + ((size_t)n * Cout + oc) * P + px;
        *(float4*)op       = make_float4(v0.x * sc + sh, v0.y * sc + sh, v1.x * sc + sh, v1.y * sc + sh);
        *(float4*)(op + 4) = make_float4(v2.x * sc + sh, v2.y * sc + sh, v3.x * sc + sh, v3.y * sc + sh);
    }
}

// ---------------- reduce K-splits + BN (+ReLU), float4 ----------------
__global__ void __launch_bounds__(256)
reduce_bn4(const float4* __restrict__ part, const float* __restrict__ bn,
           float4* __restrict__ out, int C, int P, int KS, int relu)
{
    const int idx = blockIdx.x * 256 + threadIdx.x;
    const int total4 = 2 * C * P / 4;
    if (idx >= total4) return;
    const int c = ((idx * 4) / P) % C;
    const size_t stride4 = (size_t)2 * C * P / 4;
    float4 s = make_float4(0.f, 0.f, 0.f, 0.f);
    for (int k = 0; k < KS; ++k) {
        const float4 q = part[(size_t)k * stride4 + idx];
        s.x += q.x; s.y += q.y; s.z += q.z; s.w += q.w;
    }
    const float g = bn[c], b = bn[C + c], m = bn[2 * C + c], v = bn[3 * C + c];
    const float sc = g / sqrtf(v + BN_EPS);
    const float sh = b - m * sc;
    float4 r = make_float4(s.x * sc + sh, s.y * sc + sh, s.z * sc + sh, s.w * sc + sh);
    if (relu) {
        r.x = fmaxf(r.x, 0.f); r.y = fmaxf(r.y, 0.f);
        r.z = fmaxf(r.z, 0.f); r.w = fmaxf(r.w, 0.f);
    }
    out[idx] = r;
}

// ---------------- bilinear upsample (k path only) ----------------
__global__ void __launch_bounds__(256)
upsample_ac(const float* __restrict__ in, float* __restrict__ out,
            int NC, int h, int w, int H, int W, float sy, float sx)
{
    const int idx = blockIdx.x * 256 + threadIdx.x;
    const int total = NC * H * W;
    if (idx >= total) return;
    const int x  = idx % W;
    const int y  = (idx / W) % H;
    const int nc = idx / (W * H);
    const float fy = y * sy;
    const float fx = x * sx;
    int y0 = (int)fy; if (y0 > h - 1) y0 = h - 1;
    int x0 = (int)fx; if (x0 > w - 1) x0 = w - 1;
    const int y1 = min(y0 + 1, h - 1);
    const int x1 = min(x0 + 1, w - 1);
    const float wy = fy - y0, wx = fx - x0;
    const float* p = in + (size_t)nc * h * w;
    const float v00 = p[y0 * w + x0], v01 = p[y0 * w + x1];
    const float v10 = p[y1 * w + x0], v11 = p[y1 * w + x1];
    const float a = v00 * (1.f - wy) + v10 * wy;
    const float b = v01 * (1.f - wy) + v11 * wy;
    out[idx] = a * (1.f - wx) + b * wx;
}

// ---------------- attention v2: kd-split across block for SM parallelism ------
__global__ void __launch_bounds__(256)
attention_v2(const float* __restrict__ q, const float* __restrict__ kmap,
             float* __restrict__ att, int kd, int H, int W)
{
    __shared__ float s_part[32][8][36];
    __shared__ float s_red[8][36];
    const int tid  = threadIdx.x;
    const int qloc = tid & 7;
    const int si   = tid >> 3;
    const int Wq   = W >> 2;
    const int qg   = blockIdx.x * 8 + qloc;
    const int xq   = qg % Wq;
    const int y    = (qg / Wq) % H;
    const int n    = qg / (Wq * H);
    const int x0   = xq << 2;
    const size_t plane = (size_t)H * W;

    const bool lok = (x0 >= 4);
    const bool rok = (x0 + 4 < W);
    int rowoff[3]; bool rowok[3];
#pragma unroll
    for (int r = 0; r < 3; r++) {
        const int yy = y + (r - 1) * 2;
        rowok[r]  = ((unsigned)yy < (unsigned)H);
        rowoff[r] = yy * W + x0;
    }

    uint64_t lg[9][2];
#pragma unroll
    for (int t = 0; t < 9; t++) { lg[t][0] = 0ull; lg[t][1] = 0ull; }

    const int cpt = kd >> 5;
    const int c0  = si * cpt;
    const float* qp = q + ((size_t)n * kd + c0) * plane + (size_t)y * W + x0;
    const float* kp = kmap + ((size_t)n * kd + c0) * plane;
    const float4 z4 = make_float4(0.f, 0.f, 0.f, 0.f);

    for (int c = 0; c < cpt; ++c) {
        const float4 qv = *(const float4*)(qp + (size_t)c * plane);
        const uint64_t* qh = (const uint64_t*)&qv;
        const uint64_t q01 = qh[0], q23 = qh[1];
        const float* kc = kp + (size_t)c * plane;
#pragma unroll
        for (int r = 0; r < 3; r++) {
            if (!rowok[r]) continue;
            const float* kr = kc + rowoff[r];
            const float4 L = lok ? *(const float4*)(kr - 4) : z4;
            const float4 M = *(const float4*)kr;
            const float4 R = rok ? *(const float4*)(kr + 4) : z4;
            const uint64_t* Lh = (const uint64_t*)&L;
            const uint64_t* Mh = (const uint64_t*)&M;
            const uint64_t* Rh = (const uint64_t*)&R;
            const int t0 = r * 3;
            lg[t0 + 0][0] = fma2(q01, Lh[1], lg[t0 + 0][0]);
            lg[t0 + 0][1] = fma2(q23, Mh[0], lg[t0 + 0][1]);
            lg[t0 + 1][0] = fma2(q01, Mh[0], lg[t0 + 1][0]);
            lg[t0 + 1][1] = fma2(q23, Mh[1], lg[t0 + 1][1]);
            lg[t0 + 2][0] = fma2(q01, Mh[1], lg[t0 + 2][0]);
            lg[t0 + 2][1] = fma2(q23, Rh[0], lg[t0 + 2][1]);
        }
    }
#pragma unroll
    for (int t = 0; t < 9; t++) {
        const float2 a = unpack2(lg[t][0]);
        const float2 b = unpack2(lg[t][1]);
        s_part[si][qloc][t * 4 + 0] = a.x;
        s_part[si][qloc][t * 4 + 1] = a.y;
        s_part[si][qloc][t * 4 + 2] = b.x;
        s_part[si][qloc][t * 4 + 3] = b.y;
    }
    __syncthreads();

    for (int i = tid; i < 8 * 36; i += 256) {
        const int qq = i / 36, j = i - qq * 36;
        float s = 0.f;
#pragma unroll
        for (int s2 = 0; s2 < 32; s2++) s += s_part[s2][qq][j];
        s_red[qq][j] = s;
    }
    __syncthreads();

    if (tid < 32) {
        const int qq = tid >> 2, p = tid & 3;
        float l[9];
#pragma unroll
        for (int t = 0; t < 9; t++) l[t] = s_red[qq][t * 4 + p];
        float mx = l[0];
#pragma unroll
        for (int t = 1; t < 9; t++) mx = fmaxf(mx, l[t]);
        float s = 0.f;
#pragma unroll
        for (int t = 0; t < 9; t++) { l[t] = expf(l[t] - mx); s += l[t]; }
        const float inv = 1.f / s;
        const int qg2 = blockIdx.x * 8 + qq;
        const int xq2 = qg2 % Wq;
        const int y2  = (qg2 / Wq) % H;
        const int n2  = qg2 / (Wq * H);
        float* ap = att + (size_t)n2 * 9 * plane + (size_t)y2 * W + (xq2 << 2) + p;
#pragma unroll
        for (int t = 0; t < 9; t++) ap[(size_t)t * plane] = l[t] * inv;
    }
}

// ---------------- fused upsample + attention apply ----------------
template<int H, int W, int h, int w>
__global__ void __launch_bounds__(256)
apply_fused(const float* __restrict__ att, const float* __restrict__ lo,
            float* __restrict__ outp)
{
    constexpr int WPAD = W + 8;
    __shared__ __align__(16) float s_lo[8][6][w + 2];
    __shared__ __align__(16) float s_up[8][8][WPAD];
    const int y0  = blockIdx.x * 4;
    const int ch0 = blockIdx.y * 8;
    const int n   = blockIdx.z;
    const int tid = threadIdx.x;
    const int nth = blockDim.x;
    constexpr float sy = (float)(h - 1) / (float)(H - 1);
    constexpr float sx = (float)(w - 1) / (float)(W - 1);
    const size_t planeL = (size_t)h * w;
    const size_t planeH = (size_t)H * W;

    const int ylo = (y0 >= 2 ? y0 - 2 : 0);
    const int base = (int)((float)ylo * sy);
    for (int i = tid; i < 8 * 6 * w; i += nth) {
        const int ch = i / (6 * w);
        const int r  = (i / w) % 6;
        const int x  = i % w;
        const int gr = min(base + r, h - 1);
        s_lo[ch][r][x] = lo[((size_t)(n * 512 + ch0 + ch)) * planeL + (size_t)gr * w + x];
    }
    __syncthreads();

    for (int i = tid; i < 8 * 8 * WPAD; i += nth) {
        const int ch  = i / (8 * WPAD);
        const int rem = i - ch * (8 * WPAD);
        const int row = rem / WPAD;
        const int col = rem - row * WPAD;
        const int Y = y0 - 2 + row;
        const int X = col - 4;
        float v = 0.f;
        if ((unsigned)Y < (unsigned)H && (unsigned)X < (unsigned)W) {
            const float fy = Y * sy;
            int iy0 = (int)fy; if (iy0 > h - 1) iy0 = h - 1;
            const int ry0 = iy0 - base;
            const int ry1 = min(iy0 + 1, h - 1) - base;
            const float wy = fy - iy0;
            const float fx = X * sx;
            int ix0 = (int)fx; if (ix0 > w - 1) ix0 = w - 1;
            const int ix1 = min(ix0 + 1, w - 1);
            const float wx = fx - ix0;
            const float a = s_lo[ch][ry0][ix0] * (1.f - wx) + s_lo[ch][ry0][ix1] * wx;
            const float b = s_lo[ch][ry1][ix0] * (1.f - wx) + s_lo[ch][ry1][ix1] * wx;
            v = a * (1.f - wy) + b * wy;
        }
        s_up[ch][row][col] = v;
    }
    __syncthreads();

    const int Wp = W >> 1;
    const int xp = tid % Wp;
    const int yy = tid / Wp;
    const int y  = y0 + yy;
    const int x0 = xp << 1;

    uint64_t att2[9];
    const float* ap = att + (size_t)n * 9 * planeH + (size_t)y * W + x0;
#pragma unroll
    for (int t = 0; t < 9; t++) att2[t] = *(const uint64_t*)(ap + (size_t)t * planeH);

#pragma unroll
    for (int c = 0; c < 8; ++c) {
        uint64_t acc = 0ull;
#pragma unroll
        for (int iy = 0; iy < 3; iy++) {
            const float* rp = &s_up[c][yy + 2 * iy][0];
#pragma unroll
            for (int ix = 0; ix < 3; ix++) {
                const uint64_t u2 = *(const uint64_t*)(rp + x0 + 2 * ix + 2);
                acc = fma2(att2[iy * 3 + ix], u2, acc);
            }
        }
        const float2 v = unpack2(acc);
        *(float2*)&outp[((size_t)(n * 512 + ch0 + c)) * planeH + (size_t)y * W + x0] = v;
    }
}

// ---------------- conv6: 1x1, 512->19, C-split partial, f32x2 ----------------
__global__ void __launch_bounds__(128)
conv6_partial(const float* __restrict__ in, const float* __restrict__ w,
              float* __restrict__ part)
{
    __shared__ float sw[19 * 128];
    const int tid = threadIdx.x;
    const int cs  = blockIdx.y;
    const int n   = blockIdx.z;
    const int c0  = cs * 128;
    for (int i = tid; i < 19 * 128; i += 128) {
        const int o = i >> 7, c = i & 127;
        sw[i] = w[o * 512 + c0 + c];
    }
    __syncthreads();
    const int px = (blockIdx.x * 128 + tid) * 2;
    uint64_t acc2[19];
#pragma unroll
    for (int o = 0; o < 19; o++) acc2[o] = 0ull;
    const float* ip = in + ((size_t)n * 512 + c0) * 16384 + px;
    for (int c = 0; c < 128; ++c) {
        const uint64_t v2 = *(const uint64_t*)(ip + (size_t)c * 16384);
#pragma unroll
        for (int o = 0; o < 19; o++)
            acc2[o] = fma2(bcast2(sw[(o << 7) + c]), v2, acc2[o]);
    }
    float* op = part + ((size_t)(cs * 2 + n) * 19) * 16384 + px;
#pragma unroll
    for (int o = 0; o < 19; o++) {
        const float2 v = unpack2(acc2[o]);
        *(float2*)(op + (size_t)o * 16384) = v;
    }
}

// ---------------- conv6 reduce + bias, float4 ----------------
__global__ void __launch_bounds__(256)
conv6_reduce(const float4* __restrict__ part, const float* __restrict__ bias,
             float4* __restrict__ out)
{
    const int idx = blockIdx.x * 256 + threadIdx.x;
    const int perN = 19 * 16384 / 4;
    const int total = 2 * perN;
    if (idx >= total) return;
    const int n   = idx / perN;
    const int rem = idx - n * perN;
    const int o   = (rem * 4) / 16384;
    float4 s = make_float4(0.f, 0.f, 0.f, 0.f);
#pragma unroll
    for (int cs = 0; cs < 4; ++cs) {
        const float4 q = part[(size_t)(cs * 2 + n) * perN + rem];
        s.x += q.x; s.y += q.y; s.z += q.z; s.w += q.w;
    }
    const float b = bias[o];
    out[idx] = make_float4(s.x + b, s.y + b, s.z + b, s.w + b);
}

// ---------------- launch ----------------
extern "C" void kernel_launch(void* const* d_in, const int* in_sizes, int n_in,
                              void* d_out, int out_size)
{
    (void)in_sizes; (void)n_in; (void)out_size;
    const float* c1      = (const float*)d_in[0];
    const float* c2      = (const float*)d_in[1];
    const float* c3      = (const float*)d_in[2];
    const float* c4      = (const float*)d_in[3];
    const float* c30     = (const float*)d_in[5];
    const float* c40     = (const float*)d_in[6];
    const float* conv5_w = (const float*)d_in[7];
    const float* bn5     = (const float*)d_in[8];
    const float* conv6_w = (const float*)d_in[9];
    const float* conv6_b = (const float*)d_in[10];
    const float* lu4_w1  = (const float*)d_in[11];
    const float* lu4_bn1 = (const float*)d_in[12];
    const float* lu4_w2  = (const float*)d_in[13];
    const float* lu4_bn2 = (const float*)d_in[14];
    const float* lu3_w1  = (const float*)d_in[15];
    const float* lu3_bn1 = (const float*)d_in[16];
    const float* lu3_w2  = (const float*)d_in[17];
    const float* lu3_bn2 = (const float*)d_in[18];
    const float* lu2_w1  = (const float*)d_in[19];
    const float* lu2_bn1 = (const float*)d_in[20];
    const float* lu2_w2  = (const float*)d_in[21];
    const float* lu2_bn2 = (const float*)d_in[22];
    float* out = (float*)d_out;

    float *p_out, *p_up, *p_q, *p_k, *p_klo, *p_att, *p_part;
    cudaGetSymbolAddress((void**)&p_out,  g_out);
    cudaGetSymbolAddress((void**)&p_up,   g_up);
    cudaGetSymbolAddress((void**)&p_q,    g_q);
    cudaGetSymbolAddress((void**)&p_k,    g_k);
    cudaGetSymbolAddress((void**)&p_klo,  g_klo);
    cudaGetSymbolAddress((void**)&p_att,  g_att);
    cudaGetSymbolAddress((void**)&p_part, g_part);

    // ---- conv5 + BN + ReLU -> g_out (2,512,16,16) ----
    conv5_partial<<<dim3(16, 8, 2), 256>>>(c4, conv5_w, p_part);
    reduce_bn4<<<(2 * 512 * 256 / 4 + 255) / 256, 256>>>((const float4*)p_part, bn5, (float4*)p_out, 512, 256, 16, 1);

    // ---- localUp4: H=32, kd=128; lo=g_out -> g_up ----  (round-6 geometry)
    conv1x1_partial<<<dim3(8, 2 * 8, 2), 256>>>(c3, lu4_w1, p_part, 1024, 128, 1024, 8, 128);
    reduce_bn4<<<(2 * 128 * 1024 / 4 + 255) / 256, 256>>>((const float4*)p_part, lu4_bn1, (float4*)p_q, 128, 1024, 8, 0);
    conv1x1_partial<<<dim3(2, 2 * 64, 2), 256>>>(c40, lu4_w2, p_part, 2048, 128, 256, 64, 32);
    reduce_bn4<<<(2 * 128 * 256 / 4 + 255) / 256, 256>>>((const float4*)p_part, lu4_bn2, (float4*)p_klo, 128, 256, 64, 0);
    upsample_ac<<<(2 * 128 * 32 * 32 + 255) / 256, 256>>>(p_klo, p_k, 2 * 128, 16, 16, 32, 32, 15.f / 31.f, 15.f / 31.f);
    attention_v2<<<2 * 32 * 8 / 8, 256>>>(p_q, p_k, p_att, 128, 32, 32);
    apply_fused<32, 32, 16, 16><<<dim3(8, 64, 2), 64>>>(p_att, p_out, p_up);

    // ---- localUp3: H=64, kd=64; lo=g_up -> g_out ----  (KS=4: 256 blocks)
    conv1x1_partial<<<dim3(32, 1 * 4, 2), 256>>>(c2, lu3_w1, p_part, 512, 64, 4096, 4, 128);
    reduce_bn4<<<(2 * 64 * 4096 / 4 + 255) / 256, 256>>>((const float4*)p_part, lu3_bn1, (float4*)p_q, 64, 4096, 4, 0);
    conv1x1_partial<<<dim3(8, 1 * 32, 2), 256>>>(c30, lu3_w2, p_part, 1024, 64, 1024, 32, 32);
    reduce_bn4<<<(2 * 64 * 1024 / 4 + 255) / 256, 256>>>((const float4*)p_part, lu3_bn2, (float4*)p_klo, 64, 1024, 32, 0);
    upsample_ac<<<(2 * 64 * 64 * 64 + 255) / 256, 256>>>(p_klo, p_k, 2 * 64, 32, 32, 64, 64, 31.f / 63.f, 31.f / 63.f);
    attention_v2<<<2 * 64 * 16 / 8, 256>>>(p_q, p_k, p_att, 64, 64, 64);
    apply_fused<64, 64, 32, 32><<<dim3(16, 64, 2), 128>>>(p_att, p_up, p_out);

    // ---- localUp2: H=128, kd=64; lo=g_out -> g_up ----
    conv1x1_bn<<<dim3(128, 1, 2), 256>>>(c1, lu2_w1, lu2_bn1, p_q, 256, 64, 16384);
    conv1x1_partial<<<dim3(32, 1 * 4, 2), 256>>>(c2, lu2_w2, p_part, 512, 64, 4096, 4, 128);
    reduce_bn4<<<(2 * 64 * 4096 / 4 + 255) / 256, 256>>>((const float4*)p_part, lu2_bn2, (float4*)p_klo, 64, 4096, 4, 0);
    upsample_ac<<<(2 * 64 * 128 * 128 + 255) / 256, 256>>>(p_klo, p_k, 2 * 64, 64, 64, 128, 128, 63.f / 127.f, 63.f / 127.f);
    attention_v2<<<2 * 128 * 32 / 8, 256>>>(p_q, p_k, p_att, 64, 128, 128);
    apply_fused<128, 128, 64, 64><<<dim3(32, 64, 2), 256>>>(p_att, p_out, p_up);

    // ---- conv6 1x1 -> (2,19,128,128), C-split x4 ----
    conv6_partial<<<dim3(64, 4, 2), 128>>>(p_up, conv6_w, p_part);
    conv6_reduce<<<(2 * 19 * 16384 / 4 + 255) / 256, 256>>>((const float4*)p_part, conv6_b, (float4*)out);
}

// round 9
// speedup vs baseline: 1.2487x; 1.0216x over previous
#include <cuda_runtime.h>
#include <math.h>
#include <stdint.h>

#define BN_EPS 1e-5f

// ---------------- f32x2 helpers ----------------
__device__ __forceinline__ uint64_t bcast2(float v) {
    uint64_t r; asm("mov.b64 %0, {%1,%1};" : "=l"(r) : "f"(v)); return r;
}
__device__ __forceinline__ uint64_t fma2(uint64_t a, uint64_t b, uint64_t c) {
    uint64_t d; asm("fma.rn.f32x2 %0, %1, %2, %3;" : "=l"(d) : "l"(a), "l"(b), "l"(c)); return d;
}
__device__ __forceinline__ float2 unpack2(uint64_t v) {
    float2 f; asm("mov.b64 {%0,%1}, %2;" : "=f"(f.x), "=f"(f.y) : "l"(v)); return f;
}

// ---------------- scratch ----------------
__device__ float g_out [16777216];  // ping
__device__ float g_up  [16777216];  // pong
__device__ float g_q   [2097152];
__device__ float g_q2  [2097152];   // localUp2 q (computed early, must survive)
__device__ float g_k   [2097152];
__device__ float g_klo [524288];
__device__ float g_att [294912];
__device__ float g_part[4194304];

// ---------------- conv5: 3x3, 2048->512 @ 16x16, K-split partial ----------------
__global__ void __launch_bounds__(256, 2)
conv5_partial(const float* __restrict__ in, const float* __restrict__ w,
              float* __restrict__ part)
{
    const int ks = blockIdx.x, ocb = blockIdx.y, n = blockIdx.z;
    __shared__ float s_in[8 * 342];        // 8 ic x (18 rows, stride 19)
    __shared__ float s_w [8 * 9 * 64];     // [ic][tap][oc]
    const int tid = threadIdx.x;
    const int og  = tid >> 5;
    const int pg  = tid & 31;
    const int py  = pg >> 1;
    const int px0 = (pg & 1) << 3;

    uint64_t acc2[4][8];
#pragma unroll
    for (int i = 0; i < 4; i++)
#pragma unroll
        for (int j = 0; j < 8; j++) acc2[i][j] = 0ull;

    const int icbase = ks * 128;
    for (int tile = 0; tile < 16; ++tile) {
        const int ict0 = icbase + tile * 8;
        __syncthreads();
        for (int i = tid; i < 8 * 324; i += 256) {
            const int ic = i / 324, rem = i - ic * 324;
            const int ry = rem / 18, rx = rem - ry * 18;
            const int yy = ry - 1, xx = rx - 1;
            float v = 0.f;
            if ((unsigned)yy < 16u && (unsigned)xx < 16u)
                v = in[(((size_t)n * 2048 + ict0 + ic) * 16 + yy) * 16 + xx];
            s_in[ic * 342 + ry * 19 + rx] = v;
        }
        for (int i = tid; i < 8 * 576; i += 256) {
            const int oc = i / 72, r = i - oc * 72;
            const int ic = r / 9, t = r - ic * 9;
            s_w[(ic * 9 + t) * 64 + oc] =
                w[(size_t)(ocb * 64 + oc) * 18432 + (size_t)(ict0 + ic) * 9 + t];
        }
        __syncthreads();
        for (int ic = 0; ic < 8; ++ic) {
            const float* si  = s_in + ic * 342;
            const float* swp = s_w  + ic * 576;
#pragma unroll
            for (int t = 0; t < 9; ++t) {
                const int r = t / 3, s = t - 3 * r;
                const uint64_t* wrow = (const uint64_t*)(swp + t * 64 + og * 8);
                uint64_t wv2[4];
#pragma unroll
                for (int i = 0; i < 4; i++) wv2[i] = wrow[i];
                const float* ib = si + (py + r) * 19 + px0 + s;
#pragma unroll
                for (int j = 0; j < 8; j++) {
                    const uint64_t iv2 = bcast2(ib[j]);
#pragma unroll
                    for (int i = 0; i < 4; i++) acc2[i][j] = fma2(wv2[i], iv2, acc2[i][j]);
                }
            }
        }
    }
    float* dst = part + (size_t)(ks * 2 + n) * 512 * 256;
    const int px = py * 16 + px0;
#pragma unroll
    for (int i = 0; i < 4; i++) {
        const int oc = ocb * 64 + og * 8 + 2 * i;
#pragma unroll
        for (int j = 0; j < 8; j++) {
            const float2 v = unpack2(acc2[i][j]);
            dst[oc * 256 + px + j]       = v.x;
            dst[(oc + 1) * 256 + px + j] = v.y;
        }
    }
}

// ---------------- generic 1x1 conv (GEMM) K-split partial ----------------
__global__ void __launch_bounds__(256)
conv1x1_partial(const float* __restrict__ in, const float* __restrict__ w,
                float* __restrict__ part,
                int Cin, int Cout, int P, int KS, int KCH)
{
    const int pxb = blockIdx.x;
    const int ocb = blockIdx.y / KS;
    const int ks  = blockIdx.y % KS;
    const int n   = blockIdx.z;
    const int k0  = ks * KCH;
    __shared__ float sA[16][68];
    __shared__ float sB[16][136];
    const int tid = threadIdx.x;
    const int ocg = tid >> 4;
    const int pxg = tid & 15;

    uint64_t acc2[4][4];
#pragma unroll
    for (int i = 0; i < 4; i++)
#pragma unroll
        for (int j = 0; j < 4; j++) acc2[i][j] = 0ull;

    const float* wrow = w + (size_t)(ocb * 64) * Cin + k0;
    const float* brow = in + ((size_t)n * Cin + k0) * P + pxb * 128;

    for (int kc = 0; kc < KCH; kc += 16) {
        __syncthreads();
        for (int i = tid; i < 1024; i += 256) {
            int oc = i >> 4, kk = i & 15;
            sA[kk][oc] = wrow[(size_t)oc * Cin + kc + kk];
        }
        for (int i = tid; i < 512; i += 256) {
            int kk = i >> 5, p4 = (i & 31) << 2;
            *(float4*)&sB[kk][p4] = *(const float4*)&brow[((size_t)(kc + kk)) * P + p4];
        }
        __syncthreads();
#pragma unroll
        for (int kk = 0; kk < 16; ++kk) {
            const float4 a4 = *(const float4*)&sA[kk][ocg << 2];
            const float4 b40 = *(const float4*)&sB[kk][pxg << 3];
            const float4 b41 = *(const float4*)&sB[kk][(pxg << 3) + 4];
            const uint64_t* b2 = (const uint64_t*)&b40;
            const uint64_t* b3 = (const uint64_t*)&b41;
            const uint64_t a0 = bcast2(a4.x), a1 = bcast2(a4.y);
            const uint64_t a2 = bcast2(a4.z), a3 = bcast2(a4.w);
            acc2[0][0] = fma2(a0, b2[0], acc2[0][0]);
            acc2[0][1] = fma2(a0, b2[1], acc2[0][1]);
            acc2[0][2] = fma2(a0, b3[0], acc2[0][2]);
            acc2[0][3] = fma2(a0, b3[1], acc2[0][3]);
            acc2[1][0] = fma2(a1, b2[0], acc2[1][0]);
            acc2[1][1] = fma2(a1, b2[1], acc2[1][1]);
            acc2[1][2] = fma2(a1, b3[0], acc2[1][2]);
            acc2[1][3] = fma2(a1, b3[1], acc2[1][3]);
            acc2[2][0] = fma2(a2, b2[0], acc2[2][0]);
            acc2[2][1] = fma2(a2, b2[1], acc2[2][1]);
            acc2[2][2] = fma2(a2, b3[0], acc2[2][2]);
            acc2[2][3] = fma2(a2, b3[1], acc2[2][3]);
            acc2[3][0] = fma2(a3, b2[0], acc2[3][0]);
            acc2[3][1] = fma2(a3, b2[1], acc2[3][1]);
            acc2[3][2] = fma2(a3, b3[0], acc2[3][2]);
            acc2[3][3] = fma2(a3, b3[1], acc2[3][3]);
        }
    }
    float* dst = part + (size_t)(ks * 2 + n) * Cout * P;
    const int ocx = ocb * 64 + (ocg << 2);
    const int px  = pxb * 128 + (pxg << 3);
#pragma unroll
    for (int i = 0; i < 4; i++) {
        const float2 v0 = unpack2(acc2[i][0]), v1 = unpack2(acc2[i][1]);
        const float2 v2 = unpack2(acc2[i][2]), v3 = unpack2(acc2[i][3]);
        *(float4*)&dst[(size_t)(ocx + i) * P + px]     = make_float4(v0.x, v0.y, v1.x, v1.y);
        *(float4*)&dst[(size_t)(ocx + i) * P + px + 4] = make_float4(v2.x, v2.y, v3.x, v3.y);
    }
}

// ---------------- 1x1 conv + fused BN (no K-split; used only where blocks >= 256) ----
__global__ void __launch_bounds__(256)
conv1x1_bn(const float* __restrict__ in, const float* __restrict__ w,
           const float* __restrict__ bn, float* __restrict__ outp,
           int Cin, int Cout, int P)
{
    const int pxb = blockIdx.x;
    const int ocb = blockIdx.y;
    const int n   = blockIdx.z;
    __shared__ float sA[16][68];
    __shared__ float sB[16][136];
    const int tid = threadIdx.x;
    const int ocg = tid >> 4;
    const int pxg = tid & 15;

    uint64_t acc2[4][4];
#pragma unroll
    for (int i = 0; i < 4; i++)
#pragma unroll
        for (int j = 0; j < 4; j++) acc2[i][j] = 0ull;

    const float* wrow = w + (size_t)(ocb * 64) * Cin;
    const float* brow = in + ((size_t)n * Cin) * P + pxb * 128;

    for (int kc = 0; kc < Cin; kc += 16) {
        __syncthreads();
        for (int i = tid; i < 1024; i += 256) {
            int oc = i >> 4, kk = i & 15;
            sA[kk][oc] = wrow[(size_t)oc * Cin + kc + kk];
        }
        for (int i = tid; i < 512; i += 256) {
            int kk = i >> 5, p4 = (i & 31) << 2;
            *(float4*)&sB[kk][p4] = *(const float4*)&brow[((size_t)(kc + kk)) * P + p4];
        }
        __syncthreads();
#pragma unroll
        for (int kk = 0; kk < 16; ++kk) {
            const float4 a4 = *(const float4*)&sA[kk][ocg << 2];
            const uint64_t* bp = (const uint64_t*)&sB[kk][pxg << 3];
            uint64_t b2[4] = { bp[0], bp[1], bp[2], bp[3] };
            const uint64_t a0 = bcast2(a4.x), a1 = bcast2(a4.y);
            const uint64_t a2 = bcast2(a4.z), a3 = bcast2(a4.w);
#pragma unroll
            for (int j = 0; j < 4; j++) {
                acc2[0][j] = fma2(a0, b2[j], acc2[0][j]);
                acc2[1][j] = fma2(a1, b2[j], acc2[1][j]);
                acc2[2][j] = fma2(a2, b2[j], acc2[2][j]);
                acc2[3][j] = fma2(a3, b2[j], acc2[3][j]);
            }
        }
    }
    const int ocx = ocb * 64 + (ocg << 2);
    const int px  = pxb * 128 + (pxg << 3);
#pragma unroll
    for (int i = 0; i < 4; i++) {
        const int oc = ocx + i;
        const float g = bn[oc], b = bn[Cout + oc], m = bn[2 * Cout + oc], v = bn[3 * Cout + oc];
        const float sc = g / sqrtf(v + BN_EPS);
        const float sh = b - m * sc;
        const float2 v0 = unpack2(acc2[i][0]), v1 = unpack2(acc2[i][1]);
        const float2 v2 = unpack2(acc2[i][2]), v3 = unpack2(acc2[i][3]);
        float* op = outp + ((size_t)n * Cout + oc) * P + px;
        *(float4*)op       = make_float4(v0.x * sc + sh, v0.y * sc + sh, v1.x * sc + sh, v1.y * sc + sh);
        *(float4*)(op + 4) = make_float4(v2.x * sc + sh, v2.y * sc + sh, v3.x * sc + sh, v3.y * sc + sh);
    }
}

// ---------------- reduce K-splits + BN (+ReLU), float4 ----------------
__global__ void __launch_bounds__(256)
reduce_bn4(const float4* __restrict__ part, const float* __restrict__ bn,
           float4* __restrict__ out, int C, int P, int KS, int relu)
{
    const int idx = blockIdx.x * 256 + threadIdx.x;
    const int total4 = 2 * C * P / 4;
    if (idx >= total4) return;
    const int c = ((idx * 4) / P) % C;
    const size_t stride4 = (size_t)2 * C * P / 4;
    float4 s = make_float4(0.f, 0.f, 0.f, 0.f);
    for (int k = 0; k < KS; ++k) {
        const float4 q = part[(size_t)k * stride4 + idx];
        s.x += q.x; s.y += q.y; s.z += q.z; s.w += q.w;
    }
    const float g = bn[c], b = bn[C + c], m = bn[2 * C + c], v = bn[3 * C + c];
    const float sc = g / sqrtf(v + BN_EPS);
    const float sh = b - m * sc;
    float4 r = make_float4(s.x * sc + sh, s.y * sc + sh, s.z * sc + sh, s.w * sc + sh);
    if (relu) {
        r.x = fmaxf(r.x, 0.f); r.y = fmaxf(r.y, 0.f);
        r.z = fmaxf(r.z, 0.f); r.w = fmaxf(r.w, 0.f);
    }
    out[idx] = r;
}

// ---------------- bilinear upsample (k path only) ----------------
__global__ void __launch_bounds__(256)
upsample_ac(const float* __restrict__ in, float* __restrict__ out,
            int NC, int h, int w, int H, int W, float sy, float sx)
{
    const int idx = blockIdx.x * 256 + threadIdx.x;
    const int total = NC * H * W;
    if (idx >= total) return;
    const int x  = idx % W;
    const int y  = (idx / W) % H;
    const int nc = idx / (W * H);
    const float fy = y * sy;
    const float fx = x * sx;
    int y0 = (int)fy; if (y0 > h - 1) y0 = h - 1;
    int x0 = (int)fx; if (x0 > w - 1) x0 = w - 1;
    const int y1 = min(y0 + 1, h - 1);
    const int x1 = min(x0 + 1, w - 1);
    const float wy = fy - y0, wx = fx - x0;
    const float* p = in + (size_t)nc * h * w;
    const float v00 = p[y0 * w + x0], v01 = p[y0 * w + x1];
    const float v10 = p[y1 * w + x0], v11 = p[y1 * w + x1];
    const float a = v00 * (1.f - wy) + v10 * wy;
    const float b = v01 * (1.f - wy) + v11 * wy;
    out[idx] = a * (1.f - wx) + b * wx;
}

// ---------------- attention v2: kd-split across block for SM parallelism ------
__global__ void __launch_bounds__(256)
attention_v2(const float* __restrict__ q, const float* __restrict__ kmap,
             float* __restrict__ att, int kd, int H, int W)
{
    __shared__ float s_part[32][8][36];
    __shared__ float s_red[8][36];
    const int tid  = threadIdx.x;
    const int qloc = tid & 7;
    const int si   = tid >> 3;
    const int Wq   = W >> 2;
    const int qg   = blockIdx.x * 8 + qloc;
    const int xq   = qg % Wq;
    const int y    = (qg / Wq) % H;
    const int n    = qg / (Wq * H);
    const int x0   = xq << 2;
    const size_t plane = (size_t)H * W;

    const bool lok = (x0 >= 4);
    const bool rok = (x0 + 4 < W);
    int rowoff[3]; bool rowok[3];
#pragma unroll
    for (int r = 0; r < 3; r++) {
        const int yy = y + (r - 1) * 2;
        rowok[r]  = ((unsigned)yy < (unsigned)H);
        rowoff[r] = yy * W + x0;
    }

    uint64_t lg[9][2];
#pragma unroll
    for (int t = 0; t < 9; t++) { lg[t][0] = 0ull; lg[t][1] = 0ull; }

    const int cpt = kd >> 5;
    const int c0  = si * cpt;
    const float* qp = q + ((size_t)n * kd + c0) * plane + (size_t)y * W + x0;
    const float* kp = kmap + ((size_t)n * kd + c0) * plane;
    const float4 z4 = make_float4(0.f, 0.f, 0.f, 0.f);

    for (int c = 0; c < cpt; ++c) {
        const float4 qv = *(const float4*)(qp + (size_t)c * plane);
        const uint64_t* qh = (const uint64_t*)&qv;
        const uint64_t q01 = qh[0], q23 = qh[1];
        const float* kc = kp + (size_t)c * plane;
#pragma unroll
        for (int r = 0; r < 3; r++) {
            if (!rowok[r]) continue;
            const float* kr = kc + rowoff[r];
            const float4 L = lok ? *(const float4*)(kr - 4) : z4;
            const float4 M = *(const float4*)kr;
            const float4 R = rok ? *(const float4*)(kr + 4) : z4;
            const uint64_t* Lh = (const uint64_t*)&L;
            const uint64_t* Mh = (const uint64_t*)&M;
            const uint64_t* Rh = (const uint64_t*)&R;
            const int t0 = r * 3;
            lg[t0 + 0][0] = fma2(q01, Lh[1], lg[t0 + 0][0]);
            lg[t0 + 0][1] = fma2(q23, Mh[0], lg[t0 + 0][1]);
            lg[t0 + 1][0] = fma2(q01, Mh[0], lg[t0 + 1][0]);
            lg[t0 + 1][1] = fma2(q23, Mh[1], lg[t0 + 1][1]);
            lg[t0 + 2][0] = fma2(q01, Mh[1], lg[t0 + 2][0]);
            lg[t0 + 2][1] = fma2(q23, Rh[0], lg[t0 + 2][1]);
        }
    }
#pragma unroll
    for (int t = 0; t < 9; t++) {
        const float2 a = unpack2(lg[t][0]);
        const float2 b = unpack2(lg[t][1]);
        s_part[si][qloc][t * 4 + 0] = a.x;
        s_part[si][qloc][t * 4 + 1] = a.y;
        s_part[si][qloc][t * 4 + 2] = b.x;
        s_part[si][qloc][t * 4 + 3] = b.y;
    }
    __syncthreads();

    for (int i = tid; i < 8 * 36; i += 256) {
        const int qq = i / 36, j = i - qq * 36;
        float s = 0.f;
#pragma unroll
        for (int s2 = 0; s2 < 32; s2++) s += s_part[s2][qq][j];
        s_red[qq][j] = s;
    }
    __syncthreads();

    if (tid < 32) {
        const int qq = tid >> 2, p = tid & 3;
        float l[9];
#pragma unroll
        for (int t = 0; t < 9; t++) l[t] = s_red[qq][t * 4 + p];
        float mx = l[0];
#pragma unroll
        for (int t = 1; t < 9; t++) mx = fmaxf(mx, l[t]);
        float s = 0.f;
#pragma unroll
        for (int t = 0; t < 9; t++) { l[t] = expf(l[t] - mx); s += l[t]; }
        const float inv = 1.f / s;
        const int qg2 = blockIdx.x * 8 + qq;
        const int xq2 = qg2 % Wq;
        const int y2  = (qg2 / Wq) % H;
        const int n2  = qg2 / (Wq * H);
        float* ap = att + (size_t)n2 * 9 * plane + (size_t)y2 * W + (xq2 << 2) + p;
#pragma unroll
        for (int t = 0; t < 9; t++) ap[(size_t)t * plane] = l[t] * inv;
    }
}

// ---------------- fused upsample + attention apply ----------------
template<int H, int W, int h, int w>
__global__ void __launch_bounds__(256)
apply_fused(const float* __restrict__ att, const float* __restrict__ lo,
            float* __restrict__ outp)
{
    constexpr int WPAD = W + 8;
    __shared__ __align__(16) float s_lo[8][6][w + 2];
    __shared__ __align__(16) float s_up[8][8][WPAD];
    const int y0  = blockIdx.x * 4;
    const int ch0 = blockIdx.y * 8;
    const int n   = blockIdx.z;
    const int tid = threadIdx.x;
    const int nth = blockDim.x;
    constexpr float sy = (float)(h - 1) / (float)(H - 1);
    constexpr float sx = (float)(w - 1) / (float)(W - 1);
    const size_t planeL = (size_t)h * w;
    const size_t planeH = (size_t)H * W;

    const int ylo = (y0 >= 2 ? y0 - 2 : 0);
    const int base = (int)((float)ylo * sy);
    for (int i = tid; i < 8 * 6 * w; i += nth) {
        const int ch = i / (6 * w);
        const int r  = (i / w) % 6;
        const int x  = i % w;
        const int gr = min(base + r, h - 1);
        s_lo[ch][r][x] = lo[((size_t)(n * 512 + ch0 + ch)) * planeL + (size_t)gr * w + x];
    }
    __syncthreads();

    for (int i = tid; i < 8 * 8 * WPAD; i += nth) {
        const int ch  = i / (8 * WPAD);
        const int rem = i - ch * (8 * WPAD);
        const int row = rem / WPAD;
        const int col = rem - row * WPAD;
        const int Y = y0 - 2 + row;
        const int X = col - 4;
        float v = 0.f;
        if ((unsigned)Y < (unsigned)H && (unsigned)X < (unsigned)W) {
            const float fy = Y * sy;
            int iy0 = (int)fy; if (iy0 > h - 1) iy0 = h - 1;
            const int ry0 = iy0 - base;
            const int ry1 = min(iy0 + 1, h - 1) - base;
            const float wy = fy - iy0;
            const float fx = X * sx;
            int ix0 = (int)fx; if (ix0 > w - 1) ix0 = w - 1;
            const int ix1 = min(ix0 + 1, w - 1);
            const float wx = fx - ix0;
            const float a = s_lo[ch][ry0][ix0] * (1.f - wx) + s_lo[ch][ry0][ix1] * wx;
            const float b = s_lo[ch][ry1][ix0] * (1.f - wx) + s_lo[ch][ry1][ix1] * wx;
            v = a * (1.f - wy) + b * wy;
        }
        s_up[ch][row][col] = v;
    }
    __syncthreads();

    const int Wp = W >> 1;
    const int xp = tid % Wp;
    const int yy = tid / Wp;
    const int y  = y0 + yy;
    const int x0 = xp << 1;

    uint64_t att2[9];
    const float* ap = att + (size_t)n * 9 * planeH + (size_t)y * W + x0;
#pragma unroll
    for (int t = 0; t < 9; t++) att2[t] = *(const uint64_t*)(ap + (size_t)t * planeH);

#pragma unroll
    for (int c = 0; c < 8; ++c) {
        uint64_t acc = 0ull;
#pragma unroll
        for (int iy = 0; iy < 3; iy++) {
            const float* rp = &s_up[c][yy + 2 * iy][0];
#pragma unroll
            for (int ix = 0; ix < 3; ix++) {
                const uint64_t u2 = *(const uint64_t*)(rp + x0 + 2 * ix + 2);
                acc = fma2(att2[iy * 3 + ix], u2, acc);
            }
        }
        const float2 v = unpack2(acc);
        *(float2*)&outp[((size_t)(n * 512 + ch0 + c)) * planeH + (size_t)y * W + x0] = v;
    }
}

// ---------------- conv6: 1x1, 512->19, C-split partial, f32x2 ----------------
__global__ void __launch_bounds__(128)
conv6_partial(const float* __restrict__ in, const float* __restrict__ w,
              float* __restrict__ part)
{
    __shared__ float sw[19 * 128];
    const int tid = threadIdx.x;
    const int cs  = blockIdx.y;
    const int n   = blockIdx.z;
    const int c0  = cs * 128;
    for (int i = tid; i < 19 * 128; i += 128) {
        const int o = i >> 7, c = i & 127;
        sw[i] = w[o * 512 + c0 + c];
    }
    __syncthreads();
    const int px = (blockIdx.x * 128 + tid) * 2;
    uint64_t acc2[19];
#pragma unroll
    for (int o = 0; o < 19; o++) acc2[o] = 0ull;
    const float* ip = in + ((size_t)n * 512 + c0) * 16384 + px;
    for (int c = 0; c < 128; ++c) {
        const uint64_t v2 = *(const uint64_t*)(ip + (size_t)c * 16384);
#pragma unroll
        for (int o = 0; o < 19; o++)
            acc2[o] = fma2(bcast2(sw[(o << 7) + c]), v2, acc2[o]);
    }
    float* op = part + ((size_t)(cs * 2 + n) * 19) * 16384 + px;
#pragma unroll
    for (int o = 0; o < 19; o++) {
        const float2 v = unpack2(acc2[o]);
        *(float2*)(op + (size_t)o * 16384) = v;
    }
}

// ---------------- conv6 reduce + bias, float4 ----------------
__global__ void __launch_bounds__(256)
conv6_reduce(const float4* __restrict__ part, const float* __restrict__ bias,
             float4* __restrict__ out)
{
    const int idx = blockIdx.x * 256 + threadIdx.x;
    const int perN = 19 * 16384 / 4;
    const int total = 2 * perN;
    if (idx >= total) return;
    const int n   = idx / perN;
    const int rem = idx - n * perN;
    const int o   = (rem * 4) / 16384;
    float4 s = make_float4(0.f, 0.f, 0.f, 0.f);
#pragma unroll
    for (int cs = 0; cs < 4; ++cs) {
        const float4 q = part[(size_t)(cs * 2 + n) * perN + rem];
        s.x += q.x; s.y += q.y; s.z += q.z; s.w += q.w;
    }
    const float b = bias[o];
    out[idx] = make_float4(s.x + b, s.y + b, s.z + b, s.w + b);
}

// ---------------- launch ----------------
extern "C" void kernel_launch(void* const* d_in, const int* in_sizes, int n_in,
                              void* d_out, int out_size)
{
    (void)in_sizes; (void)n_in; (void)out_size;
    const float* c1      = (const float*)d_in[0];
    const float* c2      = (const float*)d_in[1];
    const float* c3      = (const float*)d_in[2];
    const float* c4      = (const float*)d_in[3];
    const float* c30     = (const float*)d_in[5];
    const float* c40     = (const float*)d_in[6];
    const float* conv5_w = (const float*)d_in[7];
    const float* bn5     = (const float*)d_in[8];
    const float* conv6_w = (const float*)d_in[9];
    const float* conv6_b = (const float*)d_in[10];
    const float* lu4_w1  = (const float*)d_in[11];
    const float* lu4_bn1 = (const float*)d_in[12];
    const float* lu4_w2  = (const float*)d_in[13];
    const float* lu4_bn2 = (const float*)d_in[14];
    const float* lu3_w1  = (const float*)d_in[15];
    const float* lu3_bn1 = (const float*)d_in[16];
    const float* lu3_w2  = (const float*)d_in[17];
    const float* lu3_bn2 = (const float*)d_in[18];
    const float* lu2_w1  = (const float*)d_in[19];
    const float* lu2_bn1 = (const float*)d_in[20];
    const float* lu2_w2  = (const float*)d_in[21];
    const float* lu2_bn2 = (const float*)d_in[22];
    float* out = (float*)d_out;

    float *p_out, *p_up, *p_q, *p_q2, *p_k, *p_klo, *p_att, *p_part;
    cudaGetSymbolAddress((void**)&p_out,  g_out);
    cudaGetSymbolAddress((void**)&p_up,   g_up);
    cudaGetSymbolAddress((void**)&p_q,    g_q);
    cudaGetSymbolAddress((void**)&p_q2,   g_q2);
    cudaGetSymbolAddress((void**)&p_k,    g_k);
    cudaGetSymbolAddress((void**)&p_klo,  g_klo);
    cudaGetSymbolAddress((void**)&p_att,  g_att);
    cudaGetSymbolAddress((void**)&p_part, g_part);

    // ---- conv5 + BN + ReLU -> g_out (2,512,16,16) ----
    conv5_partial<<<dim3(16, 8, 2), 256>>>(c4, conv5_w, p_part);                                       // #1
    reduce_bn4<<<(2 * 512 * 256 / 4 + 255) / 256, 256>>>((const float4*)p_part, bn5, (float4*)p_out, 512, 256, 16, 1); // #2

    // ---- localUp2 q projection early (independent; dedicated buffer) ----
    conv1x1_bn<<<dim3(128, 1, 2), 256>>>(c1, lu2_w1, lu2_bn1, p_q2, 256, 64, 16384);                   // #3

    // ---- localUp4: H=32, kd=128; lo=g_out -> g_up ----  (round-6 geometry)
    conv1x1_partial<<<dim3(8, 2 * 8, 2), 256>>>(c3, lu4_w1, p_part, 1024, 128, 1024, 8, 128);          // #4 (profiled)
    reduce_bn4<<<(2 * 128 * 1024 / 4 + 255) / 256, 256>>>((const float4*)p_part, lu4_bn1, (float4*)p_q, 128, 1024, 8, 0);
    conv1x1_partial<<<dim3(2, 2 * 64, 2), 256>>>(c40, lu4_w2, p_part, 2048, 128, 256, 64, 32);
    reduce_bn4<<<(2 * 128 * 256 / 4 + 255) / 256, 256>>>((const float4*)p_part, lu4_bn2, (float4*)p_klo, 128, 256, 64, 0);
    upsample_ac<<<(2 * 128 * 32 * 32 + 255) / 256, 256>>>(p_klo, p_k, 2 * 128, 16, 16, 32, 32, 15.f / 31.f, 15.f / 31.f);
    attention_v2<<<2 * 32 * 8 / 8, 256>>>(p_q, p_k, p_att, 128, 32, 32);
    apply_fused<32, 32, 16, 16><<<dim3(8, 64, 2), 64>>>(p_att, p_out, p_up);

    // ---- localUp3: H=64, kd=64; lo=g_up -> g_out ----  (round-6 geometry: KS=8)
    conv1x1_partial<<<dim3(32, 1 * 8, 2), 256>>>(c2, lu3_w1, p_part, 512, 64, 4096, 8, 64);
    reduce_bn4<<<(2 * 64 * 4096 / 4 + 255) / 256, 256>>>((const float4*)p_part, lu3_bn1, (float4*)p_q, 64, 4096, 8, 0);
    conv1x1_partial<<<dim3(8, 1 * 32, 2), 256>>>(c30, lu3_w2, p_part, 1024, 64, 1024, 32, 32);
    reduce_bn4<<<(2 * 64 * 1024 / 4 + 255) / 256, 256>>>((const float4*)p_part, lu3_bn2, (float4*)p_klo, 64, 1024, 32, 0);
    upsample_ac<<<(2 * 64 * 64 * 64 + 255) / 256, 256>>>(p_klo, p_k, 2 * 64, 32, 32, 64, 64, 31.f / 63.f, 31.f / 63.f);
    attention_v2<<<2 * 64 * 16 / 8, 256>>>(p_q, p_k, p_att, 64, 64, 64);
    apply_fused<64, 64, 32, 32><<<dim3(16, 64, 2), 128>>>(p_att, p_up, p_out);

    // ---- localUp2: H=128, kd=64; lo=g_out -> g_up ----  (q already in g_q2; KS=8)
    conv1x1_partial<<<dim3(32, 1 * 8, 2), 256>>>(c2, lu2_w2, p_part, 512, 64, 4096, 8, 64);
    reduce_bn4<<<(2 * 64 * 4096 / 4 + 255) / 256, 256>>>((const float4*)p_part, lu2_bn2, (float4*)p_klo, 64, 4096, 8, 0);
    upsample_ac<<<(2 * 64 * 128 * 128 + 255) / 256, 256>>>(p_klo, p_k, 2 * 64, 64, 64, 128, 128, 63.f / 127.f, 63.f / 127.f);
    attention_v2<<<2 * 128 * 32 / 8, 256>>>(p_q2, p_k, p_att, 64, 128, 128);
    apply_fused<128, 128, 64, 64><<<dim3(32, 64, 2), 256>>>(p_att, p_out, p_up);

    // ---- conv6 1x1 -> (2,19,128,128), C-split x4 ----
    conv6_partial<<<dim3(64, 4, 2), 128>>>(p_up, conv6_w, p_part);
    conv6_reduce<<<(2 * 19 * 16384 / 4 + 255) / 256, 256>>>((const float4*)p_part, conv6_b, (float4*)out);
}

// round 11
// speedup vs baseline: 1.3034x; 1.0438x over previous
#include <cuda_runtime.h>
#include <math.h>
#include <stdint.h>

#define BN_EPS 1e-5f

// ---------------- f32x2 helpers ----------------
__device__ __forceinline__ uint64_t bcast2(float v) {
    uint64_t r; asm("mov.b64 %0, {%1,%1};" : "=l"(r) : "f"(v)); return r;
}
__device__ __forceinline__ uint64_t fma2(uint64_t a, uint64_t b, uint64_t c) {
    uint64_t d; asm("fma.rn.f32x2 %0, %1, %2, %3;" : "=l"(d) : "l"(a), "l"(b), "l"(c)); return d;
}
__device__ __forceinline__ float2 unpack2(uint64_t v) {
    float2 f; asm("mov.b64 {%0,%1}, %2;" : "=f"(f.x), "=f"(f.y) : "l"(v)); return f;
}

// ---------------- scratch ----------------
__device__ float g_out [16777216];  // ping
__device__ float g_up  [16777216];  // pong
__device__ float g_q   [2097152];
__device__ float g_q2  [2097152];   // localUp2 q (computed early, must survive)
__device__ float g_k   [2097152];
__device__ float g_klo [524288];
__device__ float g_att [294912];
__device__ float g_part[8388608];   // K-split partials (conv5 KS=32 needs 8.4M)

// ---------------- conv5: 3x3, 2048->512 @ 16x16, K-split (KS=32, 64 IC each) ----
__global__ void __launch_bounds__(256, 2)
conv5_partial(const float* __restrict__ in, const float* __restrict__ w,
              float* __restrict__ part)
{
    const int ks = blockIdx.x, ocb = blockIdx.y, n = blockIdx.z;
    __shared__ float s_in[8 * 342];        // 8 ic x (18 rows, stride 19)
    __shared__ float s_w [8 * 9 * 64];     // [ic][tap][oc]
    const int tid = threadIdx.x;
    const int og  = tid >> 5;
    const int pg  = tid & 31;
    const int py  = pg >> 1;
    const int px0 = (pg & 1) << 3;

    uint64_t acc2[4][8];
#pragma unroll
    for (int i = 0; i < 4; i++)
#pragma unroll
        for (int j = 0; j < 8; j++) acc2[i][j] = 0ull;

    const int icbase = ks * 64;
    for (int tile = 0; tile < 8; ++tile) {
        const int ict0 = icbase + tile * 8;
        __syncthreads();
        for (int i = tid; i < 8 * 324; i += 256) {
            const int ic = i / 324, rem = i - ic * 324;
            const int ry = rem / 18, rx = rem - ry * 18;
            const int yy = ry - 1, xx = rx - 1;
            float v = 0.f;
            if ((unsigned)yy < 16u && (unsigned)xx < 16u)
                v = in[(((size_t)n * 2048 + ict0 + ic) * 16 + yy) * 16 + xx];
            s_in[ic * 342 + ry * 19 + rx] = v;
        }
        for (int i = tid; i < 8 * 576; i += 256) {
            const int oc = i / 72, r = i - oc * 72;
            const int ic = r / 9, t = r - ic * 9;
            s_w[(ic * 9 + t) * 64 + oc] =
                w[(size_t)(ocb * 64 + oc) * 18432 + (size_t)(ict0 + ic) * 9 + t];
        }
        __syncthreads();
        for (int ic = 0; ic < 8; ++ic) {
            const float* si  = s_in + ic * 342;
            const float* swp = s_w  + ic * 576;
#pragma unroll
            for (int t = 0; t < 9; ++t) {
                const int r = t / 3, s = t - 3 * r;
                const uint64_t* wrow = (const uint64_t*)(swp + t * 64 + og * 8);
                uint64_t wv2[4];
#pragma unroll
                for (int i = 0; i < 4; i++) wv2[i] = wrow[i];
                const float* ib = si + (py + r) * 19 + px0 + s;
#pragma unroll
                for (int j = 0; j < 8; j++) {
                    const uint64_t iv2 = bcast2(ib[j]);
#pragma unroll
                    for (int i = 0; i < 4; i++) acc2[i][j] = fma2(wv2[i], iv2, acc2[i][j]);
                }
            }
        }
    }
    float* dst = part + (size_t)(ks * 2 + n) * 512 * 256;
    const int px = py * 16 + px0;
#pragma unroll
    for (int i = 0; i < 4; i++) {
        const int oc = ocb * 64 + og * 8 + 2 * i;
#pragma unroll
        for (int j = 0; j < 8; j++) {
            const float2 v = unpack2(acc2[i][j]);
            dst[oc * 256 + px + j]       = v.x;
            dst[(oc + 1) * 256 + px + j] = v.y;
        }
    }
}

// ---------------- generic 1x1 conv (GEMM) K-split partial, double-buffered ----
__global__ void __launch_bounds__(256)
conv1x1_partial(const float* __restrict__ in, const float* __restrict__ w,
                float* __restrict__ part,
                int Cin, int Cout, int P, int KS, int KCH)
{
    const int pxb = blockIdx.x;
    const int ocb = blockIdx.y / KS;
    const int ks  = blockIdx.y % KS;
    const int n   = blockIdx.z;
    const int k0  = ks * KCH;
    __shared__ float sA[16][68];
    __shared__ float sB[16][136];
    const int tid = threadIdx.x;
    const int ocg = tid >> 4;
    const int pxg = tid & 15;

    uint64_t acc2[4][4];
#pragma unroll
    for (int i = 0; i < 4; i++)
#pragma unroll
        for (int j = 0; j < 4; j++) acc2[i][j] = 0ull;

    const float* wrow = w + (size_t)(ocb * 64) * Cin + k0;
    const float* brow = in + ((size_t)n * Cin + k0) * P + pxb * 128;

    float  a_reg[4];
    float4 b_reg[2];
    // prefetch chunk 0
#pragma unroll
    for (int i = 0; i < 4; i++) {
        const int idx = (i << 8) + tid;
        a_reg[i] = wrow[(size_t)(idx >> 4) * Cin + (idx & 15)];
    }
#pragma unroll
    for (int i = 0; i < 2; i++) {
        const int idx = (i << 8) + tid;
        b_reg[i] = *(const float4*)&brow[(size_t)(idx >> 5) * P + ((idx & 31) << 2)];
    }

    for (int kc = 0; kc < KCH; kc += 16) {
        __syncthreads();
#pragma unroll
        for (int i = 0; i < 4; i++) {
            const int idx = (i << 8) + tid;
            sA[idx & 15][idx >> 4] = a_reg[i];
        }
#pragma unroll
        for (int i = 0; i < 2; i++) {
            const int idx = (i << 8) + tid;
            *(float4*)&sB[idx >> 5][(idx & 31) << 2] = b_reg[i];
        }
        __syncthreads();
        const int kn = kc + 16;
        if (kn < KCH) {
#pragma unroll
            for (int i = 0; i < 4; i++) {
                const int idx = (i << 8) + tid;
                a_reg[i] = wrow[(size_t)(idx >> 4) * Cin + kn + (idx & 15)];
            }
#pragma unroll
            for (int i = 0; i < 2; i++) {
                const int idx = (i << 8) + tid;
                b_reg[i] = *(const float4*)&brow[(size_t)(kn + (idx >> 5)) * P + ((idx & 31) << 2)];
            }
        }
#pragma unroll
        for (int kk = 0; kk < 16; ++kk) {
            const float4 a4 = *(const float4*)&sA[kk][ocg << 2];
            const float4 b40 = *(const float4*)&sB[kk][pxg << 3];
            const float4 b41 = *(const float4*)&sB[kk][(pxg << 3) + 4];
            const uint64_t* b2 = (const uint64_t*)&b40;
            const uint64_t* b3 = (const uint64_t*)&b41;
            const uint64_t a0 = bcast2(a4.x), a1 = bcast2(a4.y);
            const uint64_t a2 = bcast2(a4.z), a3 = bcast2(a4.w);
            acc2[0][0] = fma2(a0, b2[0], acc2[0][0]);
            acc2[0][1] = fma2(a0, b2[1], acc2[0][1]);
            acc2[0][2] = fma2(a0, b3[0], acc2[0][2]);
            acc2[0][3] = fma2(a0, b3[1], acc2[0][3]);
            acc2[1][0] = fma2(a1, b2[0], acc2[1][0]);
            acc2[1][1] = fma2(a1, b2[1], acc2[1][1]);
            acc2[1][2] = fma2(a1, b3[0], acc2[1][2]);
            acc2[1][3] = fma2(a1, b3[1], acc2[1][3]);
            acc2[2][0] = fma2(a2, b2[0], acc2[2][0]);
            acc2[2][1] = fma2(a2, b2[1], acc2[2][1]);
            acc2[2][2] = fma2(a2, b3[0], acc2[2][2]);
            acc2[2][3] = fma2(a2, b3[1], acc2[2][3]);
            acc2[3][0] = fma2(a3, b2[0], acc2[3][0]);
            acc2[3][1] = fma2(a3, b2[1], acc2[3][1]);
            acc2[3][2] = fma2(a3, b3[0], acc2[3][2]);
            acc2[3][3] = fma2(a3, b3[1], acc2[3][3]);
        }
    }
    float* dst = part + (size_t)(ks * 2 + n) * Cout * P;
    const int ocx = ocb * 64 + (ocg << 2);
    const int px  = pxb * 128 + (pxg << 3);
#pragma unroll
    for (int i = 0; i < 4; i++) {
        const float2 v0 = unpack2(acc2[i][0]), v1 = unpack2(acc2[i][1]);
        const float2 v2 = unpack2(acc2[i][2]), v3 = unpack2(acc2[i][3]);
        *(float4*)&dst[(size_t)(ocx + i) * P + px]     = make_float4(v0.x, v0.y, v1.x, v1.y);
        *(float4*)&dst[(size_t)(ocx + i) * P + px + 4] = make_float4(v2.x, v2.y, v3.x, v3.y);
    }
}

// ---------------- 1x1 conv + fused BN, double-buffered ----------------
__global__ void __launch_bounds__(256)
conv1x1_bn(const float* __restrict__ in, const float* __restrict__ w,
           const float* __restrict__ bn, float* __restrict__ outp,
           int Cin, int Cout, int P)
{
    const int pxb = blockIdx.x;
    const int ocb = blockIdx.y;
    const int n   = blockIdx.z;
    __shared__ float sA[16][68];
    __shared__ float sB[16][136];
    const int tid = threadIdx.x;
    const int ocg = tid >> 4;
    const int pxg = tid & 15;

    uint64_t acc2[4][4];
#pragma unroll
    for (int i = 0; i < 4; i++)
#pragma unroll
        for (int j = 0; j < 4; j++) acc2[i][j] = 0ull;

    const float* wrow = w + (size_t)(ocb * 64) * Cin;
    const float* brow = in + ((size_t)n * Cin) * P + pxb * 128;

    float  a_reg[4];
    float4 b_reg[2];
#pragma unroll
    for (int i = 0; i < 4; i++) {
        const int idx = (i << 8) + tid;
        a_reg[i] = wrow[(size_t)(idx >> 4) * Cin + (idx & 15)];
    }
#pragma unroll
    for (int i = 0; i < 2; i++) {
        const int idx = (i << 8) + tid;
        b_reg[i] = *(const float4*)&brow[(size_t)(idx >> 5) * P + ((idx & 31) << 2)];
    }

    for (int kc = 0; kc < Cin; kc += 16) {
        __syncthreads();
#pragma unroll
        for (int i = 0; i < 4; i++) {
            const int idx = (i << 8) + tid;
            sA[idx & 15][idx >> 4] = a_reg[i];
        }
#pragma unroll
        for (int i = 0; i < 2; i++) {
            const int idx = (i << 8) + tid;
            *(float4*)&sB[idx >> 5][(idx & 31) << 2] = b_reg[i];
        }
        __syncthreads();
        const int kn = kc + 16;
        if (kn < Cin) {
#pragma unroll
            for (int i = 0; i < 4; i++) {
                const int idx = (i << 8) + tid;
                a_reg[i] = wrow[(size_t)(idx >> 4) * Cin + kn + (idx & 15)];
            }
#pragma unroll
            for (int i = 0; i < 2; i++) {
                const int idx = (i << 8) + tid;
                b_reg[i] = *(const float4*)&brow[(size_t)(kn + (idx >> 5)) * P + ((idx & 31) << 2)];
            }
        }
#pragma unroll
        for (int kk = 0; kk < 16; ++kk) {
            const float4 a4 = *(const float4*)&sA[kk][ocg << 2];
            const uint64_t* bp = (const uint64_t*)&sB[kk][pxg << 3];
            uint64_t b2[4] = { bp[0], bp[1], bp[2], bp[3] };
            const uint64_t a0 = bcast2(a4.x), a1 = bcast2(a4.y);
            const uint64_t a2 = bcast2(a4.z), a3 = bcast2(a4.w);
#pragma unroll
            for (int j = 0; j < 4; j++) {
                acc2[0][j] = fma2(a0, b2[j], acc2[0][j]);
                acc2[1][j] = fma2(a1, b2[j], acc2[1][j]);
                acc2[2][j] = fma2(a2, b2[j], acc2[2][j]);
                acc2[3][j] = fma2(a3, b2[j], acc2[3][j]);
            }
        }
    }
    const int ocx = ocb * 64 + (ocg << 2);
    const int px  = pxb * 128 + (pxg << 3);
#pragma unroll
    for (int i = 0; i < 4; i++) {
        const int oc = ocx + i;
        const float g = bn[oc], b = bn[Cout + oc], m = bn[2 * Cout + oc], v = bn[3 * Cout + oc];
        const float sc = g / sqrtf(v + BN_EPS);
        const float sh = b - m * sc;
        const float2 v0 = unpack2(acc2[i][0]), v1 = unpack2(acc2[i][1]);
        const float2 v2 = unpack2(acc2[i][2]), v3 = unpack2(acc2[i][3]);
        float* op = outp + ((size_t)n * Cout + oc) * P + px;
        *(float4*)op       = make_float4(v0.x * sc + sh, v0.y * sc + sh, v1.x * sc + sh, v1.y * sc + sh);
        *(float4*)(op + 4) = make_float4(v2.x * sc + sh, v2.y * sc + sh, v3.x * sc + sh, v3.y * sc + sh);
    }
}

// ---------------- reduce K-splits + BN (+ReLU), float4 ----------------
__global__ void __launch_bounds__(256)
reduce_bn4(const float4* __restrict__ part, const float* __restrict__ bn,
           float4* __restrict__ out, int C, int P, int KS, int relu)
{
    const int idx = blockIdx.x * 256 + threadIdx.x;
    const int total4 = 2 * C * P / 4;
    if (idx >= total4) return;
    const int c = ((idx * 4) / P) % C;
    const size_t stride4 = (size_t)2 * C * P / 4;
    float4 s = make_float4(0.f, 0.f, 0.f, 0.f);
    for (int k = 0; k < KS; ++k) {
        const float4 q = part[(size_t)k * stride4 + idx];
        s.x += q.x; s.y += q.y; s.z += q.z; s.w += q.w;
    }
    const float g = bn[c], b = bn[C + c], m = bn[2 * C + c], v = bn[3 * C + c];
    const float sc = g / sqrtf(v + BN_EPS);
    const float sh = b - m * sc;
    float4 r = make_float4(s.x * sc + sh, s.y * sc + sh, s.z * sc + sh, s.w * sc + sh);
    if (relu) {
        r.x = fmaxf(r.x, 0.f); r.y = fmaxf(r.y, 0.f);
        r.z = fmaxf(r.z, 0.f); r.w = fmaxf(r.w, 0.f);
    }
    out[idx] = r;
}

// ---------------- bilinear upsample (k path only) ----------------
__global__ void __launch_bounds__(256)
upsample_ac(const float* __restrict__ in, float* __restrict__ out,
            int NC, int h, int w, int H, int W, float sy, float sx)
{
    const int idx = blockIdx.x * 256 + threadIdx.x;
    const int total = NC * H * W;
    if (idx >= total) return;
    const int x  = idx % W;
    const int y  = (idx / W) % H;
    const int nc = idx / (W * H);
    const float fy = y * sy;
    const float fx = x * sx;
    int y0 = (int)fy; if (y0 > h - 1) y0 = h - 1;
    int x0 = (int)fx; if (x0 > w - 1) x0 = w - 1;
    const int y1 = min(y0 + 1, h - 1);
    const int x1 = min(x0 + 1, w - 1);
    const float wy = fy - y0, wx = fx - x0;
    const float* p = in + (size_t)nc * h * w;
    const float v00 = p[y0 * w + x0], v01 = p[y0 * w + x1];
    const float v10 = p[y1 * w + x0], v11 = p[y1 * w + x1];
    const float a = v00 * (1.f - wy) + v10 * wy;
    const float b = v01 * (1.f - wy) + v11 * wy;
    out[idx] = a * (1.f - wx) + b * wx;
}

// ---------------- attention v2: kd-split across block for SM parallelism ------
__global__ void __launch_bounds__(256)
attention_v2(const float* __restrict__ q, const float* __restrict__ kmap,
             float* __restrict__ att, int kd, int H, int W)
{
    __shared__ float s_part[32][8][36];
    __shared__ float s_red[8][36];
    const int tid  = threadIdx.x;
    const int qloc = tid & 7;
    const int si   = tid >> 3;
    const int Wq   = W >> 2;
    const int qg   = blockIdx.x * 8 + qloc;
    const int xq   = qg % Wq;
    const int y    = (qg / Wq) % H;
    const int n    = qg / (Wq * H);
    const int x0   = xq << 2;
    const size_t plane = (size_t)H * W;

    const bool lok = (x0 >= 4);
    const bool rok = (x0 + 4 < W);
    int rowoff[3]; bool rowok[3];
#pragma unroll
    for (int r = 0; r < 3; r++) {
        const int yy = y + (r - 1) * 2;
        rowok[r]  = ((unsigned)yy < (unsigned)H);
        rowoff[r] = yy * W + x0;
    }

    uint64_t lg[9][2];
#pragma unroll
    for (int t = 0; t < 9; t++) { lg[t][0] = 0ull; lg[t][1] = 0ull; }

    const int cpt = kd >> 5;
    const int c0  = si * cpt;
    const float* qp = q + ((size_t)n * kd + c0) * plane + (size_t)y * W + x0;
    const float* kp = kmap + ((size_t)n * kd + c0) * plane;
    const float4 z4 = make_float4(0.f, 0.f, 0.f, 0.f);

    for (int c = 0; c < cpt; ++c) {
        const float4 qv = *(const float4*)(qp + (size_t)c * plane);
        const uint64_t* qh = (const uint64_t*)&qv;
        const uint64_t q01 = qh[0], q23 = qh[1];
        const float* kc = kp + (size_t)c * plane;
#pragma unroll
        for (int r = 0; r < 3; r++) {
            if (!rowok[r]) continue;
            const float* kr = kc + rowoff[r];
            const float4 L = lok ? *(const float4*)(kr - 4) : z4;
            const float4 M = *(const float4*)kr;
            const float4 R = rok ? *(const float4*)(kr + 4) : z4;
            const uint64_t* Lh = (const uint64_t*)&L;
            const uint64_t* Mh = (const uint64_t*)&M;
            const uint64_t* Rh = (const uint64_t*)&R;
            const int t0 = r * 3;
            lg[t0 + 0][0] = fma2(q01, Lh[1], lg[t0 + 0][0]);
            lg[t0 + 0][1] = fma2(q23, Mh[0], lg[t0 + 0][1]);
            lg[t0 + 1][0] = fma2(q01, Mh[0], lg[t0 + 1][0]);
            lg[t0 + 1][1] = fma2(q23, Mh[1], lg[t0 + 1][1]);
            lg[t0 + 2][0] = fma2(q01, Mh[1], lg[t0 + 2][0]);
            lg[t0 + 2][1] = fma2(q23, Rh[0], lg[t0 + 2][1]);
        }
    }
#pragma unroll
    for (int t = 0; t < 9; t++) {
        const float2 a = unpack2(lg[t][0]);
        const float2 b = unpack2(lg[t][1]);
        s_part[si][qloc][t * 4 + 0] = a.x;
        s_part[si][qloc][t * 4 + 1] = a.y;
        s_part[si][qloc][t * 4 + 2] = b.x;
        s_part[si][qloc][t * 4 + 3] = b.y;
    }
    __syncthreads();

    for (int i = tid; i < 8 * 36; i += 256) {
        const int qq = i / 36, j = i - qq * 36;
        float s = 0.f;
#pragma unroll
        for (int s2 = 0; s2 < 32; s2++) s += s_part[s2][qq][j];
        s_red[qq][j] = s;
    }
    __syncthreads();

    if (tid < 32) {
        const int qq = tid >> 2, p = tid & 3;
        float l[9];
#pragma unroll
        for (int t = 0; t < 9; t++) l[t] = s_red[qq][t * 4 + p];
        float mx = l[0];
#pragma unroll
        for (int t = 1; t < 9; t++) mx = fmaxf(mx, l[t]);
        float s = 0.f;
#pragma unroll
        for (int t = 0; t < 9; t++) { l[t] = expf(l[t] - mx); s += l[t]; }
        const float inv = 1.f / s;
        const int qg2 = blockIdx.x * 8 + qq;
        const int xq2 = qg2 % Wq;
        const int y2  = (qg2 / Wq) % H;
        const int n2  = qg2 / (Wq * H);
        float* ap = att + (size_t)n2 * 9 * plane + (size_t)y2 * W + (xq2 << 2) + p;
#pragma unroll
        for (int t = 0; t < 9; t++) ap[(size_t)t * plane] = l[t] * inv;
    }
}

// ---------------- fused upsample + attention apply ----------------
template<int H, int W, int h, int w>
__global__ void __launch_bounds__(256)
apply_fused(const float* __restrict__ att, const float* __restrict__ lo,
            float* __restrict__ outp)
{
    constexpr int WPAD = W + 8;
    __shared__ __align__(16) float s_lo[8][6][w + 2];
    __shared__ __align__(16) float s_up[8][8][WPAD];
    const int y0  = blockIdx.x * 4;
    const int ch0 = blockIdx.y * 8;
    const int n   = blockIdx.z;
    const int tid = threadIdx.x;
    const int nth = blockDim.x;
    constexpr float sy = (float)(h - 1) / (float)(H - 1);
    constexpr float sx = (float)(w - 1) / (float)(W - 1);
    const size_t planeL = (size_t)h * w;
    const size_t planeH = (size_t)H * W;

    const int ylo = (y0 >= 2 ? y0 - 2 : 0);
    const int base = (int)((float)ylo * sy);
    for (int i = tid; i < 8 * 6 * w; i += nth) {
        const int ch = i / (6 * w);
        const int r  = (i / w) % 6;
        const int x  = i % w;
        const int gr = min(base + r, h - 1);
        s_lo[ch][r][x] = lo[((size_t)(n * 512 + ch0 + ch)) * planeL + (size_t)gr * w + x];
    }
    __syncthreads();

    for (int i = tid; i < 8 * 8 * WPAD; i += nth) {
        const int ch  = i / (8 * WPAD);
        const int rem = i - ch * (8 * WPAD);
        const int row = rem / WPAD;
        const int col = rem - row * WPAD;
        const int Y = y0 - 2 + row;
        const int X = col - 4;
        float v = 0.f;
        if ((unsigned)Y < (unsigned)H && (unsigned)X < (unsigned)W) {
            const float fy = Y * sy;
            int iy0 = (int)fy; if (iy0 > h - 1) iy0 = h - 1;
            const int ry0 = iy0 - base;
            const int ry1 = min(iy0 + 1, h - 1) - base;
            const float wy = fy - iy0;
            const float fx = X * sx;
            int ix0 = (int)fx; if (ix0 > w - 1) ix0 = w - 1;
            const int ix1 = min(ix0 + 1, w - 1);
            const float wx = fx - ix0;
            const float a = s_lo[ch][ry0][ix0] * (1.f - wx) + s_lo[ch][ry0][ix1] * wx;
            const float b = s_lo[ch][ry1][ix0] * (1.f - wx) + s_lo[ch][ry1][ix1] * wx;
            v = a * (1.f - wy) + b * wy;
        }
        s_up[ch][row][col] = v;
    }
    __syncthreads();

    const int Wp = W >> 1;
    const int xp = tid % Wp;
    const int yy = tid / Wp;
    const int y  = y0 + yy;
    const int x0 = xp << 1;

    uint64_t att2[9];
    const float* ap = att + (size_t)n * 9 * planeH + (size_t)y * W + x0;
#pragma unroll
    for (int t = 0; t < 9; t++) att2[t] = *(const uint64_t*)(ap + (size_t)t * planeH);

#pragma unroll
    for (int c = 0; c < 8; ++c) {
        uint64_t acc = 0ull;
#pragma unroll
        for (int iy = 0; iy < 3; iy++) {
            const float* rp = &s_up[c][yy + 2 * iy][0];
#pragma unroll
            for (int ix = 0; ix < 3; ix++) {
                const uint64_t u2 = *(const uint64_t*)(rp + x0 + 2 * ix + 2);
                acc = fma2(att2[iy * 3 + ix], u2, acc);
            }
        }
        const float2 v = unpack2(acc);
        *(float2*)&outp[((size_t)(n * 512 + ch0 + c)) * planeH + (size_t)y * W + x0] = v;
    }
}

// ---------------- conv6: 1x1, 512->19, C-split partial, f32x2 ----------------
__global__ void __launch_bounds__(128)
conv6_partial(const float* __restrict__ in, const float* __restrict__ w,
              float* __restrict__ part)
{
    __shared__ float sw[19 * 128];
    const int tid = threadIdx.x;
    const int cs  = blockIdx.y;
    const int n   = blockIdx.z;
    const int c0  = cs * 128;
    for (int i = tid; i < 19 * 128; i += 128) {
        const int o = i >> 7, c = i & 127;
        sw[i] = w[o * 512 + c0 + c];
    }
    __syncthreads();
    const int px = (blockIdx.x * 128 + tid) * 2;
    uint64_t acc2[19];
#pragma unroll
    for (int o = 0; o < 19; o++) acc2[o] = 0ull;
    const float* ip = in + ((size_t)n * 512 + c0) * 16384 + px;
    for (int c = 0; c < 128; ++c) {
        const uint64_t v2 = *(const uint64_t*)(ip + (size_t)c * 16384);
#pragma unroll
        for (int o = 0; o < 19; o++)
            acc2[o] = fma2(bcast2(sw[(o << 7) + c]), v2, acc2[o]);
    }
    float* op = part + ((size_t)(cs * 2 + n) * 19) * 16384 + px;
#pragma unroll
    for (int o = 0; o < 19; o++) {
        const float2 v = unpack2(acc2[o]);
        *(float2*)(op + (size_t)o * 16384) = v;
    }
}

// ---------------- conv6 reduce + bias, float4 ----------------
__global__ void __launch_bounds__(256)
conv6_reduce(const float4* __restrict__ part, const float* __restrict__ bias,
             float4* __restrict__ out)
{
    const int idx = blockIdx.x * 256 + threadIdx.x;
    const int perN = 19 * 16384 / 4;
    const int total = 2 * perN;
    if (idx >= total) return;
    const int n   = idx / perN;
    const int rem = idx - n * perN;
    const int o   = (rem * 4) / 16384;
    float4 s = make_float4(0.f, 0.f, 0.f, 0.f);
#pragma unroll
    for (int cs = 0; cs < 4; ++cs) {
        const float4 q = part[(size_t)(cs * 2 + n) * perN + rem];
        s.x += q.x; s.y += q.y; s.z += q.z; s.w += q.w;
    }
    const float b = bias[o];
    out[idx] = make_float4(s.x + b, s.y + b, s.z + b, s.w + b);
}

// ---------------- launch ----------------
extern "C" void kernel_launch(void* const* d_in, const int* in_sizes, int n_in,
                              void* d_out, int out_size)
{
    (void)in_sizes; (void)n_in; (void)out_size;
    const float* c1      = (const float*)d_in[0];
    const float* c2      = (const float*)d_in[1];
    const float* c3      = (const float*)d_in[2];
    const float* c4      = (const float*)d_in[3];
    const float* c30     = (const float*)d_in[5];
    const float* c40     = (const float*)d_in[6];
    const float* conv5_w = (const float*)d_in[7];
    const float* bn5     = (const float*)d_in[8];
    const float* conv6_w = (const float*)d_in[9];
    const float* conv6_b = (const float*)d_in[10];
    const float* lu4_w1  = (const float*)d_in[11];
    const float* lu4_bn1 = (const float*)d_in[12];
    const float* lu4_w2  = (const float*)d_in[13];
    const float* lu4_bn2 = (const float*)d_in[14];
    const float* lu3_w1  = (const float*)d_in[15];
    const float* lu3_bn1 = (const float*)d_in[16];
    const float* lu3_w2  = (const float*)d_in[17];
    const float* lu3_bn2 = (const float*)d_in[18];
    const float* lu2_w1  = (const float*)d_in[19];
    const float* lu2_bn1 = (const float*)d_in[20];
    const float* lu2_w2  = (const float*)d_in[21];
    const float* lu2_bn2 = (const float*)d_in[22];
    float* out = (float*)d_out;

    float *p_out, *p_up, *p_q, *p_q2, *p_k, *p_klo, *p_att, *p_part;
    cudaGetSymbolAddress((void**)&p_out,  g_out);
    cudaGetSymbolAddress((void**)&p_up,   g_up);
    cudaGetSymbolAddress((void**)&p_q,    g_q);
    cudaGetSymbolAddress((void**)&p_q2,   g_q2);
    cudaGetSymbolAddress((void**)&p_k,    g_k);
    cudaGetSymbolAddress((void**)&p_klo,  g_klo);
    cudaGetSymbolAddress((void**)&p_att,  g_att);
    cudaGetSymbolAddress((void**)&p_part, g_part);

    // ---- conv5 + BN + ReLU -> g_out (2,512,16,16); KS=32 ----
    conv5_partial<<<dim3(32, 8, 2), 256>>>(c4, conv5_w, p_part);
    reduce_bn4<<<(2 * 512 * 256 / 4 + 255) / 256, 256>>>((const float4*)p_part, bn5, (float4*)p_out, 512, 256, 32, 1);

    // ---- localUp2 q projection early (independent; dedicated buffer) ----
    conv1x1_bn<<<dim3(128, 1, 2), 256>>>(c1, lu2_w1, lu2_bn1, p_q2, 256, 64, 16384);

    // ---- localUp4: H=32, kd=128; lo=g_out -> g_up ----  (KS=16: 512 blocks)
    conv1x1_partial<<<dim3(8, 2 * 16, 2), 256>>>(c3, lu4_w1, p_part, 1024, 128, 1024, 16, 64);  // #4 (profiled)
    reduce_bn4<<<(2 * 128 * 1024 / 4 + 255) / 256, 256>>>((const float4*)p_part, lu4_bn1, (float4*)p_q, 128, 1024, 16, 0);
    conv1x1_partial<<<dim3(2, 2 * 64, 2), 256>>>(c40, lu4_w2, p_part, 2048, 128, 256, 64, 32);
    reduce_bn4<<<(2 * 128 * 256 / 4 + 255) / 256, 256>>>((const float4*)p_part, lu4_bn2, (float4*)p_klo, 128, 256, 64, 0);
    upsample_ac<<<(2 * 128 * 32 * 32 + 255) / 256, 256>>>(p_klo, p_k, 2 * 128, 16, 16, 32, 32, 15.f / 31.f, 15.f / 31.f);
    attention_v2<<<2 * 32 * 8 / 8, 256>>>(p_q, p_k, p_att, 128, 32, 32);
    apply_fused<32, 32, 16, 16><<<dim3(8, 64, 2), 64>>>(p_att, p_out, p_up);

    // ---- localUp3: H=64, kd=64; lo=g_up -> g_out ----  (KS=8: 512 blocks)
    conv1x1_partial<<<dim3(32, 1 * 8, 2), 256>>>(c2, lu3_w1, p_part, 512, 64, 4096, 8, 64);
    reduce_bn4<<<(2 * 64 * 4096 / 4 + 255) / 256, 256>>>((const float4*)p_part, lu3_bn1, (float4*)p_q, 64, 4096, 8, 0);
    conv1x1_partial<<<dim3(8, 1 * 32, 2), 256>>>(c30, lu3_w2, p_part, 1024, 64, 1024, 32, 32);
    reduce_bn4<<<(2 * 64 * 1024 / 4 + 255) / 256, 256>>>((const float4*)p_part, lu3_bn2, (float4*)p_klo, 64, 1024, 32, 0);
    upsample_ac<<<(2 * 64 * 64 * 64 + 255) / 256, 256>>>(p_klo, p_k, 2 * 64, 32, 32, 64, 64, 31.f / 63.f, 31.f / 63.f);
    attention_v2<<<2 * 64 * 16 / 8, 256>>>(p_q, p_k, p_att, 64, 64, 64);
    apply_fused<64, 64, 32, 32><<<dim3(16, 64, 2), 128>>>(p_att, p_up, p_out);

    // ---- localUp2: H=128, kd=64; lo=g_out -> g_up ----  (q already in g_q2; KS=8)
    conv1x1_partial<<<dim3(32, 1 * 8, 2), 256>>>(c2, lu2_w2, p_part, 512, 64, 4096, 8, 64);
    reduce_bn4<<<(2 * 64 * 4096 / 4 + 255) / 256, 256>>>((const float4*)p_part, lu2_bn2, (float4*)p_klo, 64, 4096, 8, 0);
    upsample_ac<<<(2 * 64 * 128 * 128 + 255) / 256, 256>>>(p_klo, p_k, 2 * 64, 64, 64, 128, 128, 63.f / 127.f, 63.f / 127.f);
    attention_v2<<<2 * 128 * 32 / 8, 256>>>(p_q2, p_k, p_att, 64, 128, 128);
    apply_fused<128, 128, 64, 64><<<dim3(32, 64, 2), 256>>>(p_att, p_out, p_up);

    // ---- conv6 1x1 -> (2,19,128,128), C-split x4 ----
    conv6_partial<<<dim3(64, 4, 2), 128>>>(p_up, conv6_w, p_part);
    conv6_reduce<<<(2 * 19 * 16384 / 4 + 255) / 256, 256>>>((const float4*)p_part, conv6_b, (float4*)out);
}

// round 12
// speedup vs baseline: 1.3369x; 1.0257x over previous
#include <cuda_runtime.h>
#include <math.h>
#include <stdint.h>

#define BN_EPS 1e-5f

// ---------------- f32x2 helpers ----------------
__device__ __forceinline__ uint64_t bcast2(float v) {
    uint64_t r; asm("mov.b64 %0, {%1,%1};" : "=l"(r) : "f"(v)); return r;
}
__device__ __forceinline__ uint64_t fma2(uint64_t a, uint64_t b, uint64_t c) {
    uint64_t d; asm("fma.rn.f32x2 %0, %1, %2, %3;" : "=l"(d) : "l"(a), "l"(b), "l"(c)); return d;
}
__device__ __forceinline__ float2 unpack2(uint64_t v) {
    float2 f; asm("mov.b64 {%0,%1}, %2;" : "=f"(f.x), "=f"(f.y) : "l"(v)); return f;
}

// ---------------- scratch ----------------
__device__ float g_out [16777216];  // ping
__device__ float g_up  [16777216];  // pong
__device__ float g_q   [2097152];
__device__ float g_q2  [2097152];   // localUp2 q (computed early, must survive)
__device__ float g_k   [2097152];
__device__ float g_klo [524288];
__device__ float g_att [294912];
__device__ float g_part[8388608];   // K-split partials

// ---------------- conv5: 3x3, 2048->512 @ 16x16, K-split (KS=32) ----------------
// Row-hoisted inner loop: 10 input scalars broadcast once per (ic,row),
// reused across the 3 taps of that row.
__global__ void __launch_bounds__(256, 2)
conv5_partial(const float* __restrict__ in, const float* __restrict__ w,
              float* __restrict__ part)
{
    const int ks = blockIdx.x, ocb = blockIdx.y, n = blockIdx.z;
    __shared__ float s_in[8 * 342];        // 8 ic x (18 rows, stride 19)
    __shared__ float s_w [8 * 9 * 64];     // [ic][tap][oc]
    const int tid = threadIdx.x;
    const int og  = tid >> 5;
    const int pg  = tid & 31;
    const int py  = pg >> 1;
    const int px0 = (pg & 1) << 3;

    uint64_t acc2[4][8];
#pragma unroll
    for (int i = 0; i < 4; i++)
#pragma unroll
        for (int j = 0; j < 8; j++) acc2[i][j] = 0ull;

    const int icbase = ks * 64;
    for (int tile = 0; tile < 8; ++tile) {
        const int ict0 = icbase + tile * 8;
        __syncthreads();
        for (int i = tid; i < 8 * 324; i += 256) {
            const int ic = i / 324, rem = i - ic * 324;
            const int ry = rem / 18, rx = rem - ry * 18;
            const int yy = ry - 1, xx = rx - 1;
            float v = 0.f;
            if ((unsigned)yy < 16u && (unsigned)xx < 16u)
                v = in[(((size_t)n * 2048 + ict0 + ic) * 16 + yy) * 16 + xx];
            s_in[ic * 342 + ry * 19 + rx] = v;
        }
        for (int i = tid; i < 8 * 576; i += 256) {
            const int oc = i / 72, r = i - oc * 72;
            const int ic = r / 9, t = r - ic * 9;
            s_w[(ic * 9 + t) * 64 + oc] =
                w[(size_t)(ocb * 64 + oc) * 18432 + (size_t)(ict0 + ic) * 9 + t];
        }
        __syncthreads();
        for (int ic = 0; ic < 8; ++ic) {
            const float* si  = s_in + ic * 342;
            const float* swp = s_w  + ic * 576;
#pragma unroll
            for (int r = 0; r < 3; ++r) {
                const float* rp = si + (py + r) * 19 + px0;
                uint64_t inb[10];
#pragma unroll
                for (int u = 0; u < 10; ++u) inb[u] = bcast2(rp[u]);
#pragma unroll
                for (int s = 0; s < 3; ++s) {
                    const int t = r * 3 + s;
                    const uint64_t* wrow = (const uint64_t*)(swp + t * 64 + og * 8);
                    uint64_t wv2[4];
#pragma unroll
                    for (int i = 0; i < 4; i++) wv2[i] = wrow[i];
#pragma unroll
                    for (int j = 0; j < 8; j++) {
                        const uint64_t iv2 = inb[s + j];
#pragma unroll
                        for (int i = 0; i < 4; i++) acc2[i][j] = fma2(wv2[i], iv2, acc2[i][j]);
                    }
                }
            }
        }
    }
    float* dst = part + (size_t)(ks * 2 + n) * 512 * 256;
    const int px = py * 16 + px0;
#pragma unroll
    for (int i = 0; i < 4; i++) {
        const int oc = ocb * 64 + og * 8 + 2 * i;
#pragma unroll
        for (int j = 0; j < 8; j++) {
            const float2 v = unpack2(acc2[i][j]);
            dst[oc * 256 + px + j]       = v.x;
            dst[(oc + 1) * 256 + px + j] = v.y;
        }
    }
}

// ---------------- generic 1x1 conv GEMM, smem double-buffer (1 sync/tile) ----
__global__ void __launch_bounds__(256)
conv1x1_partial(const float* __restrict__ in, const float* __restrict__ w,
                float* __restrict__ part,
                int Cin, int Cout, int P, int KS, int KCH)
{
    const int pxb = blockIdx.x;
    const int ocb = blockIdx.y / KS;
    const int ks  = blockIdx.y % KS;
    const int n   = blockIdx.z;
    const int k0  = ks * KCH;
    __shared__ float sA[2][16][68];
    __shared__ float sB[2][16][136];
    const int tid = threadIdx.x;
    const int ocg = tid >> 4;
    const int pxg = tid & 15;

    uint64_t acc2[4][4];
#pragma unroll
    for (int i = 0; i < 4; i++)
#pragma unroll
        for (int j = 0; j < 4; j++) acc2[i][j] = 0ull;

    const float* wrow = w + (size_t)(ocb * 64) * Cin + k0;
    const float* brow = in + ((size_t)n * Cin + k0) * P + pxb * 128;

    float  a_reg[4];
    float4 b_reg[2];
    // tile 0 -> buf 0
#pragma unroll
    for (int i = 0; i < 4; i++) {
        const int idx = (i << 8) + tid;
        sA[0][idx & 15][idx >> 4] = wrow[(size_t)(idx >> 4) * Cin + (idx & 15)];
    }
#pragma unroll
    for (int i = 0; i < 2; i++) {
        const int idx = (i << 8) + tid;
        *(float4*)&sB[0][idx >> 5][(idx & 31) << 2] =
            *(const float4*)&brow[(size_t)(idx >> 5) * P + ((idx & 31) << 2)];
    }
    __syncthreads();

    for (int kc = 0; kc < KCH; kc += 16) {
        const int cur = (kc >> 4) & 1;
        const int kn  = kc + 16;
        const bool more = (kn < KCH);
        if (more) {
#pragma unroll
            for (int i = 0; i < 4; i++) {
                const int idx = (i << 8) + tid;
                a_reg[i] = wrow[(size_t)(idx >> 4) * Cin + kn + (idx & 15)];
            }
#pragma unroll
            for (int i = 0; i < 2; i++) {
                const int idx = (i << 8) + tid;
                b_reg[i] = *(const float4*)&brow[(size_t)(kn + (idx >> 5)) * P + ((idx & 31) << 2)];
            }
        }
#pragma unroll
        for (int kk = 0; kk < 16; ++kk) {
            const float4 a4 = *(const float4*)&sA[cur][kk][ocg << 2];
            const float4 b40 = *(const float4*)&sB[cur][kk][pxg << 3];
            const float4 b41 = *(const float4*)&sB[cur][kk][(pxg << 3) + 4];
            const uint64_t* b2 = (const uint64_t*)&b40;
            const uint64_t* b3 = (const uint64_t*)&b41;
            const uint64_t a0 = bcast2(a4.x), a1 = bcast2(a4.y);
            const uint64_t a2 = bcast2(a4.z), a3 = bcast2(a4.w);
            acc2[0][0] = fma2(a0, b2[0], acc2[0][0]);
            acc2[0][1] = fma2(a0, b2[1], acc2[0][1]);
            acc2[0][2] = fma2(a0, b3[0], acc2[0][2]);
            acc2[0][3] = fma2(a0, b3[1], acc2[0][3]);
            acc2[1][0] = fma2(a1, b2[0], acc2[1][0]);
            acc2[1][1] = fma2(a1, b2[1], acc2[1][1]);
            acc2[1][2] = fma2(a1, b3[0], acc2[1][2]);
            acc2[1][3] = fma2(a1, b3[1], acc2[1][3]);
            acc2[2][0] = fma2(a2, b2[0], acc2[2][0]);
            acc2[2][1] = fma2(a2, b2[1], acc2[2][1]);
            acc2[2][2] = fma2(a2, b3[0], acc2[2][2]);
            acc2[2][3] = fma2(a2, b3[1], acc2[2][3]);
            acc2[3][0] = fma2(a3, b2[0], acc2[3][0]);
            acc2[3][1] = fma2(a3, b2[1], acc2[3][1]);
            acc2[3][2] = fma2(a3, b3[0], acc2[3][2]);
            acc2[3][3] = fma2(a3, b3[1], acc2[3][3]);
        }
        if (more) {
            const int nxt = cur ^ 1;
#pragma unroll
            for (int i = 0; i < 4; i++) {
                const int idx = (i << 8) + tid;
                sA[nxt][idx & 15][idx >> 4] = a_reg[i];
            }
#pragma unroll
            for (int i = 0; i < 2; i++) {
                const int idx = (i << 8) + tid;
                *(float4*)&sB[nxt][idx >> 5][(idx & 31) << 2] = b_reg[i];
            }
        }
        __syncthreads();
    }
    float* dst = part + (size_t)(ks * 2 + n) * Cout * P;
    const int ocx = ocb * 64 + (ocg << 2);
    const int px  = pxb * 128 + (pxg << 3);
#pragma unroll
    for (int i = 0; i < 4; i++) {
        const float2 v0 = unpack2(acc2[i][0]), v1 = unpack2(acc2[i][1]);
        const float2 v2 = unpack2(acc2[i][2]), v3 = unpack2(acc2[i][3]);
        *(float4*)&dst[(size_t)(ocx + i) * P + px]     = make_float4(v0.x, v0.y, v1.x, v1.y);
        *(float4*)&dst[(size_t)(ocx + i) * P + px + 4] = make_float4(v2.x, v2.y, v3.x, v3.y);
    }
}

// ---------------- 1x1 conv + fused BN, smem double-buffer ----------------
__global__ void __launch_bounds__(256)
conv1x1_bn(const float* __restrict__ in, const float* __restrict__ w,
           const float* __restrict__ bn, float* __restrict__ outp,
           int Cin, int Cout, int P)
{
    const int pxb = blockIdx.x;
    const int ocb = blockIdx.y;
    const int n   = blockIdx.z;
    __shared__ float sA[2][16][68];
    __shared__ float sB[2][16][136];
    const int tid = threadIdx.x;
    const int ocg = tid >> 4;
    const int pxg = tid & 15;

    uint64_t acc2[4][4];
#pragma unroll
    for (int i = 0; i < 4; i++)
#pragma unroll
        for (int j = 0; j < 4; j++) acc2[i][j] = 0ull;

    const float* wrow = w + (size_t)(ocb * 64) * Cin;
    const float* brow = in + ((size_t)n * Cin) * P + pxb * 128;

    float  a_reg[4];
    float4 b_reg[2];
#pragma unroll
    for (int i = 0; i < 4; i++) {
        const int idx = (i << 8) + tid;
        sA[0][idx & 15][idx >> 4] = wrow[(size_t)(idx >> 4) * Cin + (idx & 15)];
    }
#pragma unroll
    for (int i = 0; i < 2; i++) {
        const int idx = (i << 8) + tid;
        *(float4*)&sB[0][idx >> 5][(idx & 31) << 2] =
            *(const float4*)&brow[(size_t)(idx >> 5) * P + ((idx & 31) << 2)];
    }
    __syncthreads();

    for (int kc = 0; kc < Cin; kc += 16) {
        const int cur = (kc >> 4) & 1;
        const int kn  = kc + 16;
        const bool more = (kn < Cin);
        if (more) {
#pragma unroll
            for (int i = 0; i < 4; i++) {
                const int idx = (i << 8) + tid;
                a_reg[i] = wrow[(size_t)(idx >> 4) * Cin + kn + (idx & 15)];
            }
#pragma unroll
            for (int i = 0; i < 2; i++) {
                const int idx = (i << 8) + tid;
                b_reg[i] = *(const float4*)&brow[(size_t)(kn + (idx >> 5)) * P + ((idx & 31) << 2)];
            }
        }
#pragma unroll
        for (int kk = 0; kk < 16; ++kk) {
            const float4 a4 = *(const float4*)&sA[cur][kk][ocg << 2];
            const uint64_t* bp = (const uint64_t*)&sB[cur][kk][pxg << 3];
            uint64_t b2[4] = { bp[0], bp[1], bp[2], bp[3] };
            const uint64_t a0 = bcast2(a4.x), a1 = bcast2(a4.y);
            const uint64_t a2 = bcast2(a4.z), a3 = bcast2(a4.w);
#pragma unroll
            for (int j = 0; j < 4; j++) {
                acc2[0][j] = fma2(a0, b2[j], acc2[0][j]);
                acc2[1][j] = fma2(a1, b2[j], acc2[1][j]);
                acc2[2][j] = fma2(a2, b2[j], acc2[2][j]);
                acc2[3][j] = fma2(a3, b2[j], acc2[3][j]);
            }
        }
        if (more) {
            const int nxt = cur ^ 1;
#pragma unroll
            for (int i = 0; i < 4; i++) {
                const int idx = (i << 8) + tid;
                sA[nxt][idx & 15][idx >> 4] = a_reg[i];
            }
#pragma unroll
            for (int i = 0; i < 2; i++) {
                const int idx = (i << 8) + tid;
                *(float4*)&sB[nxt][idx >> 5][(idx & 31) << 2] = b_reg[i];
            }
        }
        __syncthreads();
    }
    const int ocx = ocb * 64 + (ocg << 2);
    const int px  = pxb * 128 + (pxg << 3);
#pragma unroll
    for (int i = 0; i < 4; i++) {
        const int oc = ocx + i;
        const float g = bn[oc], b = bn[Cout + oc], m = bn[2 * Cout + oc], v = bn[3 * Cout + oc];
        const float sc = g / sqrtf(v + BN_EPS);
        const float sh = b - m * sc;
        const float2 v0 = unpack2(acc2[i][0]), v1 = unpack2(acc2[i][1]);
        const float2 v2 = unpack2(acc2[i][2]), v3 = unpack2(acc2[i][3]);
        float* op = outp + ((size_t)n * Cout + oc) * P + px;
        *(float4*)op       = make_float4(v0.x * sc + sh, v0.y * sc + sh, v1.x * sc + sh, v1.y * sc + sh);
        *(float4*)(op + 4) = make_float4(v2.x * sc + sh, v2.y * sc + sh, v3.x * sc + sh, v3.y * sc + sh);
    }
}

// ---------------- reduce K-splits + BN (+ReLU), float4 ----------------
__global__ void __launch_bounds__(256)
reduce_bn4(const float4* __restrict__ part, const float* __restrict__ bn,
           float4* __restrict__ out, int C, int P, int KS, int relu)
{
    const int idx = blockIdx.x * 256 + threadIdx.x;
    const int total4 = 2 * C * P / 4;
    if (idx >= total4) return;
    const int c = ((idx * 4) / P) % C;
    const size_t stride4 = (size_t)2 * C * P / 4;
    float4 s = make_float4(0.f, 0.f, 0.f, 0.f);
    for (int k = 0; k < KS; ++k) {
        const float4 q = part[(size_t)k * stride4 + idx];
        s.x += q.x; s.y += q.y; s.z += q.z; s.w += q.w;
    }
    const float g = bn[c], b = bn[C + c], m = bn[2 * C + c], v = bn[3 * C + c];
    const float sc = g / sqrtf(v + BN_EPS);
    const float sh = b - m * sc;
    float4 r = make_float4(s.x * sc + sh, s.y * sc + sh, s.z * sc + sh, s.w * sc + sh);
    if (relu) {
        r.x = fmaxf(r.x, 0.f); r.y = fmaxf(r.y, 0.f);
        r.z = fmaxf(r.z, 0.f); r.w = fmaxf(r.w, 0.f);
    }
    out[idx] = r;
}

// ---------------- bilinear upsample (k path only) ----------------
__global__ void __launch_bounds__(256)
upsample_ac(const float* __restrict__ in, float* __restrict__ out,
            int NC, int h, int w, int H, int W, float sy, float sx)
{
    const int idx = blockIdx.x * 256 + threadIdx.x;
    const int total = NC * H * W;
    if (idx >= total) return;
    const int x  = idx % W;
    const int y  = (idx / W) % H;
    const int nc = idx / (W * H);
    const float fy = y * sy;
    const float fx = x * sx;
    int y0 = (int)fy; if (y0 > h - 1) y0 = h - 1;
    int x0 = (int)fx; if (x0 > w - 1) x0 = w - 1;
    const int y1 = min(y0 + 1, h - 1);
    const int x1 = min(x0 + 1, w - 1);
    const float wy = fy - y0, wx = fx - x0;
    const float* p = in + (size_t)nc * h * w;
    const float v00 = p[y0 * w + x0], v01 = p[y0 * w + x1];
    const float v10 = p[y1 * w + x0], v11 = p[y1 * w + x1];
    const float a = v00 * (1.f - wy) + v10 * wy;
    const float b = v01 * (1.f - wy) + v11 * wy;
    out[idx] = a * (1.f - wx) + b * wx;
}

// ---------------- attention v2: kd-split across block ----------------
__global__ void __launch_bounds__(256)
attention_v2(const float* __restrict__ q, const float* __restrict__ kmap,
             float* __restrict__ att, int kd, int H, int W)
{
    __shared__ float s_part[32][8][36];
    __shared__ float s_red[8][36];
    const int tid  = threadIdx.x;
    const int qloc = tid & 7;
    const int si   = tid >> 3;
    const int Wq   = W >> 2;
    const int qg   = blockIdx.x * 8 + qloc;
    const int xq   = qg % Wq;
    const int y    = (qg / Wq) % H;
    const int n    = qg / (Wq * H);
    const int x0   = xq << 2;
    const size_t plane = (size_t)H * W;

    const bool lok = (x0 >= 4);
    const bool rok = (x0 + 4 < W);
    int rowoff[3]; bool rowok[3];
#pragma unroll
    for (int r = 0; r < 3; r++) {
        const int yy = y + (r - 1) * 2;
        rowok[r]  = ((unsigned)yy < (unsigned)H);
        rowoff[r] = yy * W + x0;
    }

    uint64_t lg[9][2];
#pragma unroll
    for (int t = 0; t < 9; t++) { lg[t][0] = 0ull; lg[t][1] = 0ull; }

    const int cpt = kd >> 5;
    const int c0  = si * cpt;
    const float* qp = q + ((size_t)n * kd + c0) * plane + (size_t)y * W + x0;
    const float* kp = kmap + ((size_t)n * kd + c0) * plane;
    const float4 z4 = make_float4(0.f, 0.f, 0.f, 0.f);

    for (int c = 0; c < cpt; ++c) {
        const float4 qv = *(const float4*)(qp + (size_t)c * plane);
        const uint64_t* qh = (const uint64_t*)&qv;
        const uint64_t q01 = qh[0], q23 = qh[1];
        const float* kc = kp + (size_t)c * plane;
#pragma unroll
        for (int r = 0; r < 3; r++) {
            if (!rowok[r]) continue;
            const float* kr = kc + rowoff[r];
            const float4 L = lok ? *(const float4*)(kr - 4) : z4;
            const float4 M = *(const float4*)kr;
            const float4 R = rok ? *(const float4*)(kr + 4) : z4;
            const uint64_t* Lh = (const uint64_t*)&L;
            const uint64_t* Mh = (const uint64_t*)&M;
            const uint64_t* Rh = (const uint64_t*)&R;
            const int t0 = r * 3;
            lg[t0 + 0][0] = fma2(q01, Lh[1], lg[t0 + 0][0]);
            lg[t0 + 0][1] = fma2(q23, Mh[0], lg[t0 + 0][1]);
            lg[t0 + 1][0] = fma2(q01, Mh[0], lg[t0 + 1][0]);
            lg[t0 + 1][1] = fma2(q23, Mh[1], lg[t0 + 1][1]);
            lg[t0 + 2][0] = fma2(q01, Mh[1], lg[t0 + 2][0]);
            lg[t0 + 2][1] = fma2(q23, Rh[0], lg[t0 + 2][1]);
        }
    }
#pragma unroll
    for (int t = 0; t < 9; t++) {
        const float2 a = unpack2(lg[t][0]);
        const float2 b = unpack2(lg[t][1]);
        s_part[si][qloc][t * 4 + 0] = a.x;
        s_part[si][qloc][t * 4 + 1] = a.y;
        s_part[si][qloc][t * 4 + 2] = b.x;
        s_part[si][qloc][t * 4 + 3] = b.y;
    }
    __syncthreads();

    for (int i = tid; i < 8 * 36; i += 256) {
        const int qq = i / 36, j = i - qq * 36;
        float s = 0.f;
#pragma unroll
        for (int s2 = 0; s2 < 32; s2++) s += s_part[s2][qq][j];
        s_red[qq][j] = s;
    }
    __syncthreads();

    if (tid < 32) {
        const int qq = tid >> 2, p = tid & 3;
        float l[9];
#pragma unroll
        for (int t = 0; t < 9; t++) l[t] = s_red[qq][t * 4 + p];
        float mx = l[0];
#pragma unroll
        for (int t = 1; t < 9; t++) mx = fmaxf(mx, l[t]);
        float s = 0.f;
#pragma unroll
        for (int t = 0; t < 9; t++) { l[t] = expf(l[t] - mx); s += l[t]; }
        const float inv = 1.f / s;
        const int qg2 = blockIdx.x * 8 + qq;
        const int xq2 = qg2 % Wq;
        const int y2  = (qg2 / Wq) % H;
        const int n2  = qg2 / (Wq * H);
        float* ap = att + (size_t)n2 * 9 * plane + (size_t)y2 * W + (xq2 << 2) + p;
#pragma unroll
        for (int t = 0; t < 9; t++) ap[(size_t)t * plane] = l[t] * inv;
    }
}

// ---------------- fused upsample + attention apply ----------------
template<int H, int W, int h, int w>
__global__ void __launch_bounds__(256)
apply_fused(const float* __restrict__ att, const float* __restrict__ lo,
            float* __restrict__ outp)
{
    constexpr int WPAD = W + 8;
    __shared__ __align__(16) float s_lo[8][6][w + 2];
    __shared__ __align__(16) float s_up[8][8][WPAD];
    const int y0  = blockIdx.x * 4;
    const int ch0 = blockIdx.y * 8;
    const int n   = blockIdx.z;
    const int tid = threadIdx.x;
    const int nth = blockDim.x;
    constexpr float sy = (float)(h - 1) / (float)(H - 1);
    constexpr float sx = (float)(w - 1) / (float)(W - 1);
    const size_t planeL = (size_t)h * w;
    const size_t planeH = (size_t)H * W;

    const int ylo = (y0 >= 2 ? y0 - 2 : 0);
    const int base = (int)((float)ylo * sy);
    for (int i = tid; i < 8 * 6 * w; i += nth) {
        const int ch = i / (6 * w);
        const int r  = (i / w) % 6;
        const int x  = i % w;
        const int gr = min(base + r, h - 1);
        s_lo[ch][r][x] = lo[((size_t)(n * 512 + ch0 + ch)) * planeL + (size_t)gr * w + x];
    }
    __syncthreads();

    for (int i = tid; i < 8 * 8 * WPAD; i += nth) {
        const int ch  = i / (8 * WPAD);
        const int rem = i - ch * (8 * WPAD);
        const int row = rem / WPAD;
        const int col = rem - row * WPAD;
        const int Y = y0 - 2 + row;
        const int X = col - 4;
        float v = 0.f;
        if ((unsigned)Y < (unsigned)H && (unsigned)X < (unsigned)W) {
            const float fy = Y * sy;
            int iy0 = (int)fy; if (iy0 > h - 1) iy0 = h - 1;
            const int ry0 = iy0 - base;
            const int ry1 = min(iy0 + 1, h - 1) - base;
            const float wy = fy - iy0;
            const float fx = X * sx;
            int ix0 = (int)fx; if (ix0 > w - 1) ix0 = w - 1;
            const int ix1 = min(ix0 + 1, w - 1);
            const float wx = fx - ix0;
            const float a = s_lo[ch][ry0][ix0] * (1.f - wx) + s_lo[ch][ry0][ix1] * wx;
            const float b = s_lo[ch][ry1][ix0] * (1.f - wx) + s_lo[ch][ry1][ix1] * wx;
            v = a * (1.f - wy) + b * wy;
        }
        s_up[ch][row][col] = v;
    }
    __syncthreads();

    const int Wp = W >> 1;
    const int xp = tid % Wp;
    const int yy = tid / Wp;
    const int y  = y0 + yy;
    const int x0 = xp << 1;

    uint64_t att2[9];
    const float* ap = att + (size_t)n * 9 * planeH + (size_t)y * W + x0;
#pragma unroll
    for (int t = 0; t < 9; t++) att2[t] = *(const uint64_t*)(ap + (size_t)t * planeH);

#pragma unroll
    for (int c = 0; c < 8; ++c) {
        uint64_t acc = 0ull;
#pragma unroll
        for (int iy = 0; iy < 3; iy++) {
            const float* rp = &s_up[c][yy + 2 * iy][0];
#pragma unroll
            for (int ix = 0; ix < 3; ix++) {
                const uint64_t u2 = *(const uint64_t*)(rp + x0 + 2 * ix + 2);
                acc = fma2(att2[iy * 3 + ix], u2, acc);
            }
        }
        const float2 v = unpack2(acc);
        *(float2*)&outp[((size_t)(n * 512 + ch0 + c)) * planeH + (size_t)y * W + x0] = v;
    }
}

// ---------------- conv6: 1x1, 512->19, C-split x8, 4 px/thread ----------------
__global__ void __launch_bounds__(128)
conv6_partial(const float* __restrict__ in, const float* __restrict__ w,
              float* __restrict__ part)
{
    __shared__ float sw[19 * 64];
    const int tid = threadIdx.x;
    const int cs  = blockIdx.y;
    const int n   = blockIdx.z;
    const int c0  = cs * 64;
    for (int i = tid; i < 19 * 64; i += 128) {
        const int o = i >> 6, c = i & 63;
        sw[i] = w[o * 512 + c0 + c];
    }
    __syncthreads();
    const int px = (blockIdx.x * 128 + tid) * 4;
    uint64_t acc2[19][2];
#pragma unroll
    for (int o = 0; o < 19; o++) { acc2[o][0] = 0ull; acc2[o][1] = 0ull; }
    const float* ip = in + ((size_t)n * 512 + c0) * 16384 + px;
    for (int c = 0; c < 64; ++c) {
        const float4 v4 = *(const float4*)(ip + (size_t)c * 16384);
        const uint64_t* vh = (const uint64_t*)&v4;
        const uint64_t v01 = vh[0], v23 = vh[1];
#pragma unroll
        for (int o = 0; o < 19; o++) {
            const uint64_t wv = bcast2(sw[(o << 6) + c]);
            acc2[o][0] = fma2(wv, v01, acc2[o][0]);
            acc2[o][1] = fma2(wv, v23, acc2[o][1]);
        }
    }
    float* op = part + ((size_t)(cs * 2 + n) * 19) * 16384 + px;
#pragma unroll
    for (int o = 0; o < 19; o++) {
        const float2 a = unpack2(acc2[o][0]);
        const float2 b = unpack2(acc2[o][1]);
        *(float4*)(op + (size_t)o * 16384) = make_float4(a.x, a.y, b.x, b.y);
    }
}

// ---------------- conv6 reduce + bias, float4, 8 splits ----------------
__global__ void __launch_bounds__(256)
conv6_reduce(const float4* __restrict__ part, const float* __restrict__ bias,
             float4* __restrict__ out)
{
    const int idx = blockIdx.x * 256 + threadIdx.x;
    const int perN = 19 * 16384 / 4;
    const int total = 2 * perN;
    if (idx >= total) return;
    const int n   = idx / perN;
    const int rem = idx - n * perN;
    const int o   = (rem * 4) / 16384;
    float4 s = make_float4(0.f, 0.f, 0.f, 0.f);
#pragma unroll
    for (int cs = 0; cs < 8; ++cs) {
        const float4 q = part[(size_t)(cs * 2 + n) * perN + rem];
        s.x += q.x; s.y += q.y; s.z += q.z; s.w += q.w;
    }
    const float b = bias[o];
    out[idx] = make_float4(s.x + b, s.y + b, s.z + b, s.w + b);
}

// ---------------- launch ----------------
extern "C" void kernel_launch(void* const* d_in, const int* in_sizes, int n_in,
                              void* d_out, int out_size)
{
    (void)in_sizes; (void)n_in; (void)out_size;
    const float* c1      = (const float*)d_in[0];
    const float* c2      = (const float*)d_in[1];
    const float* c3      = (const float*)d_in[2];
    const float* c4      = (const float*)d_in[3];
    const float* c30     = (const float*)d_in[5];
    const float* c40     = (const float*)d_in[6];
    const float* conv5_w = (const float*)d_in[7];
    const float* bn5     = (const float*)d_in[8];
    const float* conv6_w = (const float*)d_in[9];
    const float* conv6_b = (const float*)d_in[10];
    const float* lu4_w1  = (const float*)d_in[11];
    const float* lu4_bn1 = (const float*)d_in[12];
    const float* lu4_w2  = (const float*)d_in[13];
    const float* lu4_bn2 = (const float*)d_in[14];
    const float* lu3_w1  = (const float*)d_in[15];
    const float* lu3_bn1 = (const float*)d_in[16];
    const float* lu3_w2  = (const float*)d_in[17];
    const float* lu3_bn2 = (const float*)d_in[18];
    const float* lu2_w1  = (const float*)d_in[19];
    const float* lu2_bn1 = (const float*)d_in[20];
    const float* lu2_w2  = (const float*)d_in[21];
    const float* lu2_bn2 = (const float*)d_in[22];
    float* out = (float*)d_out;

    float *p_out, *p_up, *p_q, *p_q2, *p_k, *p_klo, *p_att, *p_part;
    cudaGetSymbolAddress((void**)&p_out,  g_out);
    cudaGetSymbolAddress((void**)&p_up,   g_up);
    cudaGetSymbolAddress((void**)&p_q,    g_q);
    cudaGetSymbolAddress((void**)&p_q2,   g_q2);
    cudaGetSymbolAddress((void**)&p_k,    g_k);
    cudaGetSymbolAddress((void**)&p_klo,  g_klo);
    cudaGetSymbolAddress((void**)&p_att,  g_att);
    cudaGetSymbolAddress((void**)&p_part, g_part);

    // ---- conv5 + BN + ReLU -> g_out (2,512,16,16); KS=32 ----
    conv5_partial<<<dim3(32, 8, 2), 256>>>(c4, conv5_w, p_part);
    reduce_bn4<<<(2 * 512 * 256 / 4 + 255) / 256, 256>>>((const float4*)p_part, bn5, (float4*)p_out, 512, 256, 32, 1);

    // ---- localUp2 q projection early (independent; dedicated buffer) ----
    conv1x1_bn<<<dim3(128, 1, 2), 256>>>(c1, lu2_w1, lu2_bn1, p_q2, 256, 64, 16384);

    // ---- localUp4: H=32, kd=128; lo=g_out -> g_up ----  (KS=16: 512 blocks)
    conv1x1_partial<<<dim3(8, 2 * 16, 2), 256>>>(c3, lu4_w1, p_part, 1024, 128, 1024, 16, 64);  // #4 (profiled)
    reduce_bn4<<<(2 * 128 * 1024 / 4 + 255) / 256, 256>>>((const float4*)p_part, lu4_bn1, (float4*)p_q, 128, 1024, 16, 0);
    conv1x1_partial<<<dim3(2, 2 * 64, 2), 256>>>(c40, lu4_w2, p_part, 2048, 128, 256, 64, 32);
    reduce_bn4<<<(2 * 128 * 256 / 4 + 255) / 256, 256>>>((const float4*)p_part, lu4_bn2, (float4*)p_klo, 128, 256, 64, 0);
    upsample_ac<<<(2 * 128 * 32 * 32 + 255) / 256, 256>>>(p_klo, p_k, 2 * 128, 16, 16, 32, 32, 15.f / 31.f, 15.f / 31.f);
    attention_v2<<<2 * 32 * 8 / 8, 256>>>(p_q, p_k, p_att, 128, 32, 32);
    apply_fused<32, 32, 16, 16><<<dim3(8, 64, 2), 64>>>(p_att, p_out, p_up);

    // ---- localUp3: H=64, kd=64; lo=g_up -> g_out ----  (KS=8: 512 blocks)
    conv1x1_partial<<<dim3(32, 1 * 8, 2), 256>>>(c2, lu3_w1, p_part, 512, 64, 4096, 8, 64);
    reduce_bn4<<<(2 * 64 * 4096 / 4 + 255) / 256, 256>>>((const float4*)p_part, lu3_bn1, (float4*)p_q, 64, 4096, 8, 0);
    conv1x1_partial<<<dim3(8, 1 * 32, 2), 256>>>(c30, lu3_w2, p_part, 1024, 64, 1024, 32, 32);
    reduce_bn4<<<(2 * 64 * 1024 / 4 + 255) / 256, 256>>>((const float4*)p_part, lu3_bn2, (float4*)p_klo, 64, 1024, 32, 0);
    upsample_ac<<<(2 * 64 * 64 * 64 + 255) / 256, 256>>>(p_klo, p_k, 2 * 64, 32, 32, 64, 64, 31.f / 63.f, 31.f / 63.f);
    attention_v2<<<2 * 64 * 16 / 8, 256>>>(p_q, p_k, p_att, 64, 64, 64);
    apply_fused<64, 64, 32, 32><<<dim3(16, 64, 2), 128>>>(p_att, p_up, p_out);

    // ---- localUp2: H=128, kd=64; lo=g_out -> g_up ----  (q already in g_q2; KS=8)
    conv1x1_partial<<<dim3(32, 1 * 8, 2), 256>>>(c2, lu2_w2, p_part, 512, 64, 4096, 8, 64);
    reduce_bn4<<<(2 * 64 * 4096 / 4 + 255) / 256, 256>>>((const float4*)p_part, lu2_bn2, (float4*)p_klo, 64, 4096, 8, 0);
    upsample_ac<<<(2 * 64 * 128 * 128 + 255) / 256, 256>>>(p_klo, p_k, 2 * 64, 64, 64, 128, 128, 63.f / 127.f, 63.f / 127.f);
    attention_v2<<<2 * 128 * 32 / 8, 256>>>(p_q2, p_k, p_att, 64, 128, 128);
    apply_fused<128, 128, 64, 64><<<dim3(32, 64, 2), 256>>>(p_att, p_out, p_up);

    // ---- conv6 1x1 -> (2,19,128,128), C-split x8, 4 px/thread ----
    conv6_partial<<<dim3(32, 8, 2), 128>>>(p_up, conv6_w, p_part);
    conv6_reduce<<<(2 * 19 * 16384 / 4 + 255) / 256, 256>>>((const float4*)p_part, conv6_b, (float4*)out);
}

// round 13
// speedup vs baseline: 1.3406x; 1.0028x over previous
#include <cuda_runtime.h>
#include <math.h>
#include <stdint.h>

#define BN_EPS 1e-5f

// ---------------- f32x2 helpers ----------------
__device__ __forceinline__ uint64_t bcast2(float v) {
    uint64_t r; asm("mov.b64 %0, {%1,%1};" : "=l"(r) : "f"(v)); return r;
}
__device__ __forceinline__ uint64_t fma2(uint64_t a, uint64_t b, uint64_t c) {
    uint64_t d; asm("fma.rn.f32x2 %0, %1, %2, %3;" : "=l"(d) : "l"(a), "l"(b), "l"(c)); return d;
}
__device__ __forceinline__ float2 unpack2(uint64_t v) {
    float2 f; asm("mov.b64 {%0,%1}, %2;" : "=f"(f.x), "=f"(f.y) : "l"(v)); return f;
}

// ---------------- scratch ----------------
__device__ float g_out [16777216];  // ping
__device__ float g_up  [16777216];  // pong
__device__ float g_q   [2097152];
__device__ float g_q2  [2097152];   // localUp2 q (computed early, must survive)
__device__ float g_k   [2097152];
__device__ float g_klo [524288];
__device__ float g_att [294912];
__device__ float g_part[8388608];   // K-split partials

// ---------------- conv5: 3x3, 2048->512 @ 16x16, K-split (KS=32) ----------------
// Occupancy-tiled: 32 oc x 256 px per block (acc 32 regs), grid (32,16,2).
__global__ void __launch_bounds__(256)
conv5_partial(const float* __restrict__ in, const float* __restrict__ w,
              float* __restrict__ part)
{
    const int ks = blockIdx.x, ocb = blockIdx.y, n = blockIdx.z;
    __shared__ float s_in[8 * 342];        // 8 ic x (18 rows, stride 19)
    __shared__ float s_w [8 * 9 * 32];     // [ic][tap][oc] (32 oc)
    const int tid = threadIdx.x;
    const int og  = tid >> 5;              // 0..7 -> 4 oc each
    const int pg  = tid & 31;
    const int py  = pg >> 1;
    const int px0 = (pg & 1) << 3;

    uint64_t acc2[2][8];
#pragma unroll
    for (int i = 0; i < 2; i++)
#pragma unroll
        for (int j = 0; j < 8; j++) acc2[i][j] = 0ull;

    const int icbase = ks * 64;
    for (int tile = 0; tile < 8; ++tile) {
        const int ict0 = icbase + tile * 8;
        __syncthreads();
        for (int i = tid; i < 8 * 324; i += 256) {
            const int ic = i / 324, rem = i - ic * 324;
            const int ry = rem / 18, rx = rem - ry * 18;
            const int yy = ry - 1, xx = rx - 1;
            float v = 0.f;
            if ((unsigned)yy < 16u && (unsigned)xx < 16u)
                v = in[(((size_t)n * 2048 + ict0 + ic) * 16 + yy) * 16 + xx];
            s_in[ic * 342 + ry * 19 + rx] = v;
        }
        for (int i = tid; i < 8 * 9 * 32; i += 256) {
            const int oc = i / 72, r = i - oc * 72;
            const int ic = r / 9, t = r - ic * 9;
            s_w[(ic * 9 + t) * 32 + oc] =
                w[(size_t)(ocb * 32 + oc) * 18432 + (size_t)(ict0 + ic) * 9 + t];
        }
        __syncthreads();
        for (int ic = 0; ic < 8; ++ic) {
            const float* si  = s_in + ic * 342;
            const float* swp = s_w  + ic * 9 * 32;
#pragma unroll
            for (int r = 0; r < 3; ++r) {
                const float* rp = si + (py + r) * 19 + px0;
                uint64_t inb[10];
#pragma unroll
                for (int u = 0; u < 10; ++u) inb[u] = bcast2(rp[u]);
#pragma unroll
                for (int s = 0; s < 3; ++s) {
                    const int t = r * 3 + s;
                    const uint64_t* wrow = (const uint64_t*)(swp + t * 32 + og * 4);
                    const uint64_t w0 = wrow[0], w1 = wrow[1];
#pragma unroll
                    for (int j = 0; j < 8; j++) {
                        const uint64_t iv2 = inb[s + j];
                        acc2[0][j] = fma2(w0, iv2, acc2[0][j]);
                        acc2[1][j] = fma2(w1, iv2, acc2[1][j]);
                    }
                }
            }
        }
    }
    float* dst = part + (size_t)(ks * 2 + n) * 512 * 256;
    const int px = py * 16 + px0;
#pragma unroll
    for (int i = 0; i < 2; i++) {
        const int oc = ocb * 32 + og * 4 + 2 * i;
#pragma unroll
        for (int j = 0; j < 8; j++) {
            const float2 v = unpack2(acc2[i][j]);
            dst[oc * 256 + px + j]       = v.x;
            dst[(oc + 1) * 256 + px + j] = v.y;
        }
    }
}

// ---------------- generic 1x1 conv GEMM, smem double-buffer ----------------
__global__ void __launch_bounds__(256)
conv1x1_partial(const float* __restrict__ in, const float* __restrict__ w,
                float* __restrict__ part,
                int Cin, int Cout, int P, int KS, int KCH)
{
    const int pxb = blockIdx.x;
    const int ocb = blockIdx.y / KS;
    const int ks  = blockIdx.y % KS;
    const int n   = blockIdx.z;
    const int k0  = ks * KCH;
    __shared__ float sA[2][16][68];
    __shared__ float sB[2][16][136];
    const int tid = threadIdx.x;
    const int ocg = tid >> 4;
    const int pxg = tid & 15;

    uint64_t acc2[4][4];
#pragma unroll
    for (int i = 0; i < 4; i++)
#pragma unroll
        for (int j = 0; j < 4; j++) acc2[i][j] = 0ull;

    const float* wrow = w + (size_t)(ocb * 64) * Cin + k0;
    const float* brow = in + ((size_t)n * Cin + k0) * P + pxb * 128;

    float  a_reg[4];
    float4 b_reg[2];
#pragma unroll
    for (int i = 0; i < 4; i++) {
        const int idx = (i << 8) + tid;
        sA[0][idx & 15][idx >> 4] = wrow[(size_t)(idx >> 4) * Cin + (idx & 15)];
    }
#pragma unroll
    for (int i = 0; i < 2; i++) {
        const int idx = (i << 8) + tid;
        *(float4*)&sB[0][idx >> 5][(idx & 31) << 2] =
            *(const float4*)&brow[(size_t)(idx >> 5) * P + ((idx & 31) << 2)];
    }
    __syncthreads();

    for (int kc = 0; kc < KCH; kc += 16) {
        const int cur = (kc >> 4) & 1;
        const int kn  = kc + 16;
        const bool more = (kn < KCH);
        if (more) {
#pragma unroll
            for (int i = 0; i < 4; i++) {
                const int idx = (i << 8) + tid;
                a_reg[i] = wrow[(size_t)(idx >> 4) * Cin + kn + (idx & 15)];
            }
#pragma unroll
            for (int i = 0; i < 2; i++) {
                const int idx = (i << 8) + tid;
                b_reg[i] = *(const float4*)&brow[(size_t)(kn + (idx >> 5)) * P + ((idx & 31) << 2)];
            }
        }
#pragma unroll
        for (int kk = 0; kk < 16; ++kk) {
            const float4 a4 = *(const float4*)&sA[cur][kk][ocg << 2];
            const float4 b40 = *(const float4*)&sB[cur][kk][pxg << 3];
            const float4 b41 = *(const float4*)&sB[cur][kk][(pxg << 3) + 4];
            const uint64_t* b2 = (const uint64_t*)&b40;
            const uint64_t* b3 = (const uint64_t*)&b41;
            const uint64_t a0 = bcast2(a4.x), a1 = bcast2(a4.y);
            const uint64_t a2 = bcast2(a4.z), a3 = bcast2(a4.w);
            acc2[0][0] = fma2(a0, b2[0], acc2[0][0]);
            acc2[0][1] = fma2(a0, b2[1], acc2[0][1]);
            acc2[0][2] = fma2(a0, b3[0], acc2[0][2]);
            acc2[0][3] = fma2(a0, b3[1], acc2[0][3]);
            acc2[1][0] = fma2(a1, b2[0], acc2[1][0]);
            acc2[1][1] = fma2(a1, b2[1], acc2[1][1]);
            acc2[1][2] = fma2(a1, b3[0], acc2[1][2]);
            acc2[1][3] = fma2(a1, b3[1], acc2[1][3]);
            acc2[2][0] = fma2(a2, b2[0], acc2[2][0]);
            acc2[2][1] = fma2(a2, b2[1], acc2[2][1]);
            acc2[2][2] = fma2(a2, b3[0], acc2[2][2]);
            acc2[2][3] = fma2(a2, b3[1], acc2[2][3]);
            acc2[3][0] = fma2(a3, b2[0], acc2[3][0]);
            acc2[3][1] = fma2(a3, b2[1], acc2[3][1]);
            acc2[3][2] = fma2(a3, b3[0], acc2[3][2]);
            acc2[3][3] = fma2(a3, b3[1], acc2[3][3]);
        }
        if (more) {
            const int nxt = cur ^ 1;
#pragma unroll
            for (int i = 0; i < 4; i++) {
                const int idx = (i << 8) + tid;
                sA[nxt][idx & 15][idx >> 4] = a_reg[i];
            }
#pragma unroll
            for (int i = 0; i < 2; i++) {
                const int idx = (i << 8) + tid;
                *(float4*)&sB[nxt][idx >> 5][(idx & 31) << 2] = b_reg[i];
            }
        }
        __syncthreads();
    }
    float* dst = part + (size_t)(ks * 2 + n) * Cout * P;
    const int ocx = ocb * 64 + (ocg << 2);
    const int px  = pxb * 128 + (pxg << 3);
#pragma unroll
    for (int i = 0; i < 4; i++) {
        const float2 v0 = unpack2(acc2[i][0]), v1 = unpack2(acc2[i][1]);
        const float2 v2 = unpack2(acc2[i][2]), v3 = unpack2(acc2[i][3]);
        *(float4*)&dst[(size_t)(ocx + i) * P + px]     = make_float4(v0.x, v0.y, v1.x, v1.y);
        *(float4*)&dst[(size_t)(ocx + i) * P + px + 4] = make_float4(v2.x, v2.y, v3.x, v3.y);
    }
}

// ---------------- 1x1 conv + fused BN, smem double-buffer ----------------
__global__ void __launch_bounds__(256)
conv1x1_bn(const float* __restrict__ in, const float* __restrict__ w,
           const float* __restrict__ bn, float* __restrict__ outp,
           int Cin, int Cout, int P)
{
    const int pxb = blockIdx.x;
    const int ocb = blockIdx.y;
    const int n   = blockIdx.z;
    __shared__ float sA[2][16][68];
    __shared__ float sB[2][16][136];
    const int tid = threadIdx.x;
    const int ocg = tid >> 4;
    const int pxg = tid & 15;

    uint64_t acc2[4][4];
#pragma unroll
    for (int i = 0; i < 4; i++)
#pragma unroll
        for (int j = 0; j < 4; j++) acc2[i][j] = 0ull;

    const float* wrow = w + (size_t)(ocb * 64) * Cin;
    const float* brow = in + ((size_t)n * Cin) * P + pxb * 128;

    float  a_reg[4];
    float4 b_reg[2];
#pragma unroll
    for (int i = 0; i < 4; i++) {
        const int idx = (i << 8) + tid;
        sA[0][idx & 15][idx >> 4] = wrow[(size_t)(idx >> 4) * Cin + (idx & 15)];
    }
#pragma unroll
    for (int i = 0; i < 2; i++) {
        const int idx = (i << 8) + tid;
        *(float4*)&sB[0][idx >> 5][(idx & 31) << 2] =
            *(const float4*)&brow[(size_t)(idx >> 5) * P + ((idx & 31) << 2)];
    }
    __syncthreads();

    for (int kc = 0; kc < Cin; kc += 16) {
        const int cur = (kc >> 4) & 1;
        const int kn  = kc + 16;
        const bool more = (kn < Cin);
        if (more) {
#pragma unroll
            for (int i = 0; i < 4; i++) {
                const int idx = (i << 8) + tid;
                a_reg[i] = wrow[(size_t)(idx >> 4) * Cin + kn + (idx & 15)];
            }
#pragma unroll
            for (int i = 0; i < 2; i++) {
                const int idx = (i << 8) + tid;
                b_reg[i] = *(const float4*)&brow[(size_t)(kn + (idx >> 5)) * P + ((idx & 31) << 2)];
            }
        }
#pragma unroll
        for (int kk = 0; kk < 16; ++kk) {
            const float4 a4 = *(const float4*)&sA[cur][kk][ocg << 2];
            const uint64_t* bp = (const uint64_t*)&sB[cur][kk][pxg << 3];
            uint64_t b2[4] = { bp[0], bp[1], bp[2], bp[3] };
            const uint64_t a0 = bcast2(a4.x), a1 = bcast2(a4.y);
            const uint64_t a2 = bcast2(a4.z), a3 = bcast2(a4.w);
#pragma unroll
            for (int j = 0; j < 4; j++) {
                acc2[0][j] = fma2(a0, b2[j], acc2[0][j]);
                acc2[1][j] = fma2(a1, b2[j], acc2[1][j]);
                acc2[2][j] = fma2(a2, b2[j], acc2[2][j]);
                acc2[3][j] = fma2(a3, b2[j], acc2[3][j]);
            }
        }
        if (more) {
            const int nxt = cur ^ 1;
#pragma unroll
            for (int i = 0; i < 4; i++) {
                const int idx = (i << 8) + tid;
                sA[nxt][idx & 15][idx >> 4] = a_reg[i];
            }
#pragma unroll
            for (int i = 0; i < 2; i++) {
                const int idx = (i << 8) + tid;
                *(float4*)&sB[nxt][idx >> 5][(idx & 31) << 2] = b_reg[i];
            }
        }
        __syncthreads();
    }
    const int ocx = ocb * 64 + (ocg << 2);
    const int px  = pxb * 128 + (pxg << 3);
#pragma unroll
    for (int i = 0; i < 4; i++) {
        const int oc = ocx + i;
        const float g = bn[oc], b = bn[Cout + oc], m = bn[2 * Cout + oc], v = bn[3 * Cout + oc];
        const float sc = g / sqrtf(v + BN_EPS);
        const float sh = b - m * sc;
        const float2 v0 = unpack2(acc2[i][0]), v1 = unpack2(acc2[i][1]);
        const float2 v2 = unpack2(acc2[i][2]), v3 = unpack2(acc2[i][3]);
        float* op = outp + ((size_t)n * Cout + oc) * P + px;
        *(float4*)op       = make_float4(v0.x * sc + sh, v0.y * sc + sh, v1.x * sc + sh, v1.y * sc + sh);
        *(float4*)(op + 4) = make_float4(v2.x * sc + sh, v2.y * sc + sh, v3.x * sc + sh, v3.y * sc + sh);
    }
}

// ---------------- reduce K-splits + BN (+ReLU), float4 ----------------
__global__ void __launch_bounds__(256)
reduce_bn4(const float4* __restrict__ part, const float* __restrict__ bn,
           float4* __restrict__ out, int C, int P, int KS, int relu)
{
    const int idx = blockIdx.x * 256 + threadIdx.x;
    const int total4 = 2 * C * P / 4;
    if (idx >= total4) return;
    const int c = ((idx * 4) / P) % C;
    const size_t stride4 = (size_t)2 * C * P / 4;
    float4 s = make_float4(0.f, 0.f, 0.f, 0.f);
    for (int k = 0; k < KS; ++k) {
        const float4 q = part[(size_t)k * stride4 + idx];
        s.x += q.x; s.y += q.y; s.z += q.z; s.w += q.w;
    }
    const float g = bn[c], b = bn[C + c], m = bn[2 * C + c], v = bn[3 * C + c];
    const float sc = g / sqrtf(v + BN_EPS);
    const float sh = b - m * sc;
    float4 r = make_float4(s.x * sc + sh, s.y * sc + sh, s.z * sc + sh, s.w * sc + sh);
    if (relu) {
        r.x = fmaxf(r.x, 0.f); r.y = fmaxf(r.y, 0.f);
        r.z = fmaxf(r.z, 0.f); r.w = fmaxf(r.w, 0.f);
    }
    out[idx] = r;
}

// ---------------- bilinear upsample (k path only) ----------------
__global__ void __launch_bounds__(256)
upsample_ac(const float* __restrict__ in, float* __restrict__ out,
            int NC, int h, int w, int H, int W, float sy, float sx)
{
    const int idx = blockIdx.x * 256 + threadIdx.x;
    const int total = NC * H * W;
    if (idx >= total) return;
    const int x  = idx % W;
    const int y  = (idx / W) % H;
    const int nc = idx / (W * H);
    const float fy = y * sy;
    const float fx = x * sx;
    int y0 = (int)fy; if (y0 > h - 1) y0 = h - 1;
    int x0 = (int)fx; if (x0 > w - 1) x0 = w - 1;
    const int y1 = min(y0 + 1, h - 1);
    const int x1 = min(x0 + 1, w - 1);
    const float wy = fy - y0, wx = fx - x0;
    const float* p = in + (size_t)nc * h * w;
    const float v00 = p[y0 * w + x0], v01 = p[y0 * w + x1];
    const float v10 = p[y1 * w + x0], v11 = p[y1 * w + x1];
    const float a = v00 * (1.f - wy) + v10 * wy;
    const float b = v01 * (1.f - wy) + v11 * wy;
    out[idx] = a * (1.f - wx) + b * wx;
}

// ---------------- attention v2: kd-split across block ----------------
__global__ void __launch_bounds__(256)
attention_v2(const float* __restrict__ q, const float* __restrict__ kmap,
             float* __restrict__ att, int kd, int H, int W)
{
    __shared__ float s_part[32][8][36];
    __shared__ float s_red[8][36];
    const int tid  = threadIdx.x;
    const int qloc = tid & 7;
    const int si   = tid >> 3;
    const int Wq   = W >> 2;
    const int qg   = blockIdx.x * 8 + qloc;
    const int xq   = qg % Wq;
    const int y    = (qg / Wq) % H;
    const int n    = qg / (Wq * H);
    const int x0   = xq << 2;
    const size_t plane = (size_t)H * W;

    const bool lok = (x0 >= 4);
    const bool rok = (x0 + 4 < W);
    int rowoff[3]; bool rowok[3];
#pragma unroll
    for (int r = 0; r < 3; r++) {
        const int yy = y + (r - 1) * 2;
        rowok[r]  = ((unsigned)yy < (unsigned)H);
        rowoff[r] = yy * W + x0;
    }

    uint64_t lg[9][2];
#pragma unroll
    for (int t = 0; t < 9; t++) { lg[t][0] = 0ull; lg[t][1] = 0ull; }

    const int cpt = kd >> 5;
    const int c0  = si * cpt;
    const float* qp = q + ((size_t)n * kd + c0) * plane + (size_t)y * W + x0;
    const float* kp = kmap + ((size_t)n * kd + c0) * plane;
    const float4 z4 = make_float4(0.f, 0.f, 0.f, 0.f);

    for (int c = 0; c < cpt; ++c) {
        const float4 qv = *(const float4*)(qp + (size_t)c * plane);
        const uint64_t* qh = (const uint64_t*)&qv;
        const uint64_t q01 = qh[0], q23 = qh[1];
        const float* kc = kp + (size_t)c * plane;
#pragma unroll
        for (int r = 0; r < 3; r++) {
            if (!rowok[r]) continue;
            const float* kr = kc + rowoff[r];
            const float4 L = lok ? *(const float4*)(kr - 4) : z4;
            const float4 M = *(const float4*)kr;
            const float4 R = rok ? *(const float4*)(kr + 4) : z4;
            const uint64_t* Lh = (const uint64_t*)&L;
            const uint64_t* Mh = (const uint64_t*)&M;
            const uint64_t* Rh = (const uint64_t*)&R;
            const int t0 = r * 3;
            lg[t0 + 0][0] = fma2(q01, Lh[1], lg[t0 + 0][0]);
            lg[t0 + 0][1] = fma2(q23, Mh[0], lg[t0 + 0][1]);
            lg[t0 + 1][0] = fma2(q01, Mh[0], lg[t0 + 1][0]);
            lg[t0 + 1][1] = fma2(q23, Mh[1], lg[t0 + 1][1]);
            lg[t0 + 2][0] = fma2(q01, Mh[1], lg[t0 + 2][0]);
            lg[t0 + 2][1] = fma2(q23, Rh[0], lg[t0 + 2][1]);
        }
    }
#pragma unroll
    for (int t = 0; t < 9; t++) {
        const float2 a = unpack2(lg[t][0]);
        const float2 b = unpack2(lg[t][1]);
        s_part[si][qloc][t * 4 + 0] = a.x;
        s_part[si][qloc][t * 4 + 1] = a.y;
        s_part[si][qloc][t * 4 + 2] = b.x;
        s_part[si][qloc][t * 4 + 3] = b.y;
    }
    __syncthreads();

    for (int i = tid; i < 8 * 36; i += 256) {
        const int qq = i / 36, j = i - qq * 36;
        float s = 0.f;
#pragma unroll
        for (int s2 = 0; s2 < 32; s2++) s += s_part[s2][qq][j];
        s_red[qq][j] = s;
    }
    __syncthreads();

    if (tid < 32) {
        const int qq = tid >> 2, p = tid & 3;
        float l[9];
#pragma unroll
        for (int t = 0; t < 9; t++) l[t] = s_red[qq][t * 4 + p];
        float mx = l[0];
#pragma unroll
        for (int t = 1; t < 9; t++) mx = fmaxf(mx, l[t]);
        float s = 0.f;
#pragma unroll
        for (int t = 0; t < 9; t++) { l[t] = expf(l[t] - mx); s += l[t]; }
        const float inv = 1.f / s;
        const int qg2 = blockIdx.x * 8 + qq;
        const int xq2 = qg2 % Wq;
        const int y2  = (qg2 / Wq) % H;
        const int n2  = qg2 / (Wq * H);
        float* ap = att + (size_t)n2 * 9 * plane + (size_t)y2 * W + (xq2 << 2) + p;
#pragma unroll
        for (int t = 0; t < 9; t++) ap[(size_t)t * plane] = l[t] * inv;
    }
}

// ---------------- fused upsample + attention apply ----------------
template<int H, int W, int h, int w>
__global__ void __launch_bounds__(256)
apply_fused(const float* __restrict__ att, const float* __restrict__ lo,
            float* __restrict__ outp)
{
    constexpr int WPAD = W + 8;
    __shared__ __align__(16) float s_lo[8][6][w + 2];
    __shared__ __align__(16) float s_up[8][8][WPAD];
    const int y0  = blockIdx.x * 4;
    const int ch0 = blockIdx.y * 8;
    const int n   = blockIdx.z;
    const int tid = threadIdx.x;
    const int nth = blockDim.x;
    constexpr float sy = (float)(h - 1) / (float)(H - 1);
    constexpr float sx = (float)(w - 1) / (float)(W - 1);
    const size_t planeL = (size_t)h * w;
    const size_t planeH = (size_t)H * W;

    const int ylo = (y0 >= 2 ? y0 - 2 : 0);
    const int base = (int)((float)ylo * sy);
    for (int i = tid; i < 8 * 6 * w; i += nth) {
        const int ch = i / (6 * w);
        const int r  = (i / w) % 6;
        const int x  = i % w;
        const int gr = min(base + r, h - 1);
        s_lo[ch][r][x] = lo[((size_t)(n * 512 + ch0 + ch)) * planeL + (size_t)gr * w + x];
    }
    __syncthreads();

    for (int i = tid; i < 8 * 8 * WPAD; i += nth) {
        const int ch  = i / (8 * WPAD);
        const int rem = i - ch * (8 * WPAD);
        const int row = rem / WPAD;
        const int col = rem - row * WPAD;
        const int Y = y0 - 2 + row;
        const int X = col - 4;
        float v = 0.f;
        if ((unsigned)Y < (unsigned)H && (unsigned)X < (unsigned)W) {
            const float fy = Y * sy;
            int iy0 = (int)fy; if (iy0 > h - 1) iy0 = h - 1;
            const int ry0 = iy0 - base;
            const int ry1 = min(iy0 + 1, h - 1) - base;
            const float wy = fy - iy0;
            const float fx = X * sx;
            int ix0 = (int)fx; if (ix0 > w - 1) ix0 = w - 1;
            const int ix1 = min(ix0 + 1, w - 1);
            const float wx = fx - ix0;
            const float a = s_lo[ch][ry0][ix0] * (1.f - wx) + s_lo[ch][ry0][ix1] * wx;
            const float b = s_lo[ch][ry1][ix0] * (1.f - wx) + s_lo[ch][ry1][ix1] * wx;
            v = a * (1.f - wy) + b * wy;
        }
        s_up[ch][row][col] = v;
    }
    __syncthreads();

    const int Wp = W >> 1;
    const int xp = tid % Wp;
    const int yy = tid / Wp;
    const int y  = y0 + yy;
    const int x0 = xp << 1;

    uint64_t att2[9];
    const float* ap = att + (size_t)n * 9 * planeH + (size_t)y * W + x0;
#pragma unroll
    for (int t = 0; t < 9; t++) att2[t] = *(const uint64_t*)(ap + (size_t)t * planeH);

#pragma unroll
    for (int c = 0; c < 8; ++c) {
        uint64_t acc = 0ull;
#pragma unroll
        for (int iy = 0; iy < 3; iy++) {
            const float* rp = &s_up[c][yy + 2 * iy][0];
#pragma unroll
            for (int ix = 0; ix < 3; ix++) {
                const uint64_t u2 = *(const uint64_t*)(rp + x0 + 2 * ix + 2);
                acc = fma2(att2[iy * 3 + ix], u2, acc);
            }
        }
        const float2 v = unpack2(acc);
        *(float2*)&outp[((size_t)(n * 512 + ch0 + c)) * planeH + (size_t)y * W + x0] = v;
    }
}

// ---------------- conv6: 1x1, 512->19, C-split x8, 4 px/thread ----------------
__global__ void __launch_bounds__(128)
conv6_partial(const float* __restrict__ in, const float* __restrict__ w,
              float* __restrict__ part)
{
    __shared__ float sw[19 * 64];
    const int tid = threadIdx.x;
    const int cs  = blockIdx.y;
    const int n   = blockIdx.z;
    const int c0  = cs * 64;
    for (int i = tid; i < 19 * 64; i += 128) {
        const int o = i >> 6, c = i & 63;
        sw[i] = w[o * 512 + c0 + c];
    }
    __syncthreads();
    const int px = (blockIdx.x * 128 + tid) * 4;
    uint64_t acc2[19][2];
#pragma unroll
    for (int o = 0; o < 19; o++) { acc2[o][0] = 0ull; acc2[o][1] = 0ull; }
    const float* ip = in + ((size_t)n * 512 + c0) * 16384 + px;
    for (int c = 0; c < 64; ++c) {
        const float4 v4 = *(const float4*)(ip + (size_t)c * 16384);
        const uint64_t* vh = (const uint64_t*)&v4;
        const uint64_t v01 = vh[0], v23 = vh[1];
#pragma unroll
        for (int o = 0; o < 19; o++) {
            const uint64_t wv = bcast2(sw[(o << 6) + c]);
            acc2[o][0] = fma2(wv, v01, acc2[o][0]);
            acc2[o][1] = fma2(wv, v23, acc2[o][1]);
        }
    }
    float* op = part + ((size_t)(cs * 2 + n) * 19) * 16384 + px;
#pragma unroll
    for (int o = 0; o < 19; o++) {
        const float2 a = unpack2(acc2[o][0]);
        const float2 b = unpack2(acc2[o][1]);
        *(float4*)(op + (size_t)o * 16384) = make_float4(a.x, a.y, b.x, b.y);
    }
}

// ---------------- conv6 reduce + bias, float4, 8 splits ----------------
__global__ void __launch_bounds__(256)
conv6_reduce(const float4* __restrict__ part, const float* __restrict__ bias,
             float4* __restrict__ out)
{
    const int idx = blockIdx.x * 256 + threadIdx.x;
    const int perN = 19 * 16384 / 4;
    const int total = 2 * perN;
    if (idx >= total) return;
    const int n   = idx / perN;
    const int rem = idx - n * perN;
    const int o   = (rem * 4) / 16384;
    float4 s = make_float4(0.f, 0.f, 0.f, 0.f);
#pragma unroll
    for (int cs = 0; cs < 8; ++cs) {
        const float4 q = part[(size_t)(cs * 2 + n) * perN + rem];
        s.x += q.x; s.y += q.y; s.z += q.z; s.w += q.w;
    }
    const float b = bias[o];
    out[idx] = make_float4(s.x + b, s.y + b, s.z + b, s.w + b);
}

// ---------------- launch ----------------
extern "C" void kernel_launch(void* const* d_in, const int* in_sizes, int n_in,
                              void* d_out, int out_size)
{
    (void)in_sizes; (void)n_in; (void)out_size;
    const float* c1      = (const float*)d_in[0];
    const float* c2      = (const float*)d_in[1];
    const float* c3      = (const float*)d_in[2];
    const float* c4      = (const float*)d_in[3];
    const float* c30     = (const float*)d_in[5];
    const float* c40     = (const float*)d_in[6];
    const float* conv5_w = (const float*)d_in[7];
    const float* bn5     = (const float*)d_in[8];
    const float* conv6_w = (const float*)d_in[9];
    const float* conv6_b = (const float*)d_in[10];
    const float* lu4_w1  = (const float*)d_in[11];
    const float* lu4_bn1 = (const float*)d_in[12];
    const float* lu4_w2  = (const float*)d_in[13];
    const float* lu4_bn2 = (const float*)d_in[14];
    const float* lu3_w1  = (const float*)d_in[15];
    const float* lu3_bn1 = (const float*)d_in[16];
    const float* lu3_w2  = (const float*)d_in[17];
    const float* lu3_bn2 = (const float*)d_in[18];
    const float* lu2_w1  = (const float*)d_in[19];
    const float* lu2_bn1 = (const float*)d_in[20];
    const float* lu2_w2  = (const float*)d_in[21];
    const float* lu2_bn2 = (const float*)d_in[22];
    float* out = (float*)d_out;

    float *p_out, *p_up, *p_q, *p_q2, *p_k, *p_klo, *p_att, *p_part;
    cudaGetSymbolAddress((void**)&p_out,  g_out);
    cudaGetSymbolAddress((void**)&p_up,   g_up);
    cudaGetSymbolAddress((void**)&p_q,    g_q);
    cudaGetSymbolAddress((void**)&p_q2,   g_q2);
    cudaGetSymbolAddress((void**)&p_k,    g_k);
    cudaGetSymbolAddress((void**)&p_klo,  g_klo);
    cudaGetSymbolAddress((void**)&p_att,  g_att);
    cudaGetSymbolAddress((void**)&p_part, g_part);

    // ---- independent front work (also aligns conv5 into profiled slot #4) ----
    conv1x1_bn<<<dim3(128, 1, 2), 256>>>(c1, lu2_w1, lu2_bn1, p_q2, 256, 64, 16384);              // #1
    conv1x1_partial<<<dim3(8, 2 * 16, 2), 256>>>(c3, lu4_w1, p_part, 1024, 128, 1024, 16, 64);    // #2
    reduce_bn4<<<(2 * 128 * 1024 / 4 + 255) / 256, 256>>>((const float4*)p_part, lu4_bn1, (float4*)p_q, 128, 1024, 16, 0); // #3

    // ---- conv5 + BN + ReLU -> g_out (2,512,16,16); KS=32, ocb=16 ----
    conv5_partial<<<dim3(32, 16, 2), 256>>>(c4, conv5_w, p_part);                                  // #4 (profiled)
    reduce_bn4<<<(2 * 512 * 256 / 4 + 255) / 256, 256>>>((const float4*)p_part, bn5, (float4*)p_out, 512, 256, 32, 1);

    // ---- localUp4: H=32, kd=128; lo=g_out -> g_up ----
    conv1x1_partial<<<dim3(2, 2 * 64, 2), 256>>>(c40, lu4_w2, p_part, 2048, 128, 256, 64, 32);
    reduce_bn4<<<(2 * 128 * 256 / 4 + 255) / 256, 256>>>((const float4*)p_part, lu4_bn2, (float4*)p_klo, 128, 256, 64, 0);
    upsample_ac<<<(2 * 128 * 32 * 32 + 255) / 256, 256>>>(p_klo, p_k, 2 * 128, 16, 16, 32, 32, 15.f / 31.f, 15.f / 31.f);
    attention_v2<<<2 * 32 * 8 / 8, 256>>>(p_q, p_k, p_att, 128, 32, 32);
    apply_fused<32, 32, 16, 16><<<dim3(8, 64, 2), 64>>>(p_att, p_out, p_up);

    // ---- localUp3: H=64, kd=64; lo=g_up -> g_out ----
    conv1x1_partial<<<dim3(32, 1 * 8, 2), 256>>>(c2, lu3_w1, p_part, 512, 64, 4096, 8, 64);
    reduce_bn4<<<(2 * 64 * 4096 / 4 + 255) / 256, 256>>>((const float4*)p_part, lu3_bn1, (float4*)p_q, 64, 4096, 8, 0);
    conv1x1_partial<<<dim3(8, 1 * 32, 2), 256>>>(c30, lu3_w2, p_part, 1024, 64, 1024, 32, 32);
    reduce_bn4<<<(2 * 64 * 1024 / 4 + 255) / 256, 256>>>((const float4*)p_part, lu3_bn2, (float4*)p_klo, 64, 1024, 32, 0);
    upsample_ac<<<(2 * 64 * 64 * 64 + 255) / 256, 256>>>(p_klo, p_k, 2 * 64, 32, 32, 64, 64, 31.f / 63.f, 31.f / 63.f);
    attention_v2<<<2 * 64 * 16 / 8, 256>>>(p_q, p_k, p_att, 64, 64, 64);
    apply_fused<64, 64, 32, 32><<<dim3(16, 64, 2), 128>>>(p_att, p_up, p_out);

    // ---- localUp2: H=128, kd=64; lo=g_out -> g_up ----  (q already in g_q2)
    conv1x1_partial<<<dim3(32, 1 * 8, 2), 256>>>(c2, lu2_w2, p_part, 512, 64, 4096, 8, 64);
    reduce_bn4<<<(2 * 64 * 4096 / 4 + 255) / 256, 256>>>((const float4*)p_part, lu2_bn2, (float4*)p_klo, 64, 4096, 8, 0);
    upsample_ac<<<(2 * 64 * 128 * 128 + 255) / 256, 256>>>(p_klo, p_k, 2 * 64, 64, 64, 128, 128, 63.f / 127.f, 63.f / 127.f);
    attention_v2<<<2 * 128 * 32 / 8, 256>>>(p_q2, p_k, p_att, 64, 128, 128);
    apply_fused<128, 128, 64, 64><<<dim3(32, 64, 2), 256>>>(p_att, p_out, p_up);

    // ---- conv6 1x1 -> (2,19,128,128), C-split x8, 4 px/thread ----
    conv6_partial<<<dim3(32, 8, 2), 128>>>(p_up, conv6_w, p_part);
    conv6_reduce<<<(2 * 19 * 16384 / 4 + 255) / 256, 256>>>((const float4*)p_part, conv6_b, (float4*)out);
}

// round 17
// speedup vs baseline: 1.3487x; 1.0060x over previous
#include <cuda_runtime.h>
#include <math.h>
#include <stdint.h>

#define BN_EPS 1e-5f

// ---------------- f32x2 helpers ----------------
__device__ __forceinline__ uint64_t bcast2(float v) {
    uint64_t r; asm("mov.b64 %0, {%1,%1};" : "=l"(r) : "f"(v)); return r;
}
__device__ __forceinline__ uint64_t fma2(uint64_t a, uint64_t b, uint64_t c) {
    uint64_t d; asm("fma.rn.f32x2 %0, %1, %2, %3;" : "=l"(d) : "l"(a), "l"(b), "l"(c)); return d;
}
__device__ __forceinline__ float2 unpack2(uint64_t v) {
    float2 f; asm("mov.b64 {%0,%1}, %2;" : "=f"(f.x), "=f"(f.y) : "l"(v)); return f;
}

// ---------------- scratch ----------------
__device__ float g_out [16777216];  // ping
__device__ float g_up  [16777216];  // pong
__device__ float g_q   [2097152];
__device__ float g_q2  [2097152];   // localUp2 q (computed early, must survive)
__device__ float g_k   [2097152];
__device__ float g_klo [524288];
__device__ float g_att [294912];
__device__ float g_part[8388608];   // K-split partials

// ---------------- conv5: 3x3, 2048->512 @ 16x16, K-split (KS=32) ----------------
// Occupancy-tiled: 32 oc x 256 px per block (acc 32 regs), grid (32,16,2).
__global__ void __launch_bounds__(256)
conv5_partial(const float* __restrict__ in, const float* __restrict__ w,
              float* __restrict__ part)
{
    const int ks = blockIdx.x, ocb = blockIdx.y, n = blockIdx.z;
    __shared__ float s_in[8 * 342];        // 8 ic x (18 rows, stride 19)
    __shared__ float s_w [8 * 9 * 32];     // [ic][tap][oc] (32 oc)
    const int tid = threadIdx.x;
    const int og  = tid >> 5;              // 0..7 -> 4 oc each
    const int pg  = tid & 31;
    const int py  = pg >> 1;
    const int px0 = (pg & 1) << 3;

    uint64_t acc2[2][8];
#pragma unroll
    for (int i = 0; i < 2; i++)
#pragma unroll
        for (int j = 0; j < 8; j++) acc2[i][j] = 0ull;

    const int icbase = ks * 64;
    for (int tile = 0; tile < 8; ++tile) {
        const int ict0 = icbase + tile * 8;
        __syncthreads();
        for (int i = tid; i < 8 * 324; i += 256) {
            const int ic = i / 324, rem = i - ic * 324;
            const int ry = rem / 18, rx = rem - ry * 18;
            const int yy = ry - 1, xx = rx - 1;
            float v = 0.f;
            if ((unsigned)yy < 16u && (unsigned)xx < 16u)
                v = in[(((size_t)n * 2048 + ict0 + ic) * 16 + yy) * 16 + xx];
            s_in[ic * 342 + ry * 19 + rx] = v;
        }
        for (int i = tid; i < 8 * 9 * 32; i += 256) {
            const int oc = i / 72, r = i - oc * 72;
            const int ic = r / 9, t = r - ic * 9;
            s_w[(ic * 9 + t) * 32 + oc] =
                w[(size_t)(ocb * 32 + oc) * 18432 + (size_t)(ict0 + ic) * 9 + t];
        }
        __syncthreads();
        for (int ic = 0; ic < 8; ++ic) {
            const float* si  = s_in + ic * 342;
            const float* swp = s_w  + ic * 9 * 32;
#pragma unroll
            for (int r = 0; r < 3; ++r) {
                const float* rp = si + (py + r) * 19 + px0;
                uint64_t inb[10];
#pragma unroll
                for (int u = 0; u < 10; ++u) inb[u] = bcast2(rp[u]);
#pragma unroll
                for (int s = 0; s < 3; ++s) {
                    const int t = r * 3 + s;
                    const uint64_t* wrow = (const uint64_t*)(swp + t * 32 + og * 4);
                    const uint64_t w0 = wrow[0], w1 = wrow[1];
#pragma unroll
                    for (int j = 0; j < 8; j++) {
                        const uint64_t iv2 = inb[s + j];
                        acc2[0][j] = fma2(w0, iv2, acc2[0][j]);
                        acc2[1][j] = fma2(w1, iv2, acc2[1][j]);
                    }
                }
            }
        }
    }
    float* dst = part + (size_t)(ks * 2 + n) * 512 * 256;
    const int px = py * 16 + px0;
#pragma unroll
    for (int i = 0; i < 2; i++) {
        const int oc = ocb * 32 + og * 4 + 2 * i;
#pragma unroll
        for (int j = 0; j < 8; j++) {
            const float2 v = unpack2(acc2[i][j]);
            dst[oc * 256 + px + j]       = v.x;
            dst[(oc + 1) * 256 + px + j] = v.y;
        }
    }
}

// ---------------- generic 1x1 conv GEMM, smem double-buffer ----------------
__global__ void __launch_bounds__(256)
conv1x1_partial(const float* __restrict__ in, const float* __restrict__ w,
                float* __restrict__ part,
                int Cin, int Cout, int P, int KS, int KCH)
{
    const int pxb = blockIdx.x;
    const int ocb = blockIdx.y / KS;
    const int ks  = blockIdx.y % KS;
    const int n   = blockIdx.z;
    const int k0  = ks * KCH;
    __shared__ float sA[2][16][68];
    __shared__ float sB[2][16][136];
    const int tid = threadIdx.x;
    const int ocg = tid >> 4;
    const int pxg = tid & 15;

    uint64_t acc2[4][4];
#pragma unroll
    for (int i = 0; i < 4; i++)
#pragma unroll
        for (int j = 0; j < 4; j++) acc2[i][j] = 0ull;

    const float* wrow = w + (size_t)(ocb * 64) * Cin + k0;
    const float* brow = in + ((size_t)n * Cin + k0) * P + pxb * 128;

    float  a_reg[4];
    float4 b_reg[2];
#pragma unroll
    for (int i = 0; i < 4; i++) {
        const int idx = (i << 8) + tid;
        sA[0][idx & 15][idx >> 4] = wrow[(size_t)(idx >> 4) * Cin + (idx & 15)];
    }
#pragma unroll
    for (int i = 0; i < 2; i++) {
        const int idx = (i << 8) + tid;
        *(float4*)&sB[0][idx >> 5][(idx & 31) << 2] =
            *(const float4*)&brow[(size_t)(idx >> 5) * P + ((idx & 31) << 2)];
    }
    __syncthreads();

    for (int kc = 0; kc < KCH; kc += 16) {
        const int cur = (kc >> 4) & 1;
        const int kn  = kc + 16;
        const bool more = (kn < KCH);
        if (more) {
#pragma unroll
            for (int i = 0; i < 4; i++) {
                const int idx = (i << 8) + tid;
                a_reg[i] = wrow[(size_t)(idx >> 4) * Cin + kn + (idx & 15)];
            }
#pragma unroll
            for (int i = 0; i < 2; i++) {
                const int idx = (i << 8) + tid;
                b_reg[i] = *(const float4*)&brow[(size_t)(kn + (idx >> 5)) * P + ((idx & 31) << 2)];
            }
        }
#pragma unroll
        for (int kk = 0; kk < 16; ++kk) {
            const float4 a4 = *(const float4*)&sA[cur][kk][ocg << 2];
            const float4 b40 = *(const float4*)&sB[cur][kk][pxg << 3];
            const float4 b41 = *(const float4*)&sB[cur][kk][(pxg << 3) + 4];
            const uint64_t* b2 = (const uint64_t*)&b40;
            const uint64_t* b3 = (const uint64_t*)&b41;
            const uint64_t a0 = bcast2(a4.x), a1 = bcast2(a4.y);
            const uint64_t a2 = bcast2(a4.z), a3 = bcast2(a4.w);
            acc2[0][0] = fma2(a0, b2[0], acc2[0][0]);
            acc2[0][1] = fma2(a0, b2[1], acc2[0][1]);
            acc2[0][2] = fma2(a0, b3[0], acc2[0][2]);
            acc2[0][3] = fma2(a0, b3[1], acc2[0][3]);
            acc2[1][0] = fma2(a1, b2[0], acc2[1][0]);
            acc2[1][1] = fma2(a1, b2[1], acc2[1][1]);
            acc2[1][2] = fma2(a1, b3[0], acc2[1][2]);
            acc2[1][3] = fma2(a1, b3[1], acc2[1][3]);
            acc2[2][0] = fma2(a2, b2[0], acc2[2][0]);
            acc2[2][1] = fma2(a2, b2[1], acc2[2][1]);
            acc2[2][2] = fma2(a2, b3[0], acc2[2][2]);
            acc2[2][3] = fma2(a2, b3[1], acc2[2][3]);
            acc2[3][0] = fma2(a3, b2[0], acc2[3][0]);
            acc2[3][1] = fma2(a3, b2[1], acc2[3][1]);
            acc2[3][2] = fma2(a3, b3[0], acc2[3][2]);
            acc2[3][3] = fma2(a3, b3[1], acc2[3][3]);
        }
        if (more) {
            const int nxt = cur ^ 1;
#pragma unroll
            for (int i = 0; i < 4; i++) {
                const int idx = (i << 8) + tid;
                sA[nxt][idx & 15][idx >> 4] = a_reg[i];
            }
#pragma unroll
            for (int i = 0; i < 2; i++) {
                const int idx = (i << 8) + tid;
                *(float4*)&sB[nxt][idx >> 5][(idx & 31) << 2] = b_reg[i];
            }
        }
        __syncthreads();
    }
    float* dst = part + (size_t)(ks * 2 + n) * Cout * P;
    const int ocx = ocb * 64 + (ocg << 2);
    const int px  = pxb * 128 + (pxg << 3);
#pragma unroll
    for (int i = 0; i < 4; i++) {
        const float2 v0 = unpack2(acc2[i][0]), v1 = unpack2(acc2[i][1]);
        const float2 v2 = unpack2(acc2[i][2]), v3 = unpack2(acc2[i][3]);
        *(float4*)&dst[(size_t)(ocx + i) * P + px]     = make_float4(v0.x, v0.y, v1.x, v1.y);
        *(float4*)&dst[(size_t)(ocx + i) * P + px + 4] = make_float4(v2.x, v2.y, v3.x, v3.y);
    }
}

// ---------------- 1x1 conv + fused BN, smem double-buffer ----------------
__global__ void __launch_bounds__(256)
conv1x1_bn(const float* __restrict__ in, const float* __restrict__ w,
           const float* __restrict__ bn, float* __restrict__ outp,
           int Cin, int Cout, int P)
{
    const int pxb = blockIdx.x;
    const int ocb = blockIdx.y;
    const int n   = blockIdx.z;
    __shared__ float sA[2][16][68];
    __shared__ float sB[2][16][136];
    const int tid = threadIdx.x;
    const int ocg = tid >> 4;
    const int pxg = tid & 15;

    uint64_t acc2[4][4];
#pragma unroll
    for (int i = 0; i < 4; i++)
#pragma unroll
        for (int j = 0; j < 4; j++) acc2[i][j] = 0ull;

    const float* wrow = w + (size_t)(ocb * 64) * Cin;
    const float* brow = in + ((size_t)n * Cin) * P + pxb * 128;

    float  a_reg[4];
    float4 b_reg[2];
#pragma unroll
    for (int i = 0; i < 4; i++) {
        const int idx = (i << 8) + tid;
        sA[0][idx & 15][idx >> 4] = wrow[(size_t)(idx >> 4) * Cin + (idx & 15)];
    }
#pragma unroll
    for (int i = 0; i < 2; i++) {
        const int idx = (i << 8) + tid;
        *(float4*)&sB[0][idx >> 5][(idx & 31) << 2] =
            *(const float4*)&brow[(size_t)(idx >> 5) * P + ((idx & 31) << 2)];
    }
    __syncthreads();

    for (int kc = 0; kc < Cin; kc += 16) {
        const int cur = (kc >> 4) & 1;
        const int kn  = kc + 16;
        const bool more = (kn < Cin);
        if (more) {
#pragma unroll
            for (int i = 0; i < 4; i++) {
                const int idx = (i << 8) + tid;
                a_reg[i] = wrow[(size_t)(idx >> 4) * Cin + kn + (idx & 15)];
            }
#pragma unroll
            for (int i = 0; i < 2; i++) {
                const int idx = (i << 8) + tid;
                b_reg[i] = *(const float4*)&brow[(size_t)(kn + (idx >> 5)) * P + ((idx & 31) << 2)];
            }
        }
#pragma unroll
        for (int kk = 0; kk < 16; ++kk) {
            const float4 a4 = *(const float4*)&sA[cur][kk][ocg << 2];
            const uint64_t* bp = (const uint64_t*)&sB[cur][kk][pxg << 3];
            uint64_t b2[4] = { bp[0], bp[1], bp[2], bp[3] };
            const uint64_t a0 = bcast2(a4.x), a1 = bcast2(a4.y);
            const uint64_t a2 = bcast2(a4.z), a3 = bcast2(a4.w);
#pragma unroll
            for (int j = 0; j < 4; j++) {
                acc2[0][j] = fma2(a0, b2[j], acc2[0][j]);
                acc2[1][j] = fma2(a1, b2[j], acc2[1][j]);
                acc2[2][j] = fma2(a2, b2[j], acc2[2][j]);
                acc2[3][j] = fma2(a3, b2[j], acc2[3][j]);
            }
        }
        if (more) {
            const int nxt = cur ^ 1;
#pragma unroll
            for (int i = 0; i < 4; i++) {
                const int idx = (i << 8) + tid;
                sA[nxt][idx & 15][idx >> 4] = a_reg[i];
            }
#pragma unroll
            for (int i = 0; i < 2; i++) {
                const int idx = (i << 8) + tid;
                *(float4*)&sB[nxt][idx >> 5][(idx & 31) << 2] = b_reg[i];
            }
        }
        __syncthreads();
    }
    const int ocx = ocb * 64 + (ocg << 2);
    const int px  = pxb * 128 + (pxg << 3);
#pragma unroll
    for (int i = 0; i < 4; i++) {
        const int oc = ocx + i;
        const float g = bn[oc], b = bn[Cout + oc], m = bn[2 * Cout + oc], v = bn[3 * Cout + oc];
        const float sc = g / sqrtf(v + BN_EPS);
        const float sh = b - m * sc;
        const float2 v0 = unpack2(acc2[i][0]), v1 = unpack2(acc2[i][1]);
        const float2 v2 = unpack2(acc2[i][2]), v3 = unpack2(acc2[i][3]);
        float* op = outp + ((size_t)n * Cout + oc) * P + px;
        *(float4*)op       = make_float4(v0.x * sc + sh, v0.y * sc + sh, v1.x * sc + sh, v1.y * sc + sh);
        *(float4*)(op + 4) = make_float4(v2.x * sc + sh, v2.y * sc + sh, v3.x * sc + sh, v3.y * sc + sh);
    }
}

// ---------------- reduce K-splits + BN (+ReLU), float4 ----------------
__global__ void __launch_bounds__(256)
reduce_bn4(const float4* __restrict__ part, const float* __restrict__ bn,
           float4* __restrict__ out, int C, int P, int KS, int relu)
{
    const int idx = blockIdx.x * 256 + threadIdx.x;
    const int total4 = 2 * C * P / 4;
    if (idx >= total4) return;
    const int c = ((idx * 4) / P) % C;
    const size_t stride4 = (size_t)2 * C * P / 4;
    float4 s = make_float4(0.f, 0.f, 0.f, 0.f);
    for (int k = 0; k < KS; ++k) {
        const float4 q = part[(size_t)k * stride4 + idx];
        s.x += q.x; s.y += q.y; s.z += q.z; s.w += q.w;
    }
    const float g = bn[c], b = bn[C + c], m = bn[2 * C + c], v = bn[3 * C + c];
    const float sc = g / sqrtf(v + BN_EPS);
    const float sh = b - m * sc;
    float4 r = make_float4(s.x * sc + sh, s.y * sc + sh, s.z * sc + sh, s.w * sc + sh);
    if (relu) {
        r.x = fmaxf(r.x, 0.f); r.y = fmaxf(r.y, 0.f);
        r.z = fmaxf(r.z, 0.f); r.w = fmaxf(r.w, 0.f);
    }
    out[idx] = r;
}

// ---------------- bilinear upsample (k path only) ----------------
__global__ void __launch_bounds__(256)
upsample_ac(const float* __restrict__ in, float* __restrict__ out,
            int NC, int h, int w, int H, int W, float sy, float sx)
{
    const int idx = blockIdx.x * 256 + threadIdx.x;
    const int total = NC * H * W;
    if (idx >= total) return;
    const int x  = idx % W;
    const int y  = (idx / W) % H;
    const int nc = idx / (W * H);
    const float fy = y * sy;
    const float fx = x * sx;
    int y0 = (int)fy; if (y0 > h - 1) y0 = h - 1;
    int x0 = (int)fx; if (x0 > w - 1) x0 = w - 1;
    const int y1 = min(y0 + 1, h - 1);
    const int x1 = min(x0 + 1, w - 1);
    const float wy = fy - y0, wx = fx - x0;
    const float* p = in + (size_t)nc * h * w;
    const float v00 = p[y0 * w + x0], v01 = p[y0 * w + x1];
    const float v10 = p[y1 * w + x0], v11 = p[y1 * w + x1];
    const float a = v00 * (1.f - wy) + v10 * wy;
    const float b = v01 * (1.f - wy) + v11 * wy;
    out[idx] = a * (1.f - wx) + b * wx;
}

// ---------------- attention v2: kd-split across block ----------------
__global__ void __launch_bounds__(256)
attention_v2(const float* __restrict__ q, const float* __restrict__ kmap,
             float* __restrict__ att, int kd, int H, int W)
{
    __shared__ float s_part[32][8][36];
    __shared__ float s_red[8][36];
    const int tid  = threadIdx.x;
    const int qloc = tid & 7;
    const int si   = tid >> 3;
    const int Wq   = W >> 2;
    const int qg   = blockIdx.x * 8 + qloc;
    const int xq   = qg % Wq;
    const int y    = (qg / Wq) % H;
    const int n    = qg / (Wq * H);
    const int x0   = xq << 2;
    const size_t plane = (size_t)H * W;

    const bool lok = (x0 >= 4);
    const bool rok = (x0 + 4 < W);
    int rowoff[3]; bool rowok[3];
#pragma unroll
    for (int r = 0; r < 3; r++) {
        const int yy = y + (r - 1) * 2;
        rowok[r]  = ((unsigned)yy < (unsigned)H);
        rowoff[r] = yy * W + x0;
    }

    uint64_t lg[9][2];
#pragma unroll
    for (int t = 0; t < 9; t++) { lg[t][0] = 0ull; lg[t][1] = 0ull; }

    const int cpt = kd >> 5;
    const int c0  = si * cpt;
    const float* qp = q + ((size_t)n * kd + c0) * plane + (size_t)y * W + x0;
    const float* kp = kmap + ((size_t)n * kd + c0) * plane;
    const float4 z4 = make_float4(0.f, 0.f, 0.f, 0.f);

    for (int c = 0; c < cpt; ++c) {
        const float4 qv = *(const float4*)(qp + (size_t)c * plane);
        const uint64_t* qh = (const uint64_t*)&qv;
        const uint64_t q01 = qh[0], q23 = qh[1];
        const float* kc = kp + (size_t)c * plane;
#pragma unroll
        for (int r = 0; r < 3; r++) {
            if (!rowok[r]) continue;
            const float* kr = kc + rowoff[r];
            const float4 L = lok ? *(const float4*)(kr - 4) : z4;
            const float4 M = *(const float4*)kr;
            const float4 R = rok ? *(const float4*)(kr + 4) : z4;
            const uint64_t* Lh = (const uint64_t*)&L;
            const uint64_t* Mh = (const uint64_t*)&M;
            const uint64_t* Rh = (const uint64_t*)&R;
            const int t0 = r * 3;
            lg[t0 + 0][0] = fma2(q01, Lh[1], lg[t0 + 0][0]);
            lg[t0 + 0][1] = fma2(q23, Mh[0], lg[t0 + 0][1]);
            lg[t0 + 1][0] = fma2(q01, Mh[0], lg[t0 + 1][0]);
            lg[t0 + 1][1] = fma2(q23, Mh[1], lg[t0 + 1][1]);
            lg[t0 + 2][0] = fma2(q01, Mh[1], lg[t0 + 2][0]);
            lg[t0 + 2][1] = fma2(q23, Rh[0], lg[t0 + 2][1]);
        }
    }
#pragma unroll
    for (int t = 0; t < 9; t++) {
        const float2 a = unpack2(lg[t][0]);
        const float2 b = unpack2(lg[t][1]);
        s_part[si][qloc][t * 4 + 0] = a.x;
        s_part[si][qloc][t * 4 + 1] = a.y;
        s_part[si][qloc][t * 4 + 2] = b.x;
        s_part[si][qloc][t * 4 + 3] = b.y;
    }
    __syncthreads();

    for (int i = tid; i < 8 * 36; i += 256) {
        const int qq = i / 36, j = i - qq * 36;
        float s = 0.f;
#pragma unroll
        for (int s2 = 0; s2 < 32; s2++) s += s_part[s2][qq][j];
        s_red[qq][j] = s;
    }
    __syncthreads();

    if (tid < 32) {
        const int qq = tid >> 2, p = tid & 3;
        float l[9];
#pragma unroll
        for (int t = 0; t < 9; t++) l[t] = s_red[qq][t * 4 + p];
        float mx = l[0];
#pragma unroll
        for (int t = 1; t < 9; t++) mx = fmaxf(mx, l[t]);
        float s = 0.f;
#pragma unroll
        for (int t = 0; t < 9; t++) { l[t] = expf(l[t] - mx); s += l[t]; }
        const float inv = 1.f / s;
        const int qg2 = blockIdx.x * 8 + qq;
        const int xq2 = qg2 % Wq;
        const int y2  = (qg2 / Wq) % H;
        const int n2  = qg2 / (Wq * H);
        float* ap = att + (size_t)n2 * 9 * plane + (size_t)y2 * W + (xq2 << 2) + p;
#pragma unroll
        for (int t = 0; t < 9; t++) ap[(size_t)t * plane] = l[t] * inv;
    }
}

// ---------------- fused upsample + attention apply ----------------
template<int H, int W, int h, int w>
__global__ void __launch_bounds__(256)
apply_fused(const float* __restrict__ att, const float* __restrict__ lo,
            float* __restrict__ outp)
{
    constexpr int WPAD = W + 8;
    __shared__ __align__(16) float s_lo[8][6][w + 2];
    __shared__ __align__(16) float s_up[8][8][WPAD];
    const int y0  = blockIdx.x * 4;
    const int ch0 = blockIdx.y * 8;
    const int n   = blockIdx.z;
    const int tid = threadIdx.x;
    const int nth = blockDim.x;
    constexpr float sy = (float)(h - 1) / (float)(H - 1);
    constexpr float sx = (float)(w - 1) / (float)(W - 1);
    const size_t planeL = (size_t)h * w;
    const size_t planeH = (size_t)H * W;

    const int ylo = (y0 >= 2 ? y0 - 2 : 0);
    const int base = (int)((float)ylo * sy);
    for (int i = tid; i < 8 * 6 * w; i += nth) {
        const int ch = i / (6 * w);
        const int r  = (i / w) % 6;
        const int x  = i % w;
        const int gr = min(base + r, h - 1);
        s_lo[ch][r][x] = lo[((size_t)(n * 512 + ch0 + ch)) * planeL + (size_t)gr * w + x];
    }
    __syncthreads();

    for (int i = tid; i < 8 * 8 * WPAD; i += nth) {
        const int ch  = i / (8 * WPAD);
        const int rem = i - ch * (8 * WPAD);
        const int row = rem / WPAD;
        const int col = rem - row * WPAD;
        const int Y = y0 - 2 + row;
        const int X = col - 4;
        float v = 0.f;
        if ((unsigned)Y < (unsigned)H && (unsigned)X < (unsigned)W) {
            const float fy = Y * sy;
            int iy0 = (int)fy; if (iy0 > h - 1) iy0 = h - 1;
            const int ry0 = iy0 - base;
            const int ry1 = min(iy0 + 1, h - 1) - base;
            const float wy = fy - iy0;
            const float fx = X * sx;
            int ix0 = (int)fx; if (ix0 > w - 1) ix0 = w - 1;
            const int ix1 = min(ix0 + 1, w - 1);
            const float wx = fx - ix0;
            const float a = s_lo[ch][ry0][ix0] * (1.f - wx) + s_lo[ch][ry0][ix1] * wx;
            const float b = s_lo[ch][ry1][ix0] * (1.f - wx) + s_lo[ch][ry1][ix1] * wx;
            v = a * (1.f - wy) + b * wy;
        }
        s_up[ch][row][col] = v;
    }
    __syncthreads();

    const int Wp = W >> 1;
    const int xp = tid % Wp;
    const int yy = tid / Wp;
    const int y  = y0 + yy;
    const int x0 = xp << 1;

    uint64_t att2[9];
    const float* ap = att + (size_t)n * 9 * planeH + (size_t)y * W + x0;
#pragma unroll
    for (int t = 0; t < 9; t++) att2[t] = *(const uint64_t*)(ap + (size_t)t * planeH);

#pragma unroll
    for (int c = 0; c < 8; ++c) {
        uint64_t acc = 0ull;
#pragma unroll
        for (int iy = 0; iy < 3; iy++) {
            const float* rp = &s_up[c][yy + 2 * iy][0];
#pragma unroll
            for (int ix = 0; ix < 3; ix++) {
                const uint64_t u2 = *(const uint64_t*)(rp + x0 + 2 * ix + 2);
                acc = fma2(att2[iy * 3 + ix], u2, acc);
            }
        }
        const float2 v = unpack2(acc);
        *(float2*)&outp[((size_t)(n * 512 + ch0 + c)) * planeH + (size_t)y * W + x0] = v;
    }
}

// ---------------- conv6: 1x1, 512->19, C-split x8, 4 px/thread ----------------
__global__ void __launch_bounds__(128)
conv6_partial(const float* __restrict__ in, const float* __restrict__ w,
              float* __restrict__ part)
{
    __shared__ float sw[19 * 64];
    const int tid = threadIdx.x;
    const int cs  = blockIdx.y;
    const int n   = blockIdx.z;
    const int c0  = cs * 64;
    for (int i = tid; i < 19 * 64; i += 128) {
        const int o = i >> 6, c = i & 63;
        sw[i] = w[o * 512 + c0 + c];
    }
    __syncthreads();
    const int px = (blockIdx.x * 128 + tid) * 4;
    uint64_t acc2[19][2];
#pragma unroll
    for (int o = 0; o < 19; o++) { acc2[o][0] = 0ull; acc2[o][1] = 0ull; }
    const float* ip = in + ((size_t)n * 512 + c0) * 16384 + px;
    for (int c = 0; c < 64; ++c) {
        const float4 v4 = *(const float4*)(ip + (size_t)c * 16384);
        const uint64_t* vh = (const uint64_t*)&v4;
        const uint64_t v01 = vh[0], v23 = vh[1];
#pragma unroll
        for (int o = 0; o < 19; o++) {
            const uint64_t wv = bcast2(sw[(o << 6) + c]);
            acc2[o][0] = fma2(wv, v01, acc2[o][0]);
            acc2[o][1] = fma2(wv, v23, acc2[o][1]);
        }
    }
    float* op = part + ((size_t)(cs * 2 + n) * 19) * 16384 + px;
#pragma unroll
    for (int o = 0; o < 19; o++) {
        const float2 a = unpack2(acc2[o][0]);
        const float2 b = unpack2(acc2[o][1]);
        *(float4*)(op + (size_t)o * 16384) = make_float4(a.x, a.y, b.x, b.y);
    }
}

// ---------------- conv6 reduce + bias, float4, 8 splits ----------------
__global__ void __launch_bounds__(256)
conv6_reduce(const float4* __restrict__ part, const float* __restrict__ bias,
             float4* __restrict__ out)
{
    const int idx = blockIdx.x * 256 + threadIdx.x;
    const int perN = 19 * 16384 / 4;
    const int total = 2 * perN;
    if (idx >= total) return;
    const int n   = idx / perN;
    const int rem = idx - n * perN;
    const int o   = (rem * 4) / 16384;
    float4 s = make_float4(0.f, 0.f, 0.f, 0.f);
#pragma unroll
    for (int cs = 0; cs < 8; ++cs) {
        const float4 q = part[(size_t)(cs * 2 + n) * perN + rem];
        s.x += q.x; s.y += q.y; s.z += q.z; s.w += q.w;
    }
    const float b = bias[o];
    out[idx] = make_float4(s.x + b, s.y + b, s.z + b, s.w + b);
}

// ---------------- launch ----------------
extern "C" void kernel_launch(void* const* d_in, const int* in_sizes, int n_in,
                              void* d_out, int out_size)
{
    (void)in_sizes; (void)n_in; (void)out_size;
    const float* c1      = (const float*)d_in[0];
    const float* c2      = (const float*)d_in[1];
    const float* c3      = (const float*)d_in[2];
    const float* c4      = (const float*)d_in[3];
    const float* c30     = (const float*)d_in[5];
    const float* c40     = (const float*)d_in[6];
    const float* conv5_w = (const float*)d_in[7];
    const float* bn5     = (const float*)d_in[8];
    const float* conv6_w = (const float*)d_in[9];
    const float* conv6_b = (const float*)d_in[10];
    const float* lu4_w1  = (const float*)d_in[11];
    const float* lu4_bn1 = (const float*)d_in[12];
    const float* lu4_w2  = (const float*)d_in[13];
    const float* lu4_bn2 = (const float*)d_in[14];
    const float* lu3_w1  = (const float*)d_in[15];
    const float* lu3_bn1 = (const float*)d_in[16];
    const float* lu3_w2  = (const float*)d_in[17];
    const float* lu3_bn2 = (const float*)d_in[18];
    const float* lu2_w1  = (const float*)d_in[19];
    const float* lu2_bn1 = (const float*)d_in[20];
    const float* lu2_w2  = (const float*)d_in[21];
    const float* lu2_bn2 = (const float*)d_in[22];
    float* out = (float*)d_out;

    float *p_out, *p_up, *p_q, *p_q2, *p_k, *p_klo, *p_att, *p_part;
    cudaGetSymbolAddress((void**)&p_out,  g_out);
    cudaGetSymbolAddress((void**)&p_up,   g_up);
    cudaGetSymbolAddress((void**)&p_q,    g_q);
    cudaGetSymbolAddress((void**)&p_q2,   g_q2);
    cudaGetSymbolAddress((void**)&p_k,    g_k);
    cudaGetSymbolAddress((void**)&p_klo,  g_klo);
    cudaGetSymbolAddress((void**)&p_att,  g_att);
    cudaGetSymbolAddress((void**)&p_part, g_part);

    // ---- independent front work (conv5 profiled slot #4) ----
    conv1x1_bn<<<dim3(128, 1, 2), 256>>>(c1, lu2_w1, lu2_bn1, p_q2, 256, 64, 16384);              // #1
    conv1x1_partial<<<dim3(8, 2 * 16, 2), 256>>>(c3, lu4_w1, p_part, 1024, 128, 1024, 16, 64);    // #2
    reduce_bn4<<<(2 * 128 * 1024 / 4 + 255) / 256, 256>>>((const float4*)p_part, lu4_bn1, (float4*)p_q, 128, 1024, 16, 0); // #3

    // ---- conv5 + BN + ReLU -> g_out (2,512,16,16); KS=32, ocb=16 ----
    conv5_partial<<<dim3(32, 16, 2), 256>>>(c4, conv5_w, p_part);                                  // #4 (profiled)
    reduce_bn4<<<(2 * 512 * 256 / 4 + 255) / 256, 256>>>((const float4*)p_part, bn5, (float4*)p_out, 512, 256, 32, 1);

    // ---- localUp4: H=32, kd=128; lo=g_out -> g_up ----
    conv1x1_partial<<<dim3(2, 2 * 64, 2), 256>>>(c40, lu4_w2, p_part, 2048, 128, 256, 64, 32);
    reduce_bn4<<<(2 * 128 * 256 / 4 + 255) / 256, 256>>>((const float4*)p_part, lu4_bn2, (float4*)p_klo, 128, 256, 64, 0);
    upsample_ac<<<(2 * 128 * 32 * 32 + 255) / 256, 256>>>(p_klo, p_k, 2 * 128, 16, 16, 32, 32, 15.f / 31.f, 15.f / 31.f);
    attention_v2<<<2 * 32 * 8 / 8, 256>>>(p_q, p_k, p_att, 128, 32, 32);
    apply_fused<32, 32, 16, 16><<<dim3(8, 64, 2), 64>>>(p_att, p_out, p_up);

    // ---- localUp3: H=64, kd=64; lo=g_up -> g_out ----
    conv1x1_partial<<<dim3(32, 1 * 8, 2), 256>>>(c2, lu3_w1, p_part, 512, 64, 4096, 8, 64);
    reduce_bn4<<<(2 * 64 * 4096 / 4 + 255) / 256, 256>>>((const float4*)p_part, lu3_bn1, (float4*)p_q, 64, 4096, 8, 0);
    conv1x1_partial<<<dim3(8, 1 * 32, 2), 256>>>(c30, lu3_w2, p_part, 1024, 64, 1024, 32, 32);
    reduce_bn4<<<(2 * 64 * 1024 / 4 + 255) / 256, 256>>>((const float4*)p_part, lu3_bn2, (float4*)p_klo, 64, 1024, 32, 0);
    upsample_ac<<<(2 * 64 * 64 * 64 + 255) / 256, 256>>>(p_klo, p_k, 2 * 64, 32, 32, 64, 64, 31.f / 63.f, 31.f / 63.f);
    attention_v2<<<2 * 64 * 16 / 8, 256>>>(p_q, p_k, p_att, 64, 64, 64);
    apply_fused<64, 64, 32, 32><<<dim3(16, 64, 2), 128>>>(p_att, p_up, p_out);

    // ---- localUp2: H=128, kd=64; lo=g_out -> g_up ----  (q already in g_q2)
    conv1x1_partial<<<dim3(32, 1 * 8, 2), 256>>>(c2, lu2_w2, p_part, 512, 64, 4096, 8, 64);
    reduce_bn4<<<(2 * 64 * 4096 / 4 + 255) / 256, 256>>>((const float4*)p_part, lu2_bn2, (float4*)p_klo, 64, 4096, 8, 0);
    upsample_ac<<<(2 * 64 * 128 * 128 + 255) / 256, 256>>>(p_klo, p_k, 2 * 64, 64, 64, 128, 128, 63.f / 127.f, 63.f / 127.f);
    attention_v2<<<2 * 128 * 32 / 8, 256>>>(p_q2, p_k, p_att, 64, 128, 128);
    apply_fused<128, 128, 64, 64><<<dim3(32, 64, 2), 256>>>(p_att, p_out, p_up);

    // ---- conv6 1x1 -> (2,19,128,128), C-split x8, 4 px/thread ----
    conv6_partial<<<dim3(32, 8, 2), 128>>>(p_up, conv6_w, p_part);
    conv6_reduce<<<(2 * 19 * 16384 / 4 + 255) / 256, 256>>>((const float4*)p_part, conv6_b, (float4*)out);
}